// round 6
// baseline (speedup 1.0000x reference)
#include <cuda_runtime.h>
#include <cuda_bf16.h>
#include <cstdint>

#define BB 2
#define LL 2048
#define EE 512
#define KH 4
#define KE 256
typedef __nv_bfloat16 bf16;
typedef __nv_bfloat162 bf162;

// ---------------- scratch (device globals) ----------------------------------
__device__ float g_xq [(size_t)4096*1024];
__device__ float g_xkb[(size_t)4096*1024];
__device__ float g_qn [4096*4];
__device__ float g_kn [4096*4];
__device__ float g_H  [(size_t)8*2048*2048];

__device__ bf16 g_xsa_h[(size_t)4096*512],  g_xsa_l[(size_t)4096*512];
__device__ bf16 g_wq_h [(size_t)1024*512],  g_wq_l [(size_t)1024*512];
__device__ bf16 g_wk_h [(size_t)1024*512],  g_wk_l [(size_t)1024*512];
__device__ bf16 g_wv_h [(size_t)512*2048],  g_wv_l [(size_t)512*2048];
__device__ bf16 g_xq_h [(size_t)4096*1024], g_xq_l [(size_t)4096*1024];
__device__ bf16 g_xkb_h[(size_t)4096*1024], g_xkb_l[(size_t)4096*1024];
__device__ bf16 g_P_h  [(size_t)8*2048*2048], g_P_l[(size_t)8*2048*2048];
__device__ bf16 g_vp_h [(size_t)8*2048*512],  g_vp_l[(size_t)8*2048*512];

// ---------------- helpers ----------------------------------------------------
__device__ __forceinline__ uint32_t smem_u32(const void* p) {
    uint32_t a;
    asm("{ .reg .u64 t; cvta.to.shared.u64 t, %1; cvt.u32.u64 %0, t; }" : "=r"(a) : "l"(p));
    return a;
}
__device__ __forceinline__ void cpa16(uint32_t d, const void* s) {
    asm volatile("cp.async.cg.shared.global [%0], [%1], 16;" :: "r"(d), "l"(s));
}
#define CP_COMMIT() asm volatile("cp.async.commit_group;" ::: "memory")
#define CP_WAIT1()  asm volatile("cp.async.wait_group 1;" ::: "memory")

__device__ __forceinline__ void ldsm_x4(uint32_t& r0, uint32_t& r1, uint32_t& r2,
                                        uint32_t& r3, uint32_t a) {
    asm volatile("ldmatrix.sync.aligned.m8n8.x4.shared.b16 {%0,%1,%2,%3}, [%4];"
                 : "=r"(r0), "=r"(r1), "=r"(r2), "=r"(r3) : "r"(a));
}
__device__ __forceinline__ void ldsm_x4t(uint32_t& r0, uint32_t& r1, uint32_t& r2,
                                         uint32_t& r3, uint32_t a) {
    asm volatile("ldmatrix.sync.aligned.m8n8.x4.trans.shared.b16 {%0,%1,%2,%3}, [%4];"
                 : "=r"(r0), "=r"(r1), "=r"(r2), "=r"(r3) : "r"(a));
}
__device__ __forceinline__ void mma16816(float c[4], const uint32_t a[4],
                                         const uint32_t bq[2]) {
    asm volatile("mma.sync.aligned.m16n8k16.row.col.f32.bf16.bf16.f32 "
                 "{%0,%1,%2,%3}, {%4,%5,%6,%7}, {%8,%9}, {%0,%1,%2,%3};"
                 : "+f"(c[0]), "+f"(c[1]), "+f"(c[2]), "+f"(c[3])
                 : "r"(a[0]), "r"(a[1]), "r"(a[2]), "r"(a[3]), "r"(bq[0]), "r"(bq[1]));
}
__device__ __forceinline__ void split2(float a, float b, bf162& h, bf162& l) {
    h = __floats2bfloat162_rn(a, b);
    l = __floats2bfloat162_rn(a - __bfloat162float(h.x), b - __bfloat162float(h.y));
}

// ---------------- GEMM: C[M][N] = A[M][K] * B^T ------------------------------
// CTA tile 256x128, warp tile 64x64 (4m x 2n warps), BK=32, 3-stage cp.async.
// NT stages (0,1,2): B gmem [n][k] K-contig.  NN stages (3,4): B gmem [k][n],
// ldmatrix.trans. Stage 3 B = Wv flat chunk k*262144, ld=512.
// Split bf16 hi/lo; acc = Ah*Bh + Ah*Bl + Al*Bh in fp32.
// smem buffer: Ah 16K | Al 16K | Bh 8K | Bl 8K = 48KB; 3 buffers = 144KB.

#define BUF_BYTES 49152
#define SMEM_TOT  (3 * BUF_BYTES)

template<int STAGE>
__global__ __launch_bounds__(256, 1)
void hgemm(const bf16* __restrict__ gAh, const bf16* __restrict__ gAl,
           const bf16* __restrict__ gBh, const bf16* __restrict__ gBl,
           float* __restrict__ Cf, bf16* __restrict__ Ch, bf16* __restrict__ Cl,
           const float* __restrict__ aux1, const float* __restrict__ aux2)
{
    constexpr bool NT  = (STAGE <= 2);
    constexpr int  Kd  = (STAGE <= 1) ? 512  : (STAGE == 2 ? 256  : (STAGE == 3 ? 512 : 2048));
    constexpr int  ldA = (STAGE <= 1) ? 512  : (STAGE == 2 ? 1024 : (STAGE == 3 ? 512 : 2048));
    constexpr int  ldB = (STAGE <= 1) ? 512  : (STAGE == 2 ? 1024 : 512);
    constexpr int  ldC = (STAGE <= 1) ? 1024 : (STAGE == 2 ? 2048 : (STAGE == 3 ? 512 : 2048));
    constexpr int  NC  = Kd / 32;

    extern __shared__ char smem[];
    const uint32_t sb = smem_u32(smem);
    const int tid = threadIdx.x;
    const int z = blockIdx.z, b = z >> 2, k = z & 3;

    const bf16 *Ah = gAh, *Al = gAl, *Bh = gBh, *Bl = gBl;
    size_t coff = 0;
    if (STAGE == 2) {
        size_t o = (size_t)(b * 2048) * 1024 + (size_t)k * 256;
        Ah += o; Al += o; Bh += o; Bl += o;
        coff = (size_t)z * 2048 * 2048;
    } else if (STAGE == 3) {
        size_t oa = (size_t)(b * 2048) * 512;
        Ah += oa; Al += oa;
        size_t ob = (size_t)k * 512 * 512;
        Bh += ob; Bl += ob;
        coff = (size_t)z * 2048 * 512;
    } else if (STAGE == 4) {
        size_t oa = (size_t)z * 2048 * 2048;
        Ah += oa; Al += oa;
        size_t ob = (size_t)z * 2048 * 512;
        Bh += ob; Bl += ob;
        coff = (size_t)(b * 2048) * 2048 + (size_t)k * 512;
    }
    const int yBlk = blockIdx.y * 256, xBlk = blockIdx.x * 128;
    Ah += (size_t)yBlk * ldA; Al += (size_t)yBlk * ldA;
    if (NT) { Bh += (size_t)xBlk * ldB; Bl += (size_t)xBlk * ldB; }
    else    { Bh += xBlk; Bl += xBlk; }
    if (Cf) Cf += coff;
    if (Ch) { Ch += coff; Cl += coff; }

    const int wid = tid >> 5, lane = tid & 31;
    const int m0 = (wid & 3) * 64, n0 = (wid >> 2) * 64;

    float acc[4][8][4];
    #pragma unroll
    for (int am = 0; am < 4; am++)
        #pragma unroll
        for (int j = 0; j < 8; j++)
            #pragma unroll
            for (int q = 0; q < 4; q++) acc[am][j][q] = 0.f;

    auto load_chunk = [&](int c, int buf) {
        uint32_t s0 = sb + buf * BUF_BYTES;
        // A: 256 rows x 32 cols (hi+lo)
        #pragma unroll
        for (int h = 0; h < 4; h++) {
            int s = tid + h * 256;
            int r = s >> 2, q = s & 3;
            uint32_t d = s0 + r * 64 + ((q ^ ((r >> 1) & 3)) << 4);
            cpa16(d,         Ah + (size_t)r * ldA + c * 32 + q * 8);
            cpa16(d + 16384, Al + (size_t)r * ldA + c * 32 + q * 8);
        }
        if (NT) {
            #pragma unroll
            for (int h = 0; h < 2; h++) {
                int s = tid + h * 256;
                int r = s >> 2, q = s & 3;
                uint32_t d = s0 + 32768 + r * 64 + ((q ^ ((r >> 1) & 3)) << 4);
                cpa16(d,        Bh + (size_t)r * ldB + c * 32 + q * 8);
                cpa16(d + 8192, Bl + (size_t)r * ldB + c * 32 + q * 8);
            }
        } else {
            #pragma unroll
            for (int h = 0; h < 2; h++) {
                int s = tid + h * 256;
                int kk = s >> 4, q = s & 15;
                uint32_t d = s0 + 32768 + kk * 256 + ((q ^ (kk & 7)) << 4);
                cpa16(d,        Bh + (size_t)(c * 32 + kk) * ldB + q * 8);
                cpa16(d + 8192, Bl + (size_t)(c * 32 + kk) * ldB + q * 8);
            }
        }
    };

    load_chunk(0, 0); CP_COMMIT();
    load_chunk(1, 1); CP_COMMIT();

    #pragma unroll 1
    for (int c = 0; c < NC; c++) {
        CP_WAIT1();
        __syncthreads();
        if (c + 2 < NC) load_chunk(c + 2, (c + 2) % 3);
        CP_COMMIT();

        const uint32_t s0 = sb + (c % 3) * BUF_BYTES;
        #pragma unroll
        for (int s = 0; s < 2; s++) {
            // ---- all B fragments for this k-step (8 j, hi & lo) ----
            uint32_t bh[8][2], bl[8][2];
            if (NT) {
                #pragma unroll
                for (int i = 0; i < 4; i++) {
                    int row = n0 + i * 16 + (lane & 15);
                    int q = s * 2 + (lane >> 4);
                    uint32_t addr = s0 + 32768 + row * 64 + ((q ^ ((row >> 1) & 3)) << 4);
                    uint32_t r0, r1, r2, r3;
                    ldsm_x4(r0, r1, r2, r3, addr);
                    bh[2*i][0] = r0; bh[2*i][1] = r2;
                    bh[2*i+1][0] = r1; bh[2*i+1][1] = r3;
                    ldsm_x4(r0, r1, r2, r3, addr + 8192);
                    bl[2*i][0] = r0; bl[2*i][1] = r2;
                    bl[2*i+1][0] = r1; bl[2*i+1][1] = r3;
                }
            } else {
                #pragma unroll
                for (int i = 0; i < 4; i++) {
                    int g = lane >> 3;
                    int kk = s * 16 + (g & 1) * 8 + (lane & 7);
                    int q = (n0 + i * 16) / 8 + (g >> 1);
                    uint32_t addr = s0 + 32768 + kk * 256 + ((q ^ (kk & 7)) << 4);
                    uint32_t r0, r1, r2, r3;
                    ldsm_x4t(r0, r1, r2, r3, addr);
                    bh[2*i][0] = r0; bh[2*i][1] = r1;
                    bh[2*i+1][0] = r2; bh[2*i+1][1] = r3;
                    ldsm_x4t(r0, r1, r2, r3, addr + 8192);
                    bl[2*i][0] = r0; bl[2*i][1] = r1;
                    bl[2*i+1][0] = r2; bl[2*i+1][1] = r3;
                }
            }
            // ---- A per am-row, 24 MMAs each ----
            #pragma unroll
            for (int am = 0; am < 4; am++) {
                uint32_t ah[4], al[4];
                int row = m0 + am * 16 + (lane & 15);
                int q = s * 2 + (lane >> 4);
                uint32_t addr = s0 + row * 64 + ((q ^ ((row >> 1) & 3)) << 4);
                ldsm_x4(ah[0], ah[1], ah[2], ah[3], addr);
                ldsm_x4(al[0], al[1], al[2], al[3], addr + 16384);
                #pragma unroll
                for (int j = 0; j < 8; j++) mma16816(acc[am][j], ah, bh[j]);
                #pragma unroll
                for (int j = 0; j < 8; j++) mma16816(acc[am][j], ah, bl[j]);
                #pragma unroll
                for (int j = 0; j < 8; j++) mma16816(acc[am][j], al, bh[j]);
            }
        }
    }

    // ---- epilogue ----
    #pragma unroll
    for (int am = 0; am < 4; am++) {
        const int gi0 = yBlk + m0 + am * 16 + (lane >> 2);
        #pragma unroll
        for (int j = 0; j < 8; j++) {
            const int gj = xBlk + n0 + j * 8 + (lane & 3) * 2;
            #pragma unroll
            for (int half = 0; half < 2; half++) {
                const int gi = gi0 + half * 8;
                float v0 = acc[am][j][half * 2 + 0];
                float v1 = acc[am][j][half * 2 + 1];
                if (STAGE == 1) {
                    v0 += aux1[((gj + 0) & 255) * 4 + ((gj + 0) >> 8)];
                    v1 += aux1[((gj + 1) & 255) * 4 + ((gj + 1) >> 8)];
                } else if (STAGE == 2) {
                    const float qi = aux1[(size_t)(b * 2048 + gi) * 4 + k];
                    v0 = (2.f * v0 - qi - aux2[(size_t)(b * 2048 + gj + 0) * 4 + k]) * 0.0625f;
                    v1 = (2.f * v1 - qi - aux2[(size_t)(b * 2048 + gj + 1) * 4 + k]) * 0.0625f;
                } else if (STAGE == 4) {
                    v0 += aux1[(gj + 0) * 4 + k];
                    v1 += aux1[(gj + 1) * 4 + k];
                }
                const size_t idx = (size_t)gi * ldC + gj;
                if (STAGE != 3)
                    *reinterpret_cast<float2*>(Cf + idx) = make_float2(v0, v1);
                if (STAGE <= 1 || STAGE == 3) {
                    bf162 h, l;
                    split2(v0, v1, h, l);
                    *reinterpret_cast<bf162*>(Ch + idx) = h;
                    *reinterpret_cast<bf162*>(Cl + idx) = l;
                }
            }
        }
    }
}

// ---------------- fused fp32 -> bf16 hi/lo split (all 4 inputs) --------------
__global__ void split_all(const float4* __restrict__ xsa, const float4* __restrict__ wq,
                          const float4* __restrict__ wk,  const float4* __restrict__ wv,
                          bf162* __restrict__ xh, bf162* __restrict__ xl,
                          bf162* __restrict__ qh, bf162* __restrict__ ql,
                          bf162* __restrict__ kh, bf162* __restrict__ kl,
                          bf162* __restrict__ vh, bf162* __restrict__ vl)
{
    int i = blockIdx.x * 256 + threadIdx.x;
    const float4* src;
    bf162 *hi, *lo;
    int j;
    if (i < 524288)       { src = xsa; hi = xh; lo = xl; j = i; }
    else if (i < 655360)  { src = wq;  hi = qh; lo = ql; j = i - 524288; }
    else if (i < 786432)  { src = wk;  hi = kh; lo = kl; j = i - 655360; }
    else                  { src = wv;  hi = vh; lo = vl; j = i - 786432; }
    float4 v = src[j];
    bf162 h0, l0, h1, l1;
    split2(v.x, v.y, h0, l0);
    split2(v.z, v.w, h1, l1);
    hi[2 * j] = h0; hi[2 * j + 1] = h1;
    lo[2 * j] = l0; lo[2 * j + 1] = l1;
}

// ---------------- row norms --------------------------------------------------
__global__ void norms_k(const float* __restrict__ xq, const float* __restrict__ xkb,
                        float* __restrict__ qn, float* __restrict__ kn)
{
    const int row  = blockIdx.x;
    const int w    = threadIdx.x >> 5;
    const int lane = threadIdx.x & 31;
    const size_t base = (size_t)row * 1024 + (size_t)w * 256 + lane * 8;

    float4 a0 = *reinterpret_cast<const float4*>(xq + base);
    float4 a1 = *reinterpret_cast<const float4*>(xq + base + 4);
    float sq = a0.x*a0.x + a0.y*a0.y + a0.z*a0.z + a0.w*a0.w
             + a1.x*a1.x + a1.y*a1.y + a1.z*a1.z + a1.w*a1.w;
    float4 b0 = *reinterpret_cast<const float4*>(xkb + base);
    float4 b1 = *reinterpret_cast<const float4*>(xkb + base + 4);
    float sk = b0.x*b0.x + b0.y*b0.y + b0.z*b0.z + b0.w*b0.w
             + b1.x*b1.x + b1.y*b1.y + b1.z*b1.z + b1.w*b1.w;

    #pragma unroll
    for (int o = 16; o; o >>= 1) {
        sq += __shfl_xor_sync(0xFFFFFFFFu, sq, o);
        sk += __shfl_xor_sync(0xFFFFFFFFu, sk, o);
    }
    if (lane == 0) {
        qn[(size_t)row * 4 + w] = sq;
        kn[(size_t)row * 4 + w] = sk;
    }
}

// ---------------- softmax: read H f32, write P hi/lo bf16 --------------------
__global__ __launch_bounds__(256)
void softmax_k(const float* __restrict__ H, bf16* __restrict__ Ph, bf16* __restrict__ Pl)
{
    const int row = blockIdx.x;
    const float* p = H + (size_t)row * 2048;
    const int tid  = threadIdx.x;
    const int lane = tid & 31, warp = tid >> 5;

    float x[8];
    float4 v0 = *reinterpret_cast<const float4*>(p + tid * 8);
    float4 v1 = *reinterpret_cast<const float4*>(p + tid * 8 + 4);
    x[0]=v0.x; x[1]=v0.y; x[2]=v0.z; x[3]=v0.w;
    x[4]=v1.x; x[5]=v1.y; x[6]=v1.z; x[7]=v1.w;

    float m = x[0];
    #pragma unroll
    for (int i = 1; i < 8; i++) m = fmaxf(m, x[i]);
    #pragma unroll
    for (int o = 16; o; o >>= 1) m = fmaxf(m, __shfl_xor_sync(0xFFFFFFFFu, m, o));

    __shared__ float sm[8];
    __shared__ float ss[8];
    if (lane == 0) sm[warp] = m;
    __syncthreads();
    float M = sm[0];
    #pragma unroll
    for (int i = 1; i < 8; i++) M = fmaxf(M, sm[i]);

    float s = 0.f;
    #pragma unroll
    for (int i = 0; i < 8; i++) { x[i] = __expf(x[i] - M); s += x[i]; }
    #pragma unroll
    for (int o = 16; o; o >>= 1) s += __shfl_xor_sync(0xFFFFFFFFu, s, o);
    if (lane == 0) ss[warp] = s;
    __syncthreads();
    float S = 0.f;
    #pragma unroll
    for (int i = 0; i < 8; i++) S += ss[i];
    const float inv = 1.f / S;

    bf162* ph = reinterpret_cast<bf162*>(Ph + (size_t)row * 2048 + tid * 8);
    bf162* pl = reinterpret_cast<bf162*>(Pl + (size_t)row * 2048 + tid * 8);
    #pragma unroll
    for (int i = 0; i < 4; i++) {
        bf162 h, l;
        split2(x[2*i] * inv, x[2*i+1] * inv, h, l);
        ph[i] = h; pl[i] = l;
    }
}

// ---------------- launch ------------------------------------------------------
extern "C" void kernel_launch(void* const* d_in, const int* in_sizes, int n_in,
                              void* d_out, int out_size)
{
    const float* xsa    = (const float*)d_in[0];
    const float* Wq     = (const float*)d_in[1];
    const float* Wk     = (const float*)d_in[2];
    const float* Wv     = (const float*)d_in[3];
    const float* biasW  = (const float*)d_in[4];
    const float* bias2W = (const float*)d_in[5];
    float* out = (float*)d_out;

    float *p_xq, *p_xkb, *p_qn, *p_kn, *p_H;
    bf16 *xsa_h, *xsa_l, *wq_h, *wq_l, *wk_h, *wk_l, *wv_h, *wv_l;
    bf16 *xq_h, *xq_l, *xkb_h, *xkb_l, *P_h, *P_l, *vp_h, *vp_l;
    cudaGetSymbolAddress((void**)&p_xq,  g_xq);
    cudaGetSymbolAddress((void**)&p_xkb, g_xkb);
    cudaGetSymbolAddress((void**)&p_qn,  g_qn);
    cudaGetSymbolAddress((void**)&p_kn,  g_kn);
    cudaGetSymbolAddress((void**)&p_H,   g_H);
    cudaGetSymbolAddress((void**)&xsa_h, g_xsa_h);
    cudaGetSymbolAddress((void**)&xsa_l, g_xsa_l);
    cudaGetSymbolAddress((void**)&wq_h,  g_wq_h);
    cudaGetSymbolAddress((void**)&wq_l,  g_wq_l);
    cudaGetSymbolAddress((void**)&wk_h,  g_wk_h);
    cudaGetSymbolAddress((void**)&wk_l,  g_wk_l);
    cudaGetSymbolAddress((void**)&wv_h,  g_wv_h);
    cudaGetSymbolAddress((void**)&wv_l,  g_wv_l);
    cudaGetSymbolAddress((void**)&xq_h,  g_xq_h);
    cudaGetSymbolAddress((void**)&xq_l,  g_xq_l);
    cudaGetSymbolAddress((void**)&xkb_h, g_xkb_h);
    cudaGetSymbolAddress((void**)&xkb_l, g_xkb_l);
    cudaGetSymbolAddress((void**)&P_h,   g_P_h);
    cudaGetSymbolAddress((void**)&P_l,   g_P_l);
    cudaGetSymbolAddress((void**)&vp_h,  g_vp_h);
    cudaGetSymbolAddress((void**)&vp_l,  g_vp_l);

    cudaFuncSetAttribute(hgemm<0>, cudaFuncAttributeMaxDynamicSharedMemorySize, SMEM_TOT);
    cudaFuncSetAttribute(hgemm<1>, cudaFuncAttributeMaxDynamicSharedMemorySize, SMEM_TOT);
    cudaFuncSetAttribute(hgemm<2>, cudaFuncAttributeMaxDynamicSharedMemorySize, SMEM_TOT);
    cudaFuncSetAttribute(hgemm<3>, cudaFuncAttributeMaxDynamicSharedMemorySize, SMEM_TOT);
    cudaFuncSetAttribute(hgemm<4>, cudaFuncAttributeMaxDynamicSharedMemorySize, SMEM_TOT);

    // (1) fused input split
    split_all<<<4096, 256>>>((const float4*)xsa, (const float4*)Wq,
                             (const float4*)Wk,  (const float4*)Wv,
                             (bf162*)xsa_h, (bf162*)xsa_l, (bf162*)wq_h, (bf162*)wq_l,
                             (bf162*)wk_h,  (bf162*)wk_l,  (bf162*)wv_h, (bf162*)wv_l);
    // (2) S3 first (independent): Vp = xsa @ Wv3[k]
    hgemm<3><<<dim3(4, 8, 8), 256, SMEM_TOT>>>(xsa_h, xsa_l, wv_h, wv_l,
                                               nullptr, vp_h, vp_l, nullptr, nullptr);
    // (3) S0: xq = xsa @ Wq^T
    hgemm<0><<<dim3(8, 16, 1), 256, SMEM_TOT>>>(xsa_h, xsa_l, wq_h, wq_l,
                                                p_xq, xq_h, xq_l, nullptr, nullptr);
    // (4) S1: xkb = xsa @ Wk^T + biasW
    hgemm<1><<<dim3(8, 16, 1), 256, SMEM_TOT>>>(xsa_h, xsa_l, wk_h, wk_l,
                                                p_xkb, xkb_h, xkb_l, biasW, nullptr);
    // (5) norms
    norms_k<<<4096, 128>>>(p_xq, p_xkb, p_qn, p_kn);
    // (6) S2: H = (2*xq.xkb^T - qn - kn)/16   <- ncu -s 5 -c 1 lands here
    hgemm<2><<<dim3(16, 8, 8), 256, SMEM_TOT>>>(xq_h, xq_l, xkb_h, xkb_l,
                                                p_H, nullptr, nullptr, p_qn, p_kn);
    // (7) softmax -> P hi/lo
    softmax_k<<<8 * 2048, 256>>>(p_H, P_h, P_l);
    // (8) S4: out = P @ Vp + bias2
    hgemm<4><<<dim3(4, 8, 8), 256, SMEM_TOT>>>(P_h, P_l, vp_h, vp_l,
                                               out, nullptr, nullptr, bias2W, nullptr);
}

// round 7
// speedup vs baseline: 1.0714x; 1.0714x over previous
#include <cuda_runtime.h>
#include <cuda_bf16.h>
#include <cstdint>

#define BB 2
#define LL 2048
#define EE 512
#define KH 4
#define KE 256
typedef __nv_bfloat16 bf16;
typedef __nv_bfloat162 bf162;

// ---------------- scratch (device globals) ----------------------------------
// xqk: [4096 rows][2048 cols] = [xq (cols 0..1023) | xkb (cols 1024..2047)]
__device__ float g_xqk [(size_t)4096*2048];
__device__ float g_qn [4096*4];
__device__ float g_kn [4096*4];
__device__ float g_H  [(size_t)8*2048*2048];

__device__ bf16 g_xsa_h[(size_t)4096*512],  g_xsa_l[(size_t)4096*512];
__device__ bf16 g_wqk_h[(size_t)2048*512],  g_wqk_l[(size_t)2048*512];   // [Wq;Wk]
__device__ bf16 g_wv_h [(size_t)512*2048],  g_wv_l [(size_t)512*2048];
__device__ bf16 g_xqk_h[(size_t)4096*2048], g_xqk_l[(size_t)4096*2048];
__device__ bf16 g_P_h  [(size_t)8*2048*2048], g_P_l[(size_t)8*2048*2048];
__device__ bf16 g_vp_h [(size_t)8*2048*512],  g_vp_l[(size_t)8*2048*512];

// ---------------- helpers ----------------------------------------------------
__device__ __forceinline__ uint32_t smem_u32(const void* p) {
    uint32_t a;
    asm("{ .reg .u64 t; cvta.to.shared.u64 t, %1; cvt.u32.u64 %0, t; }" : "=r"(a) : "l"(p));
    return a;
}
__device__ __forceinline__ void cpa16(uint32_t d, const void* s) {
    asm volatile("cp.async.cg.shared.global [%0], [%1], 16;" :: "r"(d), "l"(s));
}
#define CP_COMMIT() asm volatile("cp.async.commit_group;" ::: "memory")
#define CP_WAIT1()  asm volatile("cp.async.wait_group 1;" ::: "memory")

__device__ __forceinline__ void ldsm_x4(uint32_t& r0, uint32_t& r1, uint32_t& r2,
                                        uint32_t& r3, uint32_t a) {
    asm volatile("ldmatrix.sync.aligned.m8n8.x4.shared.b16 {%0,%1,%2,%3}, [%4];"
                 : "=r"(r0), "=r"(r1), "=r"(r2), "=r"(r3) : "r"(a));
}
__device__ __forceinline__ void ldsm_x4t(uint32_t& r0, uint32_t& r1, uint32_t& r2,
                                         uint32_t& r3, uint32_t a) {
    asm volatile("ldmatrix.sync.aligned.m8n8.x4.trans.shared.b16 {%0,%1,%2,%3}, [%4];"
                 : "=r"(r0), "=r"(r1), "=r"(r2), "=r"(r3) : "r"(a));
}
__device__ __forceinline__ void mma16816(float c[4], const uint32_t a[4],
                                         const uint32_t bq[2]) {
    asm volatile("mma.sync.aligned.m16n8k16.row.col.f32.bf16.bf16.f32 "
                 "{%0,%1,%2,%3}, {%4,%5,%6,%7}, {%8,%9}, {%0,%1,%2,%3};"
                 : "+f"(c[0]), "+f"(c[1]), "+f"(c[2]), "+f"(c[3])
                 : "r"(a[0]), "r"(a[1]), "r"(a[2]), "r"(a[3]), "r"(bq[0]), "r"(bq[1]));
}
__device__ __forceinline__ void split2(float a, float b, bf162& h, bf162& l) {
    h = __floats2bfloat162_rn(a, b);
    l = __floats2bfloat162_rn(a - __bfloat162float(h.x), b - __bfloat162float(h.y));
}

// ---------------- GEMM: C[M][N] = A[M][K] * B^T ------------------------------
// STAGE 0: [xq|xkb] = xsa @ [Wq;Wk]^T (+bias on xkb half)  NT  M=4096 N=2048 K=512
// STAGE 2: H = (2*xq.xkb^T - qn - kn)/16                   NT  z=8 M=N=2048 K=256
// STAGE 3: Vp = xsa @ Wv3[k]  (Wv flat chunk k*262144)     NN  z=8 M=2048 N=512 K=512
// STAGE 4: out = P @ Vp + bias2                            NN  z=8 M=2048 N=512 K=2048
// Split bf16 hi/lo; acc = Ah*Bh + Ah*Bl + Al*Bh in fp32.
// CTA tile 128x128, warp tile 32x64 (4m x 2n), BK=32, 3-stage cp.async, 2 CTA/SM.

template<int STAGE>
__global__ __launch_bounds__(256, 2)
void hgemm(const bf16* __restrict__ gAh, const bf16* __restrict__ gAl,
           const bf16* __restrict__ gBh, const bf16* __restrict__ gBl,
           float* __restrict__ Cf, bf16* __restrict__ Ch, bf16* __restrict__ Cl,
           const float* __restrict__ aux1, const float* __restrict__ aux2)
{
    constexpr bool NT  = (STAGE == 0 || STAGE == 2);
    constexpr int  Kd  = (STAGE == 0) ? 512  : (STAGE == 2 ? 256  : (STAGE == 3 ? 512 : 2048));
    constexpr int  ldA = (STAGE == 0) ? 512  : (STAGE == 2 ? 2048 : (STAGE == 3 ? 512 : 2048));
    constexpr int  ldB = (STAGE == 0) ? 512  : (STAGE == 2 ? 2048 : 512);
    constexpr int  ldC = (STAGE == 0) ? 2048 : (STAGE == 2 ? 2048 : (STAGE == 3 ? 512 : 2048));
    constexpr int  NC  = Kd / 32;

    extern __shared__ char smem[];
    const uint32_t sb = smem_u32(smem);
    const int tid = threadIdx.x;
    const int z = blockIdx.z, b = z >> 2, k = z & 3;

    const bf16 *Ah = gAh, *Al = gAl, *Bh = gBh, *Bl = gBl;
    size_t coff = 0;
    if (STAGE == 2) {
        size_t o = (size_t)(b * 2048) * 2048 + (size_t)k * 256;
        Ah += o; Al += o; Bh += o + 1024; Bl += o + 1024;
        coff = (size_t)z * 2048 * 2048;
    } else if (STAGE == 3) {
        size_t oa = (size_t)(b * 2048) * 512;
        Ah += oa; Al += oa;
        size_t ob = (size_t)k * 512 * 512;
        Bh += ob; Bl += ob;
        coff = (size_t)z * 2048 * 512;
    } else if (STAGE == 4) {
        size_t oa = (size_t)z * 2048 * 2048;
        Ah += oa; Al += oa;
        size_t ob = (size_t)z * 2048 * 512;
        Bh += ob; Bl += ob;
        coff = (size_t)(b * 2048) * 2048 + (size_t)k * 512;
    }
    const int yBlk = blockIdx.y * 128, xBlk = blockIdx.x * 128;
    Ah += (size_t)yBlk * ldA; Al += (size_t)yBlk * ldA;
    if (NT) { Bh += (size_t)xBlk * ldB; Bl += (size_t)xBlk * ldB; }
    else    { Bh += xBlk; Bl += xBlk; }
    if (Cf) Cf += coff;
    if (Ch) { Ch += coff; Cl += coff; }

    const int wid = tid >> 5, lane = tid & 31;
    const int m0 = (wid & 3) * 32, n0 = (wid >> 2) * 64;

    float acc[2][8][4];
    #pragma unroll
    for (int am = 0; am < 2; am++)
        #pragma unroll
        for (int j = 0; j < 8; j++)
            #pragma unroll
            for (int q = 0; q < 4; q++) acc[am][j][q] = 0.f;

    auto load_chunk = [&](int c, int buf) {
        uint32_t s0 = sb + buf * 32768;
        #pragma unroll
        for (int h = 0; h < 2; h++) {
            int s = tid + h * 256;
            int r = s >> 2, q = s & 3;
            uint32_t d = s0 + r * 64 + ((q ^ ((r >> 1) & 3)) << 4);
            cpa16(d,        Ah + (size_t)r * ldA + c * 32 + q * 8);
            cpa16(d + 8192, Al + (size_t)r * ldA + c * 32 + q * 8);
        }
        if (NT) {
            #pragma unroll
            for (int h = 0; h < 2; h++) {
                int s = tid + h * 256;
                int r = s >> 2, q = s & 3;
                uint32_t d = s0 + 16384 + r * 64 + ((q ^ ((r >> 1) & 3)) << 4);
                cpa16(d,        Bh + (size_t)r * ldB + c * 32 + q * 8);
                cpa16(d + 8192, Bl + (size_t)r * ldB + c * 32 + q * 8);
            }
        } else {
            #pragma unroll
            for (int h = 0; h < 2; h++) {
                int s = tid + h * 256;
                int kk = s >> 4, q = s & 15;
                uint32_t d = s0 + 16384 + kk * 256 + ((q ^ (kk & 7)) << 4);
                cpa16(d,        Bh + (size_t)(c * 32 + kk) * ldB + q * 8);
                cpa16(d + 8192, Bl + (size_t)(c * 32 + kk) * ldB + q * 8);
            }
        }
    };

    load_chunk(0, 0); CP_COMMIT();
    load_chunk(1, 1); CP_COMMIT();

    #pragma unroll 1
    for (int c = 0; c < NC; c++) {
        CP_WAIT1();
        __syncthreads();
        if (c + 2 < NC) load_chunk(c + 2, (c + 2) % 3);
        CP_COMMIT();

        const uint32_t s0 = sb + (c % 3) * 32768;
        #pragma unroll
        for (int s = 0; s < 2; s++) {
            uint32_t ah[2][4], al[2][4];
            #pragma unroll
            for (int am = 0; am < 2; am++) {
                int row = m0 + am * 16 + (lane & 15);
                int q = s * 2 + (lane >> 4);
                uint32_t addr = s0 + row * 64 + ((q ^ ((row >> 1) & 3)) << 4);
                ldsm_x4(ah[am][0], ah[am][1], ah[am][2], ah[am][3], addr);
                ldsm_x4(al[am][0], al[am][1], al[am][2], al[am][3], addr + 8192);
            }
            #pragma unroll
            for (int bp = 0; bp < 2; bp++) {
                uint32_t bh[4][2], bl[4][2];
                if (NT) {
                    #pragma unroll
                    for (int i = 0; i < 2; i++) {
                        int bn = 2 * bp + i;
                        int row = n0 + bn * 16 + (lane & 15);
                        int q = s * 2 + (lane >> 4);
                        uint32_t addr = s0 + 16384 + row * 64 + ((q ^ ((row >> 1) & 3)) << 4);
                        uint32_t r0, r1, r2, r3;
                        ldsm_x4(r0, r1, r2, r3, addr);
                        bh[2*i][0] = r0; bh[2*i][1] = r2;
                        bh[2*i+1][0] = r1; bh[2*i+1][1] = r3;
                        ldsm_x4(r0, r1, r2, r3, addr + 8192);
                        bl[2*i][0] = r0; bl[2*i][1] = r2;
                        bl[2*i+1][0] = r1; bl[2*i+1][1] = r3;
                    }
                } else {
                    #pragma unroll
                    for (int i = 0; i < 2; i++) {
                        int bn = 2 * bp + i;
                        int g = lane >> 3;
                        int kk = s * 16 + (g & 1) * 8 + (lane & 7);
                        int q = (n0 + bn * 16) / 8 + (g >> 1);
                        uint32_t addr = s0 + 16384 + kk * 256 + ((q ^ (kk & 7)) << 4);
                        uint32_t r0, r1, r2, r3;
                        ldsm_x4t(r0, r1, r2, r3, addr);
                        bh[2*i][0] = r0; bh[2*i][1] = r1;
                        bh[2*i+1][0] = r2; bh[2*i+1][1] = r3;
                        ldsm_x4t(r0, r1, r2, r3, addr + 8192);
                        bl[2*i][0] = r0; bl[2*i][1] = r1;
                        bl[2*i+1][0] = r2; bl[2*i+1][1] = r3;
                    }
                }
                #pragma unroll
                for (int am = 0; am < 2; am++)
                    #pragma unroll
                    for (int jj = 0; jj < 4; jj++)
                        mma16816(acc[am][4*bp+jj], ah[am], bh[jj]);
                #pragma unroll
                for (int am = 0; am < 2; am++)
                    #pragma unroll
                    for (int jj = 0; jj < 4; jj++)
                        mma16816(acc[am][4*bp+jj], ah[am], bl[jj]);
                #pragma unroll
                for (int am = 0; am < 2; am++)
                    #pragma unroll
                    for (int jj = 0; jj < 4; jj++)
                        mma16816(acc[am][4*bp+jj], al[am], bh[jj]);
            }
        }
    }

    // ---- epilogue ----
    #pragma unroll
    for (int am = 0; am < 2; am++) {
        const int gi0 = yBlk + m0 + am * 16 + (lane >> 2);
        #pragma unroll
        for (int j = 0; j < 8; j++) {
            const int gj = xBlk + n0 + j * 8 + (lane & 3) * 2;
            #pragma unroll
            for (int half = 0; half < 2; half++) {
                const int gi = gi0 + half * 8;
                float v0 = acc[am][j][half * 2 + 0];
                float v1 = acc[am][j][half * 2 + 1];
                if (STAGE == 0) {
                    if (gj >= 1024) {           // xkb half: add biasW
                        const int c0 = gj - 1024;
                        v0 += aux1[((c0 + 0) & 255) * 4 + ((c0 + 0) >> 8)];
                        v1 += aux1[((c0 + 1) & 255) * 4 + ((c0 + 1) >> 8)];
                    }
                } else if (STAGE == 2) {
                    const float qi = aux1[(size_t)(b * 2048 + gi) * 4 + k];
                    v0 = (2.f * v0 - qi - aux2[(size_t)(b * 2048 + gj + 0) * 4 + k]) * 0.0625f;
                    v1 = (2.f * v1 - qi - aux2[(size_t)(b * 2048 + gj + 1) * 4 + k]) * 0.0625f;
                } else if (STAGE == 4) {
                    v0 += aux1[(gj + 0) * 4 + k];
                    v1 += aux1[(gj + 1) * 4 + k];
                }
                const size_t idx = (size_t)gi * ldC + gj;
                if (STAGE == 0 || STAGE == 2 || STAGE == 4)
                    *reinterpret_cast<float2*>(Cf + idx) = make_float2(v0, v1);
                if (STAGE == 0 || STAGE == 3) {
                    bf162 h, l;
                    split2(v0, v1, h, l);
                    *reinterpret_cast<bf162*>(Ch + idx) = h;
                    *reinterpret_cast<bf162*>(Cl + idx) = l;
                }
            }
        }
    }
}

// ---------------- fused fp32 -> bf16 hi/lo split (all inputs) ----------------
// wq -> wqk[0:1024*512), wk -> wqk[1024*512:)
__global__ void split_all(const float4* __restrict__ xsa, const float4* __restrict__ wq,
                          const float4* __restrict__ wk,  const float4* __restrict__ wv,
                          bf162* __restrict__ xh, bf162* __restrict__ xl,
                          bf162* __restrict__ wqkh, bf162* __restrict__ wqkl,
                          bf162* __restrict__ vh, bf162* __restrict__ vl)
{
    int i = blockIdx.x * 256 + threadIdx.x;
    const float4* src;
    bf162 *hi, *lo;
    int j;
    if (i < 524288)       { src = xsa; hi = xh; lo = xl; j = i; }
    else if (i < 655360)  { src = wq;  hi = wqkh; lo = wqkl; j = i - 524288; }
    else if (i < 786432)  { src = wk;  hi = wqkh + 262144; lo = wqkl + 262144; j = i - 655360; }
    else                  { src = wv;  hi = vh; lo = vl; j = i - 786432; }
    float4 v = src[j];
    bf162 h0, l0, h1, l1;
    split2(v.x, v.y, h0, l0);
    split2(v.z, v.w, h1, l1);
    hi[2 * j] = h0; hi[2 * j + 1] = h1;
    lo[2 * j] = l0; lo[2 * j + 1] = l1;
}

// ---------------- row norms (from merged xqk f32) -----------------------------
__global__ void norms_k(const float* __restrict__ xqk,
                        float* __restrict__ qn, float* __restrict__ kn)
{
    const int row  = blockIdx.x;
    const int w    = threadIdx.x >> 5;
    const int lane = threadIdx.x & 31;
    const size_t base = (size_t)row * 2048 + (size_t)w * 256 + lane * 8;

    float4 a0 = *reinterpret_cast<const float4*>(xqk + base);
    float4 a1 = *reinterpret_cast<const float4*>(xqk + base + 4);
    float sq = a0.x*a0.x + a0.y*a0.y + a0.z*a0.z + a0.w*a0.w
             + a1.x*a1.x + a1.y*a1.y + a1.z*a1.z + a1.w*a1.w;
    float4 b0 = *reinterpret_cast<const float4*>(xqk + base + 1024);
    float4 b1 = *reinterpret_cast<const float4*>(xqk + base + 1028);
    float sk = b0.x*b0.x + b0.y*b0.y + b0.z*b0.z + b0.w*b0.w
             + b1.x*b1.x + b1.y*b1.y + b1.z*b1.z + b1.w*b1.w;

    #pragma unroll
    for (int o = 16; o; o >>= 1) {
        sq += __shfl_xor_sync(0xFFFFFFFFu, sq, o);
        sk += __shfl_xor_sync(0xFFFFFFFFu, sk, o);
    }
    if (lane == 0) {
        qn[(size_t)row * 4 + w] = sq;
        kn[(size_t)row * 4 + w] = sk;
    }
}

// ---------------- softmax: read H f32, write P hi/lo bf16 --------------------
__global__ __launch_bounds__(256)
void softmax_k(const float* __restrict__ H, bf16* __restrict__ Ph, bf16* __restrict__ Pl)
{
    const int row = blockIdx.x;
    const float* p = H + (size_t)row * 2048;
    const int tid  = threadIdx.x;
    const int lane = tid & 31, warp = tid >> 5;

    float x[8];
    float4 v0 = *reinterpret_cast<const float4*>(p + tid * 8);
    float4 v1 = *reinterpret_cast<const float4*>(p + tid * 8 + 4);
    x[0]=v0.x; x[1]=v0.y; x[2]=v0.z; x[3]=v0.w;
    x[4]=v1.x; x[5]=v1.y; x[6]=v1.z; x[7]=v1.w;

    float m = x[0];
    #pragma unroll
    for (int i = 1; i < 8; i++) m = fmaxf(m, x[i]);
    #pragma unroll
    for (int o = 16; o; o >>= 1) m = fmaxf(m, __shfl_xor_sync(0xFFFFFFFFu, m, o));

    __shared__ float sm[8];
    __shared__ float ss[8];
    if (lane == 0) sm[warp] = m;
    __syncthreads();
    float M = sm[0];
    #pragma unroll
    for (int i = 1; i < 8; i++) M = fmaxf(M, sm[i]);

    float s = 0.f;
    #pragma unroll
    for (int i = 0; i < 8; i++) { x[i] = __expf(x[i] - M); s += x[i]; }
    #pragma unroll
    for (int o = 16; o; o >>= 1) s += __shfl_xor_sync(0xFFFFFFFFu, s, o);
    if (lane == 0) ss[warp] = s;
    __syncthreads();
    float S = 0.f;
    #pragma unroll
    for (int i = 0; i < 8; i++) S += ss[i];
    const float inv = 1.f / S;

    bf162* ph = reinterpret_cast<bf162*>(Ph + (size_t)row * 2048 + tid * 8);
    bf162* pl = reinterpret_cast<bf162*>(Pl + (size_t)row * 2048 + tid * 8);
    #pragma unroll
    for (int i = 0; i < 4; i++) {
        bf162 h, l;
        split2(x[2*i] * inv, x[2*i+1] * inv, h, l);
        ph[i] = h; pl[i] = l;
    }
}

// ---------------- launch ------------------------------------------------------
extern "C" void kernel_launch(void* const* d_in, const int* in_sizes, int n_in,
                              void* d_out, int out_size)
{
    const float* xsa    = (const float*)d_in[0];
    const float* Wq     = (const float*)d_in[1];
    const float* Wk     = (const float*)d_in[2];
    const float* Wv     = (const float*)d_in[3];
    const float* biasW  = (const float*)d_in[4];
    const float* bias2W = (const float*)d_in[5];
    float* out = (float*)d_out;

    float *p_xqk, *p_qn, *p_kn, *p_H;
    bf16 *xsa_h, *xsa_l, *wqk_h, *wqk_l, *wv_h, *wv_l;
    bf16 *xqk_h, *xqk_l, *P_h, *P_l, *vp_h, *vp_l;
    cudaGetSymbolAddress((void**)&p_xqk, g_xqk);
    cudaGetSymbolAddress((void**)&p_qn,  g_qn);
    cudaGetSymbolAddress((void**)&p_kn,  g_kn);
    cudaGetSymbolAddress((void**)&p_H,   g_H);
    cudaGetSymbolAddress((void**)&xsa_h, g_xsa_h);
    cudaGetSymbolAddress((void**)&xsa_l, g_xsa_l);
    cudaGetSymbolAddress((void**)&wqk_h, g_wqk_h);
    cudaGetSymbolAddress((void**)&wqk_l, g_wqk_l);
    cudaGetSymbolAddress((void**)&wv_h,  g_wv_h);
    cudaGetSymbolAddress((void**)&wv_l,  g_wv_l);
    cudaGetSymbolAddress((void**)&xqk_h, g_xqk_h);
    cudaGetSymbolAddress((void**)&xqk_l, g_xqk_l);
    cudaGetSymbolAddress((void**)&P_h,   g_P_h);
    cudaGetSymbolAddress((void**)&P_l,   g_P_l);
    cudaGetSymbolAddress((void**)&vp_h,  g_vp_h);
    cudaGetSymbolAddress((void**)&vp_l,  g_vp_l);

    cudaFuncSetAttribute(hgemm<0>, cudaFuncAttributeMaxDynamicSharedMemorySize, 98304);
    cudaFuncSetAttribute(hgemm<2>, cudaFuncAttributeMaxDynamicSharedMemorySize, 98304);
    cudaFuncSetAttribute(hgemm<3>, cudaFuncAttributeMaxDynamicSharedMemorySize, 98304);
    cudaFuncSetAttribute(hgemm<4>, cudaFuncAttributeMaxDynamicSharedMemorySize, 98304);

    // (1) fused input split
    split_all<<<4096, 256>>>((const float4*)xsa, (const float4*)Wq,
                             (const float4*)Wk,  (const float4*)Wv,
                             (bf162*)xsa_h, (bf162*)xsa_l,
                             (bf162*)wqk_h, (bf162*)wqk_l,
                             (bf162*)wv_h,  (bf162*)wv_l);
    // (2) S3 (independent): Vp = xsa @ Wv3[k]
    hgemm<3><<<dim3(4, 16, 8), 256, 98304>>>(xsa_h, xsa_l, wv_h, wv_l,
                                             nullptr, vp_h, vp_l, nullptr, nullptr);
    // (3) S0 merged: [xq|xkb] = xsa @ [Wq;Wk]^T (+bias on xkb)
    hgemm<0><<<dim3(16, 32, 1), 256, 98304>>>(xsa_h, xsa_l, wqk_h, wqk_l,
                                              p_xqk, xqk_h, xqk_l, biasW, nullptr);
    // (4) norms
    norms_k<<<4096, 128>>>(p_xqk, p_qn, p_kn);
    // (5) S2: H = (2*xq.xkb^T - qn - kn)/16
    hgemm<2><<<dim3(16, 16, 8), 256, 98304>>>(xqk_h, xqk_l, xqk_h, xqk_l,
                                              p_H, nullptr, nullptr, p_qn, p_kn);
    // (6) softmax -> P hi/lo
    softmax_k<<<8 * 2048, 256>>>(p_H, P_h, P_l);
    // (7) S4: out = P @ Vp + bias2
    hgemm<4><<<dim3(4, 16, 8), 256, 98304>>>(P_h, P_l, vp_h, vp_l,
                                             out, nullptr, nullptr, bias2W, nullptr);
}

// round 8
// speedup vs baseline: 1.2658x; 1.1814x over previous
#include <cuda_runtime.h>
#include <cuda_fp16.h>
#include <cstdint>

#define BB 2
#define LL 2048
#define EE 512
#define KH 4
#define KE 256
typedef __half fp16;
typedef __half2 fp162;

// ---------------- scratch (device globals) ----------------------------------
// xqk: [4096 rows][2048 cols] = [xq (cols 0..1023) | xkb (cols 1024..2047)]
__device__ float g_xqk [(size_t)4096*2048];
__device__ float g_qn [4096*4];
__device__ float g_kn [4096*4];
__device__ float g_H  [(size_t)8*2048*2048];

__device__ fp16 g_xsa_h[(size_t)4096*512],  g_xsa_l[(size_t)4096*512];
__device__ fp16 g_wqk_h[(size_t)2048*512],  g_wqk_l[(size_t)2048*512];   // [Wq;Wk]
__device__ fp16 g_wv_h [(size_t)512*2048],  g_wv_l [(size_t)512*2048];
__device__ fp16 g_xqk_h[(size_t)4096*2048], g_xqk_l[(size_t)4096*2048];
__device__ fp16 g_P_h  [(size_t)8*2048*2048], g_P_l[(size_t)8*2048*2048];
__device__ fp16 g_vp_h [(size_t)8*2048*512];

// ---------------- helpers ----------------------------------------------------
__device__ __forceinline__ uint32_t smem_u32(const void* p) {
    uint32_t a;
    asm("{ .reg .u64 t; cvta.to.shared.u64 t, %1; cvt.u32.u64 %0, t; }" : "=r"(a) : "l"(p));
    return a;
}
__device__ __forceinline__ void cpa16(uint32_t d, const void* s) {
    asm volatile("cp.async.cg.shared.global [%0], [%1], 16;" :: "r"(d), "l"(s));
}
#define CP_COMMIT() asm volatile("cp.async.commit_group;" ::: "memory")
#define CP_WAIT1()  asm volatile("cp.async.wait_group 1;" ::: "memory")

__device__ __forceinline__ void ldsm_x4(uint32_t& r0, uint32_t& r1, uint32_t& r2,
                                        uint32_t& r3, uint32_t a) {
    asm volatile("ldmatrix.sync.aligned.m8n8.x4.shared.b16 {%0,%1,%2,%3}, [%4];"
                 : "=r"(r0), "=r"(r1), "=r"(r2), "=r"(r3) : "r"(a));
}
__device__ __forceinline__ void ldsm_x4t(uint32_t& r0, uint32_t& r1, uint32_t& r2,
                                         uint32_t& r3, uint32_t a) {
    asm volatile("ldmatrix.sync.aligned.m8n8.x4.trans.shared.b16 {%0,%1,%2,%3}, [%4];"
                 : "=r"(r0), "=r"(r1), "=r"(r2), "=r"(r3) : "r"(a));
}
__device__ __forceinline__ void mma16816(float c[4], const uint32_t a[4],
                                         const uint32_t bq[2]) {
    asm volatile("mma.sync.aligned.m16n8k16.row.col.f32.f16.f16.f32 "
                 "{%0,%1,%2,%3}, {%4,%5,%6,%7}, {%8,%9}, {%0,%1,%2,%3};"
                 : "+f"(c[0]), "+f"(c[1]), "+f"(c[2]), "+f"(c[3])
                 : "r"(a[0]), "r"(a[1]), "r"(a[2]), "r"(a[3]), "r"(bq[0]), "r"(bq[1]));
}
__device__ __forceinline__ void split2(float a, float b, fp162& h, fp162& l) {
    h = __floats2half2_rn(a, b);
    l = __floats2half2_rn(a - __half2float(__low2half(h)),
                          b - __half2float(__high2half(h)));
}

// ---------------- GEMM: C[M][N] = A[M][K] * B^T ------------------------------
// STAGE 0: [xq|xkb] = xsa @ [Wq;Wk]^T (+bias on xkb half)  NT  3-product
// STAGE 2: H = (2*xq.xkb^T - qn - kn)/16                   NT  3-product
// STAGE 3: Vp = xsa @ Wv3[k] (flat chunk k*262144)         NN  2-product (B hi only)
// STAGE 4: out = P @ Vp + bias2                            NN  2-product (B hi only)
// fp16 hi/lo splits; 3-product = Ah*Bh + Ah*Bl + Al*Bh; 2-product = Ah*Bh + Al*Bh.
// CTA tile 128x128, warp tile 32x64 (4m x 2n), BK=32, 3-stage cp.async, 2 CTA/SM.

template<int STAGE>
__global__ __launch_bounds__(256, 2)
void hgemm(const fp16* __restrict__ gAh, const fp16* __restrict__ gAl,
           const fp16* __restrict__ gBh, const fp16* __restrict__ gBl,
           float* __restrict__ Cf, fp16* __restrict__ Ch, fp16* __restrict__ Cl,
           const float* __restrict__ aux1, const float* __restrict__ aux2)
{
    constexpr bool NT     = (STAGE == 0 || STAGE == 2);
    constexpr bool USE_BL = (STAGE == 0 || STAGE == 2);   // logit path: 3-product
    constexpr int  Kd  = (STAGE == 0) ? 512  : (STAGE == 2 ? 256  : (STAGE == 3 ? 512 : 2048));
    constexpr int  ldA = (STAGE == 0) ? 512  : (STAGE == 2 ? 2048 : (STAGE == 3 ? 512 : 2048));
    constexpr int  ldB = (STAGE == 0) ? 512  : (STAGE == 2 ? 2048 : 512);
    constexpr int  ldC = (STAGE == 0) ? 2048 : (STAGE == 2 ? 2048 : (STAGE == 3 ? 512 : 2048));
    constexpr int  NC  = Kd / 32;

    extern __shared__ char smem[];
    const uint32_t sb = smem_u32(smem);
    const int tid = threadIdx.x;
    const int z = blockIdx.z, b = z >> 2, k = z & 3;

    const fp16 *Ah = gAh, *Al = gAl, *Bh = gBh, *Bl = gBl;
    size_t coff = 0;
    if (STAGE == 2) {
        size_t o = (size_t)(b * 2048) * 2048 + (size_t)k * 256;
        Ah += o; Al += o; Bh += o + 1024; Bl += o + 1024;
        coff = (size_t)z * 2048 * 2048;
    } else if (STAGE == 3) {
        size_t oa = (size_t)(b * 2048) * 512;
        Ah += oa; Al += oa;
        size_t ob = (size_t)k * 512 * 512;
        Bh += ob; Bl += ob;
        coff = (size_t)z * 2048 * 512;
    } else if (STAGE == 4) {
        size_t oa = (size_t)z * 2048 * 2048;
        Ah += oa; Al += oa;
        size_t ob = (size_t)z * 2048 * 512;
        Bh += ob; Bl += ob;
        coff = (size_t)(b * 2048) * 2048 + (size_t)k * 512;
    }
    const int yBlk = blockIdx.y * 128, xBlk = blockIdx.x * 128;
    Ah += (size_t)yBlk * ldA; Al += (size_t)yBlk * ldA;
    if (NT) { Bh += (size_t)xBlk * ldB; Bl += (size_t)xBlk * ldB; }
    else    { Bh += xBlk; Bl += xBlk; }
    if (Cf) Cf += coff;
    if (Ch) { Ch += coff; if (Cl) Cl += coff; }

    const int wid = tid >> 5, lane = tid & 31;
    const int m0 = (wid & 3) * 32, n0 = (wid >> 2) * 64;

    float acc[2][8][4];
    #pragma unroll
    for (int am = 0; am < 2; am++)
        #pragma unroll
        for (int j = 0; j < 8; j++)
            #pragma unroll
            for (int q = 0; q < 4; q++) acc[am][j][q] = 0.f;

    auto load_chunk = [&](int c, int buf) {
        uint32_t s0 = sb + buf * 32768;
        #pragma unroll
        for (int h = 0; h < 2; h++) {
            int s = tid + h * 256;
            int r = s >> 2, q = s & 3;
            uint32_t d = s0 + r * 64 + ((q ^ ((r >> 1) & 3)) << 4);
            cpa16(d,        Ah + (size_t)r * ldA + c * 32 + q * 8);
            cpa16(d + 8192, Al + (size_t)r * ldA + c * 32 + q * 8);
        }
        if (NT) {
            #pragma unroll
            for (int h = 0; h < 2; h++) {
                int s = tid + h * 256;
                int r = s >> 2, q = s & 3;
                uint32_t d = s0 + 16384 + r * 64 + ((q ^ ((r >> 1) & 3)) << 4);
                cpa16(d, Bh + (size_t)r * ldB + c * 32 + q * 8);
                if (USE_BL) cpa16(d + 8192, Bl + (size_t)r * ldB + c * 32 + q * 8);
            }
        } else {
            #pragma unroll
            for (int h = 0; h < 2; h++) {
                int s = tid + h * 256;
                int kk = s >> 4, q = s & 15;
                uint32_t d = s0 + 16384 + kk * 256 + ((q ^ (kk & 7)) << 4);
                cpa16(d, Bh + (size_t)(c * 32 + kk) * ldB + q * 8);
                if (USE_BL) cpa16(d + 8192, Bl + (size_t)(c * 32 + kk) * ldB + q * 8);
            }
        }
    };

    load_chunk(0, 0); CP_COMMIT();
    load_chunk(1, 1); CP_COMMIT();

    #pragma unroll 1
    for (int c = 0; c < NC; c++) {
        CP_WAIT1();
        __syncthreads();
        if (c + 2 < NC) load_chunk(c + 2, (c + 2) % 3);
        CP_COMMIT();

        const uint32_t s0 = sb + (c % 3) * 32768;
        #pragma unroll
        for (int s = 0; s < 2; s++) {
            uint32_t ah[2][4], al[2][4];
            #pragma unroll
            for (int am = 0; am < 2; am++) {
                int row = m0 + am * 16 + (lane & 15);
                int q = s * 2 + (lane >> 4);
                uint32_t addr = s0 + row * 64 + ((q ^ ((row >> 1) & 3)) << 4);
                ldsm_x4(ah[am][0], ah[am][1], ah[am][2], ah[am][3], addr);
                ldsm_x4(al[am][0], al[am][1], al[am][2], al[am][3], addr + 8192);
            }
            #pragma unroll
            for (int bp = 0; bp < 2; bp++) {
                uint32_t bh[4][2], bl[4][2];
                if (NT) {
                    #pragma unroll
                    for (int i = 0; i < 2; i++) {
                        int bn = 2 * bp + i;
                        int row = n0 + bn * 16 + (lane & 15);
                        int q = s * 2 + (lane >> 4);
                        uint32_t addr = s0 + 16384 + row * 64 + ((q ^ ((row >> 1) & 3)) << 4);
                        uint32_t r0, r1, r2, r3;
                        ldsm_x4(r0, r1, r2, r3, addr);
                        bh[2*i][0] = r0; bh[2*i][1] = r2;
                        bh[2*i+1][0] = r1; bh[2*i+1][1] = r3;
                        if (USE_BL) {
                            ldsm_x4(r0, r1, r2, r3, addr + 8192);
                            bl[2*i][0] = r0; bl[2*i][1] = r2;
                            bl[2*i+1][0] = r1; bl[2*i+1][1] = r3;
                        }
                    }
                } else {
                    #pragma unroll
                    for (int i = 0; i < 2; i++) {
                        int bn = 2 * bp + i;
                        int g = lane >> 3;
                        int kk = s * 16 + (g & 1) * 8 + (lane & 7);
                        int q = (n0 + bn * 16) / 8 + (g >> 1);
                        uint32_t addr = s0 + 16384 + kk * 256 + ((q ^ (kk & 7)) << 4);
                        uint32_t r0, r1, r2, r3;
                        ldsm_x4t(r0, r1, r2, r3, addr);
                        bh[2*i][0] = r0; bh[2*i][1] = r1;
                        bh[2*i+1][0] = r2; bh[2*i+1][1] = r3;
                        if (USE_BL) {
                            ldsm_x4t(r0, r1, r2, r3, addr + 8192);
                            bl[2*i][0] = r0; bl[2*i][1] = r1;
                            bl[2*i+1][0] = r2; bl[2*i+1][1] = r3;
                        }
                    }
                }
                #pragma unroll
                for (int am = 0; am < 2; am++)
                    #pragma unroll
                    for (int jj = 0; jj < 4; jj++)
                        mma16816(acc[am][4*bp+jj], ah[am], bh[jj]);
                if (USE_BL) {
                    #pragma unroll
                    for (int am = 0; am < 2; am++)
                        #pragma unroll
                        for (int jj = 0; jj < 4; jj++)
                            mma16816(acc[am][4*bp+jj], ah[am], bl[jj]);
                }
                #pragma unroll
                for (int am = 0; am < 2; am++)
                    #pragma unroll
                    for (int jj = 0; jj < 4; jj++)
                        mma16816(acc[am][4*bp+jj], al[am], bh[jj]);
            }
        }
    }

    // ---- epilogue ----
    #pragma unroll
    for (int am = 0; am < 2; am++) {
        const int gi0 = yBlk + m0 + am * 16 + (lane >> 2);
        #pragma unroll
        for (int j = 0; j < 8; j++) {
            const int gj = xBlk + n0 + j * 8 + (lane & 3) * 2;
            #pragma unroll
            for (int half = 0; half < 2; half++) {
                const int gi = gi0 + half * 8;
                float v0 = acc[am][j][half * 2 + 0];
                float v1 = acc[am][j][half * 2 + 1];
                if (STAGE == 0) {
                    if (gj >= 1024) {           // xkb half: add biasW
                        const int c0 = gj - 1024;
                        v0 += aux1[((c0 + 0) & 255) * 4 + ((c0 + 0) >> 8)];
                        v1 += aux1[((c0 + 1) & 255) * 4 + ((c0 + 1) >> 8)];
                    }
                } else if (STAGE == 2) {
                    const float qi = aux1[(size_t)(b * 2048 + gi) * 4 + k];
                    v0 = (2.f * v0 - qi - aux2[(size_t)(b * 2048 + gj + 0) * 4 + k]) * 0.0625f;
                    v1 = (2.f * v1 - qi - aux2[(size_t)(b * 2048 + gj + 1) * 4 + k]) * 0.0625f;
                } else if (STAGE == 4) {
                    v0 += aux1[(gj + 0) * 4 + k];
                    v1 += aux1[(gj + 1) * 4 + k];
                }
                const size_t idx = (size_t)gi * ldC + gj;
                if (STAGE == 0 || STAGE == 2 || STAGE == 4)
                    *reinterpret_cast<float2*>(Cf + idx) = make_float2(v0, v1);
                if (STAGE == 0) {               // hi + lo
                    fp162 h, l;
                    split2(v0, v1, h, l);
                    *reinterpret_cast<fp162*>(Ch + idx) = h;
                    *reinterpret_cast<fp162*>(Cl + idx) = l;
                } else if (STAGE == 3) {        // hi only (Vp single fp16)
                    *reinterpret_cast<fp162*>(Ch + idx) = __floats2half2_rn(v0, v1);
                }
            }
        }
    }
}

// ---------------- fused fp32 -> fp16 hi/lo split (all inputs) ----------------
// wq -> wqk[0:1024*512), wk -> wqk[1024*512:)
__global__ void split_all(const float4* __restrict__ xsa, const float4* __restrict__ wq,
                          const float4* __restrict__ wk,  const float4* __restrict__ wv,
                          fp162* __restrict__ xh, fp162* __restrict__ xl,
                          fp162* __restrict__ wqkh, fp162* __restrict__ wqkl,
                          fp162* __restrict__ vh, fp162* __restrict__ vl)
{
    int i = blockIdx.x * 256 + threadIdx.x;
    const float4* src;
    fp162 *hi, *lo;
    int j;
    if (i < 524288)       { src = xsa; hi = xh; lo = xl; j = i; }
    else if (i < 655360)  { src = wq;  hi = wqkh; lo = wqkl; j = i - 524288; }
    else if (i < 786432)  { src = wk;  hi = wqkh + 262144; lo = wqkl + 262144; j = i - 655360; }
    else                  { src = wv;  hi = vh; lo = vl; j = i - 786432; }
    float4 v = src[j];
    fp162 h0, l0, h1, l1;
    split2(v.x, v.y, h0, l0);
    split2(v.z, v.w, h1, l1);
    hi[2 * j] = h0; hi[2 * j + 1] = h1;
    lo[2 * j] = l0; lo[2 * j + 1] = l1;
}

// ---------------- row norms (from merged xqk f32) -----------------------------
__global__ void norms_k(const float* __restrict__ xqk,
                        float* __restrict__ qn, float* __restrict__ kn)
{
    const int row  = blockIdx.x;
    const int w    = threadIdx.x >> 5;
    const int lane = threadIdx.x & 31;
    const size_t base = (size_t)row * 2048 + (size_t)w * 256 + lane * 8;

    float4 a0 = *reinterpret_cast<const float4*>(xqk + base);
    float4 a1 = *reinterpret_cast<const float4*>(xqk + base + 4);
    float sq = a0.x*a0.x + a0.y*a0.y + a0.z*a0.z + a0.w*a0.w
             + a1.x*a1.x + a1.y*a1.y + a1.z*a1.z + a1.w*a1.w;
    float4 b0 = *reinterpret_cast<const float4*>(xqk + base + 1024);
    float4 b1 = *reinterpret_cast<const float4*>(xqk + base + 1028);
    float sk = b0.x*b0.x + b0.y*b0.y + b0.z*b0.z + b0.w*b0.w
             + b1.x*b1.x + b1.y*b1.y + b1.z*b1.z + b1.w*b1.w;

    #pragma unroll
    for (int o = 16; o; o >>= 1) {
        sq += __shfl_xor_sync(0xFFFFFFFFu, sq, o);
        sk += __shfl_xor_sync(0xFFFFFFFFu, sk, o);
    }
    if (lane == 0) {
        qn[(size_t)row * 4 + w] = sq;
        kn[(size_t)row * 4 + w] = sk;
    }
}

// ---------------- softmax: read H f32, write P hi/lo fp16 --------------------
__global__ __launch_bounds__(256)
void softmax_k(const float* __restrict__ H, fp16* __restrict__ Ph, fp16* __restrict__ Pl)
{
    const int row = blockIdx.x;
    const float* p = H + (size_t)row * 2048;
    const int tid  = threadIdx.x;
    const int lane = tid & 31, warp = tid >> 5;

    float x[8];
    float4 v0 = *reinterpret_cast<const float4*>(p + tid * 8);
    float4 v1 = *reinterpret_cast<const float4*>(p + tid * 8 + 4);
    x[0]=v0.x; x[1]=v0.y; x[2]=v0.z; x[3]=v0.w;
    x[4]=v1.x; x[5]=v1.y; x[6]=v1.z; x[7]=v1.w;

    float m = x[0];
    #pragma unroll
    for (int i = 1; i < 8; i++) m = fmaxf(m, x[i]);
    #pragma unroll
    for (int o = 16; o; o >>= 1) m = fmaxf(m, __shfl_xor_sync(0xFFFFFFFFu, m, o));

    __shared__ float sm[8];
    __shared__ float ss[8];
    if (lane == 0) sm[warp] = m;
    __syncthreads();
    float M = sm[0];
    #pragma unroll
    for (int i = 1; i < 8; i++) M = fmaxf(M, sm[i]);

    float s = 0.f;
    #pragma unroll
    for (int i = 0; i < 8; i++) { x[i] = __expf(x[i] - M); s += x[i]; }
    #pragma unroll
    for (int o = 16; o; o >>= 1) s += __shfl_xor_sync(0xFFFFFFFFu, s, o);
    if (lane == 0) ss[warp] = s;
    __syncthreads();
    float S = 0.f;
    #pragma unroll
    for (int i = 0; i < 8; i++) S += ss[i];
    const float inv = 1.f / S;

    fp162* ph = reinterpret_cast<fp162*>(Ph + (size_t)row * 2048 + tid * 8);
    fp162* pl = reinterpret_cast<fp162*>(Pl + (size_t)row * 2048 + tid * 8);
    #pragma unroll
    for (int i = 0; i < 4; i++) {
        fp162 h, l;
        split2(x[2*i] * inv, x[2*i+1] * inv, h, l);
        ph[i] = h; pl[i] = l;
    }
}

// ---------------- launch ------------------------------------------------------
extern "C" void kernel_launch(void* const* d_in, const int* in_sizes, int n_in,
                              void* d_out, int out_size)
{
    const float* xsa    = (const float*)d_in[0];
    const float* Wq     = (const float*)d_in[1];
    const float* Wk     = (const float*)d_in[2];
    const float* Wv     = (const float*)d_in[3];
    const float* biasW  = (const float*)d_in[4];
    const float* bias2W = (const float*)d_in[5];
    float* out = (float*)d_out;

    float *p_xqk, *p_qn, *p_kn, *p_H;
    fp16 *xsa_h, *xsa_l, *wqk_h, *wqk_l, *wv_h, *wv_l;
    fp16 *xqk_h, *xqk_l, *P_h, *P_l, *vp_h;
    cudaGetSymbolAddress((void**)&p_xqk, g_xqk);
    cudaGetSymbolAddress((void**)&p_qn,  g_qn);
    cudaGetSymbolAddress((void**)&p_kn,  g_kn);
    cudaGetSymbolAddress((void**)&p_H,   g_H);
    cudaGetSymbolAddress((void**)&xsa_h, g_xsa_h);
    cudaGetSymbolAddress((void**)&xsa_l, g_xsa_l);
    cudaGetSymbolAddress((void**)&wqk_h, g_wqk_h);
    cudaGetSymbolAddress((void**)&wqk_l, g_wqk_l);
    cudaGetSymbolAddress((void**)&wv_h,  g_wv_h);
    cudaGetSymbolAddress((void**)&wv_l,  g_wv_l);
    cudaGetSymbolAddress((void**)&xqk_h, g_xqk_h);
    cudaGetSymbolAddress((void**)&xqk_l, g_xqk_l);
    cudaGetSymbolAddress((void**)&P_h,   g_P_h);
    cudaGetSymbolAddress((void**)&P_l,   g_P_l);
    cudaGetSymbolAddress((void**)&vp_h,  g_vp_h);

    cudaFuncSetAttribute(hgemm<0>, cudaFuncAttributeMaxDynamicSharedMemorySize, 98304);
    cudaFuncSetAttribute(hgemm<2>, cudaFuncAttributeMaxDynamicSharedMemorySize, 98304);
    cudaFuncSetAttribute(hgemm<3>, cudaFuncAttributeMaxDynamicSharedMemorySize, 98304);
    cudaFuncSetAttribute(hgemm<4>, cudaFuncAttributeMaxDynamicSharedMemorySize, 98304);

    // (1) fused input split
    split_all<<<4096, 256>>>((const float4*)xsa, (const float4*)Wq,
                             (const float4*)Wk,  (const float4*)Wv,
                             (fp162*)xsa_h, (fp162*)xsa_l,
                             (fp162*)wqk_h, (fp162*)wqk_l,
                             (fp162*)wv_h,  (fp162*)wv_l);
    // (2) S3: Vp = xsa @ Wv3[k]  (2-product, Vp stored single fp16)
    hgemm<3><<<dim3(4, 16, 8), 256, 98304>>>(xsa_h, xsa_l, wv_h, wv_l,
                                             nullptr, vp_h, nullptr, nullptr, nullptr);
    // (3) S0 merged: [xq|xkb] = xsa @ [Wq;Wk]^T (+bias on xkb)
    hgemm<0><<<dim3(16, 32, 1), 256, 98304>>>(xsa_h, xsa_l, wqk_h, wqk_l,
                                              p_xqk, xqk_h, xqk_l, biasW, nullptr);
    // (4) norms
    norms_k<<<4096, 128>>>(p_xqk, p_qn, p_kn);
    // (5) S2: H = (2*xq.xkb^T - qn - kn)/16
    hgemm<2><<<dim3(16, 16, 8), 256, 98304>>>(xqk_h, xqk_l, xqk_h, xqk_l,
                                              p_H, nullptr, nullptr, p_qn, p_kn);
    // (6) softmax -> P hi/lo
    softmax_k<<<8 * 2048, 256>>>(p_H, P_h, P_l);
    // (7) S4: out = P @ Vp + bias2  (2-product)
    hgemm<4><<<dim3(4, 16, 8), 256, 98304>>>(P_h, P_l, vp_h, vp_h,
                                             out, nullptr, nullptr, bias2W, nullptr);
}

// round 9
// speedup vs baseline: 1.5612x; 1.2334x over previous
#include <cuda_runtime.h>
#include <cuda_fp16.h>
#include <cstdint>

#define BB 2
#define LL 2048
#define EE 512
#define KH 4
#define KE 256
typedef __half fp16;
typedef __half2 fp162;

// ---------------- scratch (device globals) ----------------------------------
// xqk: [4096 rows][2048 cols] = [xq (cols 0..1023) | xkb (cols 1024..2047)]
__device__ float g_xqk [(size_t)4096*2048];
__device__ float g_qn [4096*4];
__device__ float g_kn [4096*4];
__device__ float g_H  [(size_t)8*2048*2048];

__device__ fp16 g_xsa_h[(size_t)4096*512],  g_xsa_l[(size_t)4096*512];
__device__ fp16 g_wqk_h[(size_t)2048*512],  g_wqk_l[(size_t)2048*512];   // [Wq;Wk]
__device__ fp16 g_wv_h [(size_t)512*2048],  g_wv_l [(size_t)512*2048];
__device__ fp16 g_xqk_h[(size_t)4096*2048], g_xqk_l[(size_t)4096*2048];
__device__ fp16 g_P_h  [(size_t)8*2048*2048];
__device__ fp16 g_vp_h [(size_t)8*2048*512];

// ---------------- helpers ----------------------------------------------------
__device__ __forceinline__ uint32_t smem_u32(const void* p) {
    uint32_t a;
    asm("{ .reg .u64 t; cvta.to.shared.u64 t, %1; cvt.u32.u64 %0, t; }" : "=r"(a) : "l"(p));
    return a;
}
__device__ __forceinline__ void cpa16(uint32_t d, const void* s) {
    asm volatile("cp.async.cg.shared.global [%0], [%1], 16;" :: "r"(d), "l"(s));
}
#define CP_COMMIT() asm volatile("cp.async.commit_group;" ::: "memory")
#define CP_WAIT1()  asm volatile("cp.async.wait_group 1;" ::: "memory")

__device__ __forceinline__ void ldsm_x4(uint32_t& r0, uint32_t& r1, uint32_t& r2,
                                        uint32_t& r3, uint32_t a) {
    asm volatile("ldmatrix.sync.aligned.m8n8.x4.shared.b16 {%0,%1,%2,%3}, [%4];"
                 : "=r"(r0), "=r"(r1), "=r"(r2), "=r"(r3) : "r"(a));
}
__device__ __forceinline__ void ldsm_x4t(uint32_t& r0, uint32_t& r1, uint32_t& r2,
                                         uint32_t& r3, uint32_t a) {
    asm volatile("ldmatrix.sync.aligned.m8n8.x4.trans.shared.b16 {%0,%1,%2,%3}, [%4];"
                 : "=r"(r0), "=r"(r1), "=r"(r2), "=r"(r3) : "r"(a));
}
__device__ __forceinline__ void mma16816(float c[4], const uint32_t a[4],
                                         const uint32_t bq[2]) {
    asm volatile("mma.sync.aligned.m16n8k16.row.col.f32.f16.f16.f32 "
                 "{%0,%1,%2,%3}, {%4,%5,%6,%7}, {%8,%9}, {%0,%1,%2,%3};"
                 : "+f"(c[0]), "+f"(c[1]), "+f"(c[2]), "+f"(c[3])
                 : "r"(a[0]), "r"(a[1]), "r"(a[2]), "r"(a[3]), "r"(bq[0]), "r"(bq[1]));
}
__device__ __forceinline__ void split2(float a, float b, fp162& h, fp162& l) {
    h = __floats2half2_rn(a, b);
    l = __floats2half2_rn(a - __half2float(__low2half(h)),
                          b - __half2float(__high2half(h)));
}

// ---------------- GEMM: C[M][N] = A[M][K] * B^T ------------------------------
// STAGE 0: [xq|xkb] = xsa @ [Wq;Wk]^T (+bias on xkb half)  NT  3-product
// STAGE 2: H = (2*xq.xkb^T - qn - kn)/16                   NT  3-product
// STAGE 3: Vp = xsa @ Wv3[k] (flat chunk k*262144)         NN  2-product (B hi only)
// STAGE 4: out = P @ Vp + bias2                            NN  1-product (both hi)
// fp16 hi/lo splits; CTA 128x128, warp 32x64, BK=32, 3-stage cp.async, 2 CTA/SM.

template<int STAGE>
__global__ __launch_bounds__(256, 2)
void hgemm(const fp16* __restrict__ gAh, const fp16* __restrict__ gAl,
           const fp16* __restrict__ gBh, const fp16* __restrict__ gBl,
           float* __restrict__ Cf, fp16* __restrict__ Ch, fp16* __restrict__ Cl,
           const float* __restrict__ aux1, const float* __restrict__ aux2)
{
    constexpr bool NT     = (STAGE == 0 || STAGE == 2);
    constexpr bool USE_BL = (STAGE == 0 || STAGE == 2);   // logit path: 3-product
    constexpr bool USE_AL = (STAGE != 4);                 // S4: P single fp16
    constexpr int  Kd  = (STAGE == 0) ? 512  : (STAGE == 2 ? 256  : (STAGE == 3 ? 512 : 2048));
    constexpr int  ldA = (STAGE == 0) ? 512  : (STAGE == 2 ? 2048 : (STAGE == 3 ? 512 : 2048));
    constexpr int  ldB = (STAGE == 0) ? 512  : (STAGE == 2 ? 2048 : 512);
    constexpr int  ldC = (STAGE == 0) ? 2048 : (STAGE == 2 ? 2048 : (STAGE == 3 ? 512 : 2048));
    constexpr int  NC  = Kd / 32;

    extern __shared__ char smem[];
    const uint32_t sb = smem_u32(smem);
    const int tid = threadIdx.x;
    const int z = blockIdx.z, b = z >> 2, k = z & 3;

    const fp16 *Ah = gAh, *Al = gAl, *Bh = gBh, *Bl = gBl;
    size_t coff = 0;
    if (STAGE == 2) {
        size_t o = (size_t)(b * 2048) * 2048 + (size_t)k * 256;
        Ah += o; Al += o; Bh += o + 1024; Bl += o + 1024;
        coff = (size_t)z * 2048 * 2048;
    } else if (STAGE == 3) {
        size_t oa = (size_t)(b * 2048) * 512;
        Ah += oa; Al += oa;
        size_t ob = (size_t)k * 512 * 512;
        Bh += ob; Bl += ob;
        coff = (size_t)z * 2048 * 512;
    } else if (STAGE == 4) {
        size_t oa = (size_t)z * 2048 * 2048;
        Ah += oa; Al += oa;
        size_t ob = (size_t)z * 2048 * 512;
        Bh += ob; Bl += ob;
        coff = (size_t)(b * 2048) * 2048 + (size_t)k * 512;
    }
    const int yBlk = blockIdx.y * 128, xBlk = blockIdx.x * 128;
    Ah += (size_t)yBlk * ldA; Al += (size_t)yBlk * ldA;
    if (NT) { Bh += (size_t)xBlk * ldB; Bl += (size_t)xBlk * ldB; }
    else    { Bh += xBlk; Bl += xBlk; }
    if (Cf) Cf += coff;
    if (Ch) { Ch += coff; if (Cl) Cl += coff; }

    const int wid = tid >> 5, lane = tid & 31;
    const int m0 = (wid & 3) * 32, n0 = (wid >> 2) * 64;

    float acc[2][8][4];
    #pragma unroll
    for (int am = 0; am < 2; am++)
        #pragma unroll
        for (int j = 0; j < 8; j++)
            #pragma unroll
            for (int q = 0; q < 4; q++) acc[am][j][q] = 0.f;

    auto load_chunk = [&](int c, int buf) {
        uint32_t s0 = sb + buf * 32768;
        #pragma unroll
        for (int h = 0; h < 2; h++) {
            int s = tid + h * 256;
            int r = s >> 2, q = s & 3;
            uint32_t d = s0 + r * 64 + ((q ^ ((r >> 1) & 3)) << 4);
            cpa16(d, Ah + (size_t)r * ldA + c * 32 + q * 8);
            if (USE_AL) cpa16(d + 8192, Al + (size_t)r * ldA + c * 32 + q * 8);
        }
        if (NT) {
            #pragma unroll
            for (int h = 0; h < 2; h++) {
                int s = tid + h * 256;
                int r = s >> 2, q = s & 3;
                uint32_t d = s0 + 16384 + r * 64 + ((q ^ ((r >> 1) & 3)) << 4);
                cpa16(d, Bh + (size_t)r * ldB + c * 32 + q * 8);
                if (USE_BL) cpa16(d + 8192, Bl + (size_t)r * ldB + c * 32 + q * 8);
            }
        } else {
            #pragma unroll
            for (int h = 0; h < 2; h++) {
                int s = tid + h * 256;
                int kk = s >> 4, q = s & 15;
                uint32_t d = s0 + 16384 + kk * 256 + ((q ^ (kk & 7)) << 4);
                cpa16(d, Bh + (size_t)(c * 32 + kk) * ldB + q * 8);
                if (USE_BL) cpa16(d + 8192, Bl + (size_t)(c * 32 + kk) * ldB + q * 8);
            }
        }
    };

    load_chunk(0, 0); CP_COMMIT();
    load_chunk(1, 1); CP_COMMIT();

    #pragma unroll 1
    for (int c = 0; c < NC; c++) {
        CP_WAIT1();
        __syncthreads();
        if (c + 2 < NC) load_chunk(c + 2, (c + 2) % 3);
        CP_COMMIT();

        const uint32_t s0 = sb + (c % 3) * 32768;
        #pragma unroll
        for (int s = 0; s < 2; s++) {
            uint32_t ah[2][4], al[2][4];
            #pragma unroll
            for (int am = 0; am < 2; am++) {
                int row = m0 + am * 16 + (lane & 15);
                int q = s * 2 + (lane >> 4);
                uint32_t addr = s0 + row * 64 + ((q ^ ((row >> 1) & 3)) << 4);
                ldsm_x4(ah[am][0], ah[am][1], ah[am][2], ah[am][3], addr);
                if (USE_AL)
                    ldsm_x4(al[am][0], al[am][1], al[am][2], al[am][3], addr + 8192);
            }
            #pragma unroll
            for (int bp = 0; bp < 2; bp++) {
                uint32_t bh[4][2], bl[4][2];
                if (NT) {
                    #pragma unroll
                    for (int i = 0; i < 2; i++) {
                        int bn = 2 * bp + i;
                        int row = n0 + bn * 16 + (lane & 15);
                        int q = s * 2 + (lane >> 4);
                        uint32_t addr = s0 + 16384 + row * 64 + ((q ^ ((row >> 1) & 3)) << 4);
                        uint32_t r0, r1, r2, r3;
                        ldsm_x4(r0, r1, r2, r3, addr);
                        bh[2*i][0] = r0; bh[2*i][1] = r2;
                        bh[2*i+1][0] = r1; bh[2*i+1][1] = r3;
                        if (USE_BL) {
                            ldsm_x4(r0, r1, r2, r3, addr + 8192);
                            bl[2*i][0] = r0; bl[2*i][1] = r2;
                            bl[2*i+1][0] = r1; bl[2*i+1][1] = r3;
                        }
                    }
                } else {
                    #pragma unroll
                    for (int i = 0; i < 2; i++) {
                        int bn = 2 * bp + i;
                        int g = lane >> 3;
                        int kk = s * 16 + (g & 1) * 8 + (lane & 7);
                        int q = (n0 + bn * 16) / 8 + (g >> 1);
                        uint32_t addr = s0 + 16384 + kk * 256 + ((q ^ (kk & 7)) << 4);
                        uint32_t r0, r1, r2, r3;
                        ldsm_x4t(r0, r1, r2, r3, addr);
                        bh[2*i][0] = r0; bh[2*i][1] = r1;
                        bh[2*i+1][0] = r2; bh[2*i+1][1] = r3;
                        if (USE_BL) {
                            ldsm_x4t(r0, r1, r2, r3, addr + 8192);
                            bl[2*i][0] = r0; bl[2*i][1] = r1;
                            bl[2*i+1][0] = r2; bl[2*i+1][1] = r3;
                        }
                    }
                }
                #pragma unroll
                for (int am = 0; am < 2; am++)
                    #pragma unroll
                    for (int jj = 0; jj < 4; jj++)
                        mma16816(acc[am][4*bp+jj], ah[am], bh[jj]);
                if (USE_BL) {
                    #pragma unroll
                    for (int am = 0; am < 2; am++)
                        #pragma unroll
                        for (int jj = 0; jj < 4; jj++)
                            mma16816(acc[am][4*bp+jj], ah[am], bl[jj]);
                }
                if (USE_AL) {
                    #pragma unroll
                    for (int am = 0; am < 2; am++)
                        #pragma unroll
                        for (int jj = 0; jj < 4; jj++)
                            mma16816(acc[am][4*bp+jj], al[am], bh[jj]);
                }
            }
        }
    }

    // ---- epilogue ----
    #pragma unroll
    for (int am = 0; am < 2; am++) {
        const int gi0 = yBlk + m0 + am * 16 + (lane >> 2);
        #pragma unroll
        for (int j = 0; j < 8; j++) {
            const int gj = xBlk + n0 + j * 8 + (lane & 3) * 2;
            #pragma unroll
            for (int half = 0; half < 2; half++) {
                const int gi = gi0 + half * 8;
                float v0 = acc[am][j][half * 2 + 0];
                float v1 = acc[am][j][half * 2 + 1];
                if (STAGE == 0) {
                    if (gj >= 1024) {           // xkb half: add biasW
                        const int c0 = gj - 1024;
                        v0 += aux1[((c0 + 0) & 255) * 4 + ((c0 + 0) >> 8)];
                        v1 += aux1[((c0 + 1) & 255) * 4 + ((c0 + 1) >> 8)];
                    }
                } else if (STAGE == 2) {
                    const float qi = aux1[(size_t)(b * 2048 + gi) * 4 + k];
                    v0 = (2.f * v0 - qi - aux2[(size_t)(b * 2048 + gj + 0) * 4 + k]) * 0.0625f;
                    v1 = (2.f * v1 - qi - aux2[(size_t)(b * 2048 + gj + 1) * 4 + k]) * 0.0625f;
                } else if (STAGE == 4) {
                    v0 += aux1[(gj + 0) * 4 + k];
                    v1 += aux1[(gj + 1) * 4 + k];
                }
                const size_t idx = (size_t)gi * ldC + gj;
                if (STAGE == 0 || STAGE == 2 || STAGE == 4)
                    *reinterpret_cast<float2*>(Cf + idx) = make_float2(v0, v1);
                if (STAGE == 0) {               // hi + lo
                    fp162 h, l;
                    split2(v0, v1, h, l);
                    *reinterpret_cast<fp162*>(Ch + idx) = h;
                    *reinterpret_cast<fp162*>(Cl + idx) = l;
                } else if (STAGE == 3) {        // hi only (Vp single fp16)
                    *reinterpret_cast<fp162*>(Ch + idx) = __floats2half2_rn(v0, v1);
                }
            }
        }
    }
}

// ---------------- fused fp32 -> fp16 hi/lo split (all inputs) ----------------
// wq -> wqk[0:1024*512), wk -> wqk[1024*512:)
__global__ void split_all(const float4* __restrict__ xsa, const float4* __restrict__ wq,
                          const float4* __restrict__ wk,  const float4* __restrict__ wv,
                          fp162* __restrict__ xh, fp162* __restrict__ xl,
                          fp162* __restrict__ wqkh, fp162* __restrict__ wqkl,
                          fp162* __restrict__ vh, fp162* __restrict__ vl)
{
    int i = blockIdx.x * 256 + threadIdx.x;
    const float4* src;
    fp162 *hi, *lo;
    int j;
    if (i < 524288)       { src = xsa; hi = xh; lo = xl; j = i; }
    else if (i < 655360)  { src = wq;  hi = wqkh; lo = wqkl; j = i - 524288; }
    else if (i < 786432)  { src = wk;  hi = wqkh + 262144; lo = wqkl + 262144; j = i - 655360; }
    else                  { src = wv;  hi = vh; lo = vl; j = i - 786432; }
    float4 v = src[j];
    fp162 h0, l0, h1, l1;
    split2(v.x, v.y, h0, l0);
    split2(v.z, v.w, h1, l1);
    hi[2 * j] = h0; hi[2 * j + 1] = h1;
    lo[2 * j] = l0; lo[2 * j + 1] = l1;
}

// ---------------- row norms (from merged xqk f32) -----------------------------
__global__ void norms_k(const float* __restrict__ xqk,
                        float* __restrict__ qn, float* __restrict__ kn)
{
    const int row  = blockIdx.x;
    const int w    = threadIdx.x >> 5;
    const int lane = threadIdx.x & 31;
    const size_t base = (size_t)row * 2048 + (size_t)w * 256 + lane * 8;

    float4 a0 = *reinterpret_cast<const float4*>(xqk + base);
    float4 a1 = *reinterpret_cast<const float4*>(xqk + base + 4);
    float sq = a0.x*a0.x + a0.y*a0.y + a0.z*a0.z + a0.w*a0.w
             + a1.x*a1.x + a1.y*a1.y + a1.z*a1.z + a1.w*a1.w;
    float4 b0 = *reinterpret_cast<const float4*>(xqk + base + 1024);
    float4 b1 = *reinterpret_cast<const float4*>(xqk + base + 1028);
    float sk = b0.x*b0.x + b0.y*b0.y + b0.z*b0.z + b0.w*b0.w
             + b1.x*b1.x + b1.y*b1.y + b1.z*b1.z + b1.w*b1.w;

    #pragma unroll
    for (int o = 16; o; o >>= 1) {
        sq += __shfl_xor_sync(0xFFFFFFFFu, sq, o);
        sk += __shfl_xor_sync(0xFFFFFFFFu, sk, o);
    }
    if (lane == 0) {
        qn[(size_t)row * 4 + w] = sq;
        kn[(size_t)row * 4 + w] = sk;
    }
}

// ---------------- softmax: read H f32, write P single fp16 -------------------
__global__ __launch_bounds__(256)
void softmax_k(const float* __restrict__ H, fp16* __restrict__ Ph)
{
    const int row = blockIdx.x;
    const float* p = H + (size_t)row * 2048;
    const int tid  = threadIdx.x;
    const int lane = tid & 31, warp = tid >> 5;

    float x[8];
    float4 v0 = *reinterpret_cast<const float4*>(p + tid * 8);
    float4 v1 = *reinterpret_cast<const float4*>(p + tid * 8 + 4);
    x[0]=v0.x; x[1]=v0.y; x[2]=v0.z; x[3]=v0.w;
    x[4]=v1.x; x[5]=v1.y; x[6]=v1.z; x[7]=v1.w;

    float m = x[0];
    #pragma unroll
    for (int i = 1; i < 8; i++) m = fmaxf(m, x[i]);
    #pragma unroll
    for (int o = 16; o; o >>= 1) m = fmaxf(m, __shfl_xor_sync(0xFFFFFFFFu, m, o));

    __shared__ float sm[8];
    __shared__ float ss[8];
    if (lane == 0) sm[warp] = m;
    __syncthreads();
    float M = sm[0];
    #pragma unroll
    for (int i = 1; i < 8; i++) M = fmaxf(M, sm[i]);

    float s = 0.f;
    #pragma unroll
    for (int i = 0; i < 8; i++) { x[i] = __expf(x[i] - M); s += x[i]; }
    #pragma unroll
    for (int o = 16; o; o >>= 1) s += __shfl_xor_sync(0xFFFFFFFFu, s, o);
    if (lane == 0) ss[warp] = s;
    __syncthreads();
    float S = 0.f;
    #pragma unroll
    for (int i = 0; i < 8; i++) S += ss[i];
    const float inv = 1.f / S;

    fp162* ph = reinterpret_cast<fp162*>(Ph + (size_t)row * 2048 + tid * 8);
    #pragma unroll
    for (int i = 0; i < 4; i++)
        ph[i] = __floats2half2_rn(x[2*i] * inv, x[2*i+1] * inv);
}

// ---------------- launch ------------------------------------------------------
extern "C" void kernel_launch(void* const* d_in, const int* in_sizes, int n_in,
                              void* d_out, int out_size)
{
    const float* xsa    = (const float*)d_in[0];
    const float* Wq     = (const float*)d_in[1];
    const float* Wk     = (const float*)d_in[2];
    const float* Wv     = (const float*)d_in[3];
    const float* biasW  = (const float*)d_in[4];
    const float* bias2W = (const float*)d_in[5];
    float* out = (float*)d_out;

    float *p_xqk, *p_qn, *p_kn, *p_H;
    fp16 *xsa_h, *xsa_l, *wqk_h, *wqk_l, *wv_h, *wv_l;
    fp16 *xqk_h, *xqk_l, *P_h, *vp_h;
    cudaGetSymbolAddress((void**)&p_xqk, g_xqk);
    cudaGetSymbolAddress((void**)&p_qn,  g_qn);
    cudaGetSymbolAddress((void**)&p_kn,  g_kn);
    cudaGetSymbolAddress((void**)&p_H,   g_H);
    cudaGetSymbolAddress((void**)&xsa_h, g_xsa_h);
    cudaGetSymbolAddress((void**)&xsa_l, g_xsa_l);
    cudaGetSymbolAddress((void**)&wqk_h, g_wqk_h);
    cudaGetSymbolAddress((void**)&wqk_l, g_wqk_l);
    cudaGetSymbolAddress((void**)&wv_h,  g_wv_h);
    cudaGetSymbolAddress((void**)&wv_l,  g_wv_l);
    cudaGetSymbolAddress((void**)&xqk_h, g_xqk_h);
    cudaGetSymbolAddress((void**)&xqk_l, g_xqk_l);
    cudaGetSymbolAddress((void**)&P_h,   g_P_h);
    cudaGetSymbolAddress((void**)&vp_h,  g_vp_h);

    cudaFuncSetAttribute(hgemm<0>, cudaFuncAttributeMaxDynamicSharedMemorySize, 98304);
    cudaFuncSetAttribute(hgemm<2>, cudaFuncAttributeMaxDynamicSharedMemorySize, 98304);
    cudaFuncSetAttribute(hgemm<3>, cudaFuncAttributeMaxDynamicSharedMemorySize, 98304);
    cudaFuncSetAttribute(hgemm<4>, cudaFuncAttributeMaxDynamicSharedMemorySize, 98304);

    // (1) fused input split
    split_all<<<4096, 256>>>((const float4*)xsa, (const float4*)Wq,
                             (const float4*)Wk,  (const float4*)Wv,
                             (fp162*)xsa_h, (fp162*)xsa_l,
                             (fp162*)wqk_h, (fp162*)wqk_l,
                             (fp162*)wv_h,  (fp162*)wv_l);
    // (2) S3: Vp = xsa @ Wv3[k]  (2-product, Vp single fp16)
    hgemm<3><<<dim3(4, 16, 8), 256, 98304>>>(xsa_h, xsa_l, wv_h, wv_l,
                                             nullptr, vp_h, nullptr, nullptr, nullptr);
    // (3) S0 merged: [xq|xkb] = xsa @ [Wq;Wk]^T (+bias on xkb)
    hgemm<0><<<dim3(16, 32, 1), 256, 98304>>>(xsa_h, xsa_l, wqk_h, wqk_l,
                                              p_xqk, xqk_h, xqk_l, biasW, nullptr);
    // (4) norms
    norms_k<<<4096, 128>>>(p_xqk, p_qn, p_kn);
    // (5) S2: H = (2*xq.xkb^T - qn - kn)/16
    hgemm<2><<<dim3(16, 16, 8), 256, 98304>>>(xqk_h, xqk_l, xqk_h, xqk_l,
                                              p_H, nullptr, nullptr, p_qn, p_kn);
    // (6) softmax -> P single fp16
    softmax_k<<<8 * 2048, 256>>>(p_H, P_h);
    // (7) S4: out = P @ Vp + bias2  (1-product)
    hgemm<4><<<dim3(4, 16, 8), 256, 98304>>>(P_h, P_h, vp_h, vp_h,
                                             out, nullptr, nullptr, bias2W, nullptr);
}

// round 10
// speedup vs baseline: 1.7168x; 1.0996x over previous
#include <cuda_runtime.h>
#include <cuda_fp16.h>
#include <cstdint>

#define BB 2
#define LL 2048
#define EE 512
#define KH 4
#define KE 256
typedef __half fp16;
typedef __half2 fp162;

// ---------------- scratch (device globals) ----------------------------------
// xqk: [4096 rows][2048 cols] = [xq (cols 0..1023) | xkb (cols 1024..2047)]
__device__ float g_xqk [(size_t)4096*2048];
__device__ float g_qn [4096*4];
__device__ float g_kn [4096*4];
__device__ float g_H  [(size_t)8*2048*2048];

__device__ fp16 g_xsa_h[(size_t)4096*512],  g_xsa_l[(size_t)4096*512];
__device__ fp16 g_wqk_h[(size_t)2048*512],  g_wqk_l[(size_t)2048*512];   // [Wq;Wk]
__device__ fp16 g_wv_h [(size_t)512*2048];
__device__ fp16 g_xqk_h[(size_t)4096*2048], g_xqk_l[(size_t)4096*2048];
__device__ fp16 g_P_h  [(size_t)8*2048*2048];
__device__ fp16 g_vp_h [(size_t)8*2048*512];

// ---------------- helpers ----------------------------------------------------
__device__ __forceinline__ uint32_t smem_u32(const void* p) {
    uint32_t a;
    asm("{ .reg .u64 t; cvta.to.shared.u64 t, %1; cvt.u32.u64 %0, t; }" : "=r"(a) : "l"(p));
    return a;
}
__device__ __forceinline__ void cpa16(uint32_t d, const void* s) {
    asm volatile("cp.async.cg.shared.global [%0], [%1], 16;" :: "r"(d), "l"(s));
}
#define CP_COMMIT() asm volatile("cp.async.commit_group;" ::: "memory")
#define CP_WAIT1()  asm volatile("cp.async.wait_group 1;" ::: "memory")

__device__ __forceinline__ void ldsm_x4(uint32_t& r0, uint32_t& r1, uint32_t& r2,
                                        uint32_t& r3, uint32_t a) {
    asm volatile("ldmatrix.sync.aligned.m8n8.x4.shared.b16 {%0,%1,%2,%3}, [%4];"
                 : "=r"(r0), "=r"(r1), "=r"(r2), "=r"(r3) : "r"(a));
}
__device__ __forceinline__ void ldsm_x4t(uint32_t& r0, uint32_t& r1, uint32_t& r2,
                                         uint32_t& r3, uint32_t a) {
    asm volatile("ldmatrix.sync.aligned.m8n8.x4.trans.shared.b16 {%0,%1,%2,%3}, [%4];"
                 : "=r"(r0), "=r"(r1), "=r"(r2), "=r"(r3) : "r"(a));
}
__device__ __forceinline__ void mma16816(float c[4], const uint32_t a[4],
                                         const uint32_t bq[2]) {
    asm volatile("mma.sync.aligned.m16n8k16.row.col.f32.f16.f16.f32 "
                 "{%0,%1,%2,%3}, {%4,%5,%6,%7}, {%8,%9}, {%0,%1,%2,%3};"
                 : "+f"(c[0]), "+f"(c[1]), "+f"(c[2]), "+f"(c[3])
                 : "r"(a[0]), "r"(a[1]), "r"(a[2]), "r"(a[3]), "r"(bq[0]), "r"(bq[1]));
}
__device__ __forceinline__ void split2(float a, float b, fp162& h, fp162& l) {
    h = __floats2half2_rn(a, b);
    l = __floats2half2_rn(a - __half2float(__low2half(h)),
                          b - __half2float(__high2half(h)));
}

// ---------------- GEMM: C[M][N] = A[M][K] * B^T ------------------------------
// STAGE 0: [xq|xkb] = xsa @ [Wq;Wk]^T (+bias on xkb half)  NT  3-product
// STAGE 2: H = (2*xq.xkb_h^T - qn - kn)/16                 NT  2-product (B hi)
// STAGE 3: Vp = xsa @ Wv3[k] (flat chunk k*262144)         NN  2-product (B hi)
// STAGE 4: out = P @ Vp + bias2                            NN  1-product
// fp16 hi/lo splits; CTA 128x128, warp 32x64, BK=32, 3-stage cp.async, 2 CTA/SM.

template<int STAGE>
__global__ __launch_bounds__(256, 2)
void hgemm(const fp16* __restrict__ gAh, const fp16* __restrict__ gAl,
           const fp16* __restrict__ gBh, const fp16* __restrict__ gBl,
           float* __restrict__ Cf, fp16* __restrict__ Ch, fp16* __restrict__ Cl,
           const float* __restrict__ aux1, const float* __restrict__ aux2)
{
    constexpr bool NT     = (STAGE == 0 || STAGE == 2);
    constexpr bool USE_BL = (STAGE == 0);                 // only S0 keeps 3-product
    constexpr bool USE_AL = (STAGE != 4);                 // S4: P single fp16
    constexpr int  Kd  = (STAGE == 0) ? 512  : (STAGE == 2 ? 256  : (STAGE == 3 ? 512 : 2048));
    constexpr int  ldA = (STAGE == 0) ? 512  : (STAGE == 2 ? 2048 : (STAGE == 3 ? 512 : 2048));
    constexpr int  ldB = (STAGE == 0) ? 512  : (STAGE == 2 ? 2048 : 512);
    constexpr int  ldC = (STAGE == 0) ? 2048 : (STAGE == 2 ? 2048 : (STAGE == 3 ? 512 : 2048));
    constexpr int  NC  = Kd / 32;

    extern __shared__ char smem[];
    const uint32_t sb = smem_u32(smem);
    const int tid = threadIdx.x;
    const int z = blockIdx.z, b = z >> 2, k = z & 3;

    const fp16 *Ah = gAh, *Al = gAl, *Bh = gBh, *Bl = gBl;
    size_t coff = 0;
    if (STAGE == 2) {
        size_t o = (size_t)(b * 2048) * 2048 + (size_t)k * 256;
        Ah += o; Al += o; Bh += o + 1024; Bl += o + 1024;
        coff = (size_t)z * 2048 * 2048;
    } else if (STAGE == 3) {
        size_t oa = (size_t)(b * 2048) * 512;
        Ah += oa; Al += oa;
        size_t ob = (size_t)k * 512 * 512;
        Bh += ob; Bl += ob;
        coff = (size_t)z * 2048 * 512;
    } else if (STAGE == 4) {
        size_t oa = (size_t)z * 2048 * 2048;
        Ah += oa; Al += oa;
        size_t ob = (size_t)z * 2048 * 512;
        Bh += ob; Bl += ob;
        coff = (size_t)(b * 2048) * 2048 + (size_t)k * 512;
    }
    const int yBlk = blockIdx.y * 128, xBlk = blockIdx.x * 128;
    Ah += (size_t)yBlk * ldA; Al += (size_t)yBlk * ldA;
    if (NT) { Bh += (size_t)xBlk * ldB; Bl += (size_t)xBlk * ldB; }
    else    { Bh += xBlk; Bl += xBlk; }
    if (Cf) Cf += coff;
    if (Ch) { Ch += coff; if (Cl) Cl += coff; }

    const int wid = tid >> 5, lane = tid & 31;
    const int m0 = (wid & 3) * 32, n0 = (wid >> 2) * 64;

    float acc[2][8][4];
    #pragma unroll
    for (int am = 0; am < 2; am++)
        #pragma unroll
        for (int j = 0; j < 8; j++)
            #pragma unroll
            for (int q = 0; q < 4; q++) acc[am][j][q] = 0.f;

    auto load_chunk = [&](int c, int buf) {
        uint32_t s0 = sb + buf * 32768;
        #pragma unroll
        for (int h = 0; h < 2; h++) {
            int s = tid + h * 256;
            int r = s >> 2, q = s & 3;
            uint32_t d = s0 + r * 64 + ((q ^ ((r >> 1) & 3)) << 4);
            cpa16(d, Ah + (size_t)r * ldA + c * 32 + q * 8);
            if (USE_AL) cpa16(d + 8192, Al + (size_t)r * ldA + c * 32 + q * 8);
        }
        if (NT) {
            #pragma unroll
            for (int h = 0; h < 2; h++) {
                int s = tid + h * 256;
                int r = s >> 2, q = s & 3;
                uint32_t d = s0 + 16384 + r * 64 + ((q ^ ((r >> 1) & 3)) << 4);
                cpa16(d, Bh + (size_t)r * ldB + c * 32 + q * 8);
                if (USE_BL) cpa16(d + 8192, Bl + (size_t)r * ldB + c * 32 + q * 8);
            }
        } else {
            #pragma unroll
            for (int h = 0; h < 2; h++) {
                int s = tid + h * 256;
                int kk = s >> 4, q = s & 15;
                uint32_t d = s0 + 16384 + kk * 256 + ((q ^ (kk & 7)) << 4);
                cpa16(d, Bh + (size_t)(c * 32 + kk) * ldB + q * 8);
                if (USE_BL) cpa16(d + 8192, Bl + (size_t)(c * 32 + kk) * ldB + q * 8);
            }
        }
    };

    load_chunk(0, 0); CP_COMMIT();
    load_chunk(1, 1); CP_COMMIT();

    #pragma unroll 1
    for (int c = 0; c < NC; c++) {
        CP_WAIT1();
        __syncthreads();
        if (c + 2 < NC) load_chunk(c + 2, (c + 2) % 3);
        CP_COMMIT();

        const uint32_t s0 = sb + (c % 3) * 32768;
        #pragma unroll
        for (int s = 0; s < 2; s++) {
            uint32_t ah[2][4], al[2][4];
            #pragma unroll
            for (int am = 0; am < 2; am++) {
                int row = m0 + am * 16 + (lane & 15);
                int q = s * 2 + (lane >> 4);
                uint32_t addr = s0 + row * 64 + ((q ^ ((row >> 1) & 3)) << 4);
                ldsm_x4(ah[am][0], ah[am][1], ah[am][2], ah[am][3], addr);
                if (USE_AL)
                    ldsm_x4(al[am][0], al[am][1], al[am][2], al[am][3], addr + 8192);
            }
            #pragma unroll
            for (int bp = 0; bp < 2; bp++) {
                uint32_t bh[4][2], bl[4][2];
                if (NT) {
                    #pragma unroll
                    for (int i = 0; i < 2; i++) {
                        int bn = 2 * bp + i;
                        int row = n0 + bn * 16 + (lane & 15);
                        int q = s * 2 + (lane >> 4);
                        uint32_t addr = s0 + 16384 + row * 64 + ((q ^ ((row >> 1) & 3)) << 4);
                        uint32_t r0, r1, r2, r3;
                        ldsm_x4(r0, r1, r2, r3, addr);
                        bh[2*i][0] = r0; bh[2*i][1] = r2;
                        bh[2*i+1][0] = r1; bh[2*i+1][1] = r3;
                        if (USE_BL) {
                            ldsm_x4(r0, r1, r2, r3, addr + 8192);
                            bl[2*i][0] = r0; bl[2*i][1] = r2;
                            bl[2*i+1][0] = r1; bl[2*i+1][1] = r3;
                        }
                    }
                } else {
                    #pragma unroll
                    for (int i = 0; i < 2; i++) {
                        int bn = 2 * bp + i;
                        int g = lane >> 3;
                        int kk = s * 16 + (g & 1) * 8 + (lane & 7);
                        int q = (n0 + bn * 16) / 8 + (g >> 1);
                        uint32_t addr = s0 + 16384 + kk * 256 + ((q ^ (kk & 7)) << 4);
                        uint32_t r0, r1, r2, r3;
                        ldsm_x4t(r0, r1, r2, r3, addr);
                        bh[2*i][0] = r0; bh[2*i][1] = r1;
                        bh[2*i+1][0] = r2; bh[2*i+1][1] = r3;
                        if (USE_BL) {
                            ldsm_x4t(r0, r1, r2, r3, addr + 8192);
                            bl[2*i][0] = r0; bl[2*i][1] = r1;
                            bl[2*i+1][0] = r2; bl[2*i+1][1] = r3;
                        }
                    }
                }
                #pragma unroll
                for (int am = 0; am < 2; am++)
                    #pragma unroll
                    for (int jj = 0; jj < 4; jj++)
                        mma16816(acc[am][4*bp+jj], ah[am], bh[jj]);
                if (USE_BL) {
                    #pragma unroll
                    for (int am = 0; am < 2; am++)
                        #pragma unroll
                        for (int jj = 0; jj < 4; jj++)
                            mma16816(acc[am][4*bp+jj], ah[am], bl[jj]);
                }
                if (USE_AL) {
                    #pragma unroll
                    for (int am = 0; am < 2; am++)
                        #pragma unroll
                        for (int jj = 0; jj < 4; jj++)
                            mma16816(acc[am][4*bp+jj], al[am], bh[jj]);
                }
            }
        }
    }

    // ---- epilogue ----
    #pragma unroll
    for (int am = 0; am < 2; am++) {
        const int gi0 = yBlk + m0 + am * 16 + (lane >> 2);
        #pragma unroll
        for (int j = 0; j < 8; j++) {
            const int gj = xBlk + n0 + j * 8 + (lane & 3) * 2;
            #pragma unroll
            for (int half = 0; half < 2; half++) {
                const int gi = gi0 + half * 8;
                float v0 = acc[am][j][half * 2 + 0];
                float v1 = acc[am][j][half * 2 + 1];
                if (STAGE == 0) {
                    if (gj >= 1024) {           // xkb half: add biasW
                        const int c0 = gj - 1024;
                        v0 += aux1[((c0 + 0) & 255) * 4 + ((c0 + 0) >> 8)];
                        v1 += aux1[((c0 + 1) & 255) * 4 + ((c0 + 1) >> 8)];
                    }
                } else if (STAGE == 2) {
                    const float qi = aux1[(size_t)(b * 2048 + gi) * 4 + k];
                    v0 = (2.f * v0 - qi - aux2[(size_t)(b * 2048 + gj + 0) * 4 + k]) * 0.0625f;
                    v1 = (2.f * v1 - qi - aux2[(size_t)(b * 2048 + gj + 1) * 4 + k]) * 0.0625f;
                } else if (STAGE == 4) {
                    v0 += aux1[(gj + 0) * 4 + k];
                    v1 += aux1[(gj + 1) * 4 + k];
                }
                const size_t idx = (size_t)gi * ldC + gj;
                if (STAGE == 0 || STAGE == 2 || STAGE == 4)
                    *reinterpret_cast<float2*>(Cf + idx) = make_float2(v0, v1);
                if (STAGE == 0) {               // hi + lo
                    fp162 h, l;
                    split2(v0, v1, h, l);
                    *reinterpret_cast<fp162*>(Ch + idx) = h;
                    *reinterpret_cast<fp162*>(Cl + idx) = l;
                } else if (STAGE == 3) {        // hi only (Vp single fp16)
                    *reinterpret_cast<fp162*>(Ch + idx) = __floats2half2_rn(v0, v1);
                }
            }
        }
    }
}

// ---------------- fused fp32 -> fp16 hi/lo split (wv: hi only) ---------------
// wq -> wqk[0:1024*512), wk -> wqk[1024*512:)
__global__ void split_all(const float4* __restrict__ xsa, const float4* __restrict__ wq,
                          const float4* __restrict__ wk,  const float4* __restrict__ wv,
                          fp162* __restrict__ xh, fp162* __restrict__ xl,
                          fp162* __restrict__ wqkh, fp162* __restrict__ wqkl,
                          fp162* __restrict__ vh)
{
    int i = blockIdx.x * 256 + threadIdx.x;
    if (i >= 1048576) return;
    if (i >= 786432) {                 // wv: hi only
        int j = i - 786432;
        float4 v = wv[j];
        vh[2 * j]     = __floats2half2_rn(v.x, v.y);
        vh[2 * j + 1] = __floats2half2_rn(v.z, v.w);
        return;
    }
    const float4* src;
    fp162 *hi, *lo;
    int j;
    if (i < 524288)       { src = xsa; hi = xh; lo = xl; j = i; }
    else if (i < 655360)  { src = wq;  hi = wqkh; lo = wqkl; j = i - 524288; }
    else                  { src = wk;  hi = wqkh + 262144; lo = wqkl + 262144; j = i - 655360; }
    float4 v = src[j];
    fp162 h0, l0, h1, l1;
    split2(v.x, v.y, h0, l0);
    split2(v.z, v.w, h1, l1);
    hi[2 * j] = h0; hi[2 * j + 1] = h1;
    lo[2 * j] = l0; lo[2 * j + 1] = l1;
}

// ---------------- row norms (from merged xqk f32) -----------------------------
__global__ void norms_k(const float* __restrict__ xqk,
                        float* __restrict__ qn, float* __restrict__ kn)
{
    const int row  = blockIdx.x;
    const int w    = threadIdx.x >> 5;
    const int lane = threadIdx.x & 31;
    const size_t base = (size_t)row * 2048 + (size_t)w * 256 + lane * 8;

    float4 a0 = *reinterpret_cast<const float4*>(xqk + base);
    float4 a1 = *reinterpret_cast<const float4*>(xqk + base + 4);
    float sq = a0.x*a0.x + a0.y*a0.y + a0.z*a0.z + a0.w*a0.w
             + a1.x*a1.x + a1.y*a1.y + a1.z*a1.z + a1.w*a1.w;
    float4 b0 = *reinterpret_cast<const float4*>(xqk + base + 1024);
    float4 b1 = *reinterpret_cast<const float4*>(xqk + base + 1028);
    float sk = b0.x*b0.x + b0.y*b0.y + b0.z*b0.z + b0.w*b0.w
             + b1.x*b1.x + b1.y*b1.y + b1.z*b1.z + b1.w*b1.w;

    #pragma unroll
    for (int o = 16; o; o >>= 1) {
        sq += __shfl_xor_sync(0xFFFFFFFFu, sq, o);
        sk += __shfl_xor_sync(0xFFFFFFFFu, sk, o);
    }
    if (lane == 0) {
        qn[(size_t)row * 4 + w] = sq;
        kn[(size_t)row * 4 + w] = sk;
    }
}

// ---------------- softmax: read H f32, write P single fp16 -------------------
__global__ __launch_bounds__(256)
void softmax_k(const float* __restrict__ H, fp16* __restrict__ Ph)
{
    const int row = blockIdx.x;
    const float* p = H + (size_t)row * 2048;
    const int tid  = threadIdx.x;
    const int lane = tid & 31, warp = tid >> 5;

    float x[8];
    float4 v0 = *reinterpret_cast<const float4*>(p + tid * 8);
    float4 v1 = *reinterpret_cast<const float4*>(p + tid * 8 + 4);
    x[0]=v0.x; x[1]=v0.y; x[2]=v0.z; x[3]=v0.w;
    x[4]=v1.x; x[5]=v1.y; x[6]=v1.z; x[7]=v1.w;

    float m = x[0];
    #pragma unroll
    for (int i = 1; i < 8; i++) m = fmaxf(m, x[i]);
    #pragma unroll
    for (int o = 16; o; o >>= 1) m = fmaxf(m, __shfl_xor_sync(0xFFFFFFFFu, m, o));

    __shared__ float sm[8];
    __shared__ float ss[8];
    if (lane == 0) sm[warp] = m;
    __syncthreads();
    float M = sm[0];
    #pragma unroll
    for (int i = 1; i < 8; i++) M = fmaxf(M, sm[i]);

    float s = 0.f;
    #pragma unroll
    for (int i = 0; i < 8; i++) { x[i] = __expf(x[i] - M); s += x[i]; }
    #pragma unroll
    for (int o = 16; o; o >>= 1) s += __shfl_xor_sync(0xFFFFFFFFu, s, o);
    if (lane == 0) ss[warp] = s;
    __syncthreads();
    float S = 0.f;
    #pragma unroll
    for (int i = 0; i < 8; i++) S += ss[i];
    const float inv = 1.f / S;

    fp162* ph = reinterpret_cast<fp162*>(Ph + (size_t)row * 2048 + tid * 8);
    #pragma unroll
    for (int i = 0; i < 4; i++)
        ph[i] = __floats2half2_rn(x[2*i] * inv, x[2*i+1] * inv);
}

// ---------------- launch ------------------------------------------------------
extern "C" void kernel_launch(void* const* d_in, const int* in_sizes, int n_in,
                              void* d_out, int out_size)
{
    const float* xsa    = (const float*)d_in[0];
    const float* Wq     = (const float*)d_in[1];
    const float* Wk     = (const float*)d_in[2];
    const float* Wv     = (const float*)d_in[3];
    const float* biasW  = (const float*)d_in[4];
    const float* bias2W = (const float*)d_in[5];
    float* out = (float*)d_out;

    float *p_xqk, *p_qn, *p_kn, *p_H;
    fp16 *xsa_h, *xsa_l, *wqk_h, *wqk_l, *wv_h;
    fp16 *xqk_h, *xqk_l, *P_h, *vp_h;
    cudaGetSymbolAddress((void**)&p_xqk, g_xqk);
    cudaGetSymbolAddress((void**)&p_qn,  g_qn);
    cudaGetSymbolAddress((void**)&p_kn,  g_kn);
    cudaGetSymbolAddress((void**)&p_H,   g_H);
    cudaGetSymbolAddress((void**)&xsa_h, g_xsa_h);
    cudaGetSymbolAddress((void**)&xsa_l, g_xsa_l);
    cudaGetSymbolAddress((void**)&wqk_h, g_wqk_h);
    cudaGetSymbolAddress((void**)&wqk_l, g_wqk_l);
    cudaGetSymbolAddress((void**)&wv_h,  g_wv_h);
    cudaGetSymbolAddress((void**)&xqk_h, g_xqk_h);
    cudaGetSymbolAddress((void**)&xqk_l, g_xqk_l);
    cudaGetSymbolAddress((void**)&P_h,   g_P_h);
    cudaGetSymbolAddress((void**)&vp_h,  g_vp_h);

    cudaFuncSetAttribute(hgemm<0>, cudaFuncAttributeMaxDynamicSharedMemorySize, 98304);
    cudaFuncSetAttribute(hgemm<2>, cudaFuncAttributeMaxDynamicSharedMemorySize, 98304);
    cudaFuncSetAttribute(hgemm<3>, cudaFuncAttributeMaxDynamicSharedMemorySize, 98304);
    cudaFuncSetAttribute(hgemm<4>, cudaFuncAttributeMaxDynamicSharedMemorySize, 98304);

    // (1) fused input split (wv hi only)
    split_all<<<4096, 256>>>((const float4*)xsa, (const float4*)Wq,
                             (const float4*)Wk,  (const float4*)Wv,
                             (fp162*)xsa_h, (fp162*)xsa_l,
                             (fp162*)wqk_h, (fp162*)wqk_l,
                             (fp162*)wv_h);
    // (2) S3: Vp = xsa @ Wv3[k]  (2-product, Vp single fp16)
    hgemm<3><<<dim3(4, 16, 8), 256, 98304>>>(xsa_h, xsa_l, wv_h, wv_h,
                                             nullptr, vp_h, nullptr, nullptr, nullptr);
    // (3) S0 merged: [xq|xkb] = xsa @ [Wq;Wk]^T (+bias on xkb)
    hgemm<0><<<dim3(16, 32, 1), 256, 98304>>>(xsa_h, xsa_l, wqk_h, wqk_l,
                                              p_xqk, xqk_h, xqk_l, biasW, nullptr);
    // (4) norms
    norms_k<<<4096, 128>>>(p_xqk, p_qn, p_kn);
    // (5) S2: H = (2*xq.xkb_h^T - qn - kn)/16  (2-product)
    hgemm<2><<<dim3(16, 16, 8), 256, 98304>>>(xqk_h, xqk_l, xqk_h, xqk_h,
                                              p_H, nullptr, nullptr, p_qn, p_kn);
    // (6) softmax -> P single fp16
    softmax_k<<<8 * 2048, 256>>>(p_H, P_h);
    // (7) S4: out = P @ Vp + bias2  (1-product)
    hgemm<4><<<dim3(4, 16, 8), 256, 98304>>>(P_h, P_h, vp_h, vp_h,
                                             out, nullptr, nullptr, bias2W, nullptr);
}

// round 11
// speedup vs baseline: 1.7892x; 1.0422x over previous
#include <cuda_runtime.h>
#include <cuda_fp16.h>
#include <cstdint>

#define BB 2
#define LL 2048
#define EE 512
#define KH 4
#define KE 256
typedef __half fp16;
typedef __half2 fp162;

// ---------------- scratch (device globals) ----------------------------------
// xqk: [4096 rows][2048 cols] = [xq (cols 0..1023) | xkb (cols 1024..2047)]
__device__ float g_xqk [(size_t)4096*2048];
__device__ float g_kn  [4096*4];
__device__ float g_invS[16384];                       // per (z,row) 1/sum(eH)

__device__ fp16 g_xsa_h[(size_t)4096*512],  g_xsa_l[(size_t)4096*512];
__device__ fp16 g_wqk_h[(size_t)2048*512],  g_wqk_l[(size_t)2048*512];   // [Wq;Wk]
__device__ fp16 g_wv_h [(size_t)512*2048];
__device__ fp16 g_xqk_h[(size_t)4096*2048], g_xqk_l[(size_t)4096*2048];
__device__ fp16 g_eH  [(size_t)8*2048*2048];          // exp((2cross-kn)/16+14) fp16
__device__ fp16 g_vp_h [(size_t)8*2048*512];

// ---------------- helpers ----------------------------------------------------
__device__ __forceinline__ uint32_t smem_u32(const void* p) {
    uint32_t a;
    asm("{ .reg .u64 t; cvta.to.shared.u64 t, %1; cvt.u32.u64 %0, t; }" : "=r"(a) : "l"(p));
    return a;
}
__device__ __forceinline__ void cpa16(uint32_t d, const void* s) {
    asm volatile("cp.async.cg.shared.global [%0], [%1], 16;" :: "r"(d), "l"(s));
}
#define CP_COMMIT() asm volatile("cp.async.commit_group;" ::: "memory")
#define CP_WAIT1()  asm volatile("cp.async.wait_group 1;" ::: "memory")

__device__ __forceinline__ void ldsm_x4(uint32_t& r0, uint32_t& r1, uint32_t& r2,
                                        uint32_t& r3, uint32_t a) {
    asm volatile("ldmatrix.sync.aligned.m8n8.x4.shared.b16 {%0,%1,%2,%3}, [%4];"
                 : "=r"(r0), "=r"(r1), "=r"(r2), "=r"(r3) : "r"(a));
}
__device__ __forceinline__ void ldsm_x4t(uint32_t& r0, uint32_t& r1, uint32_t& r2,
                                         uint32_t& r3, uint32_t a) {
    asm volatile("ldmatrix.sync.aligned.m8n8.x4.trans.shared.b16 {%0,%1,%2,%3}, [%4];"
                 : "=r"(r0), "=r"(r1), "=r"(r2), "=r"(r3) : "r"(a));
}
__device__ __forceinline__ void mma16816(float c[4], const uint32_t a[4],
                                         const uint32_t bq[2]) {
    asm volatile("mma.sync.aligned.m16n8k16.row.col.f32.f16.f16.f32 "
                 "{%0,%1,%2,%3}, {%4,%5,%6,%7}, {%8,%9}, {%0,%1,%2,%3};"
                 : "+f"(c[0]), "+f"(c[1]), "+f"(c[2]), "+f"(c[3])
                 : "r"(a[0]), "r"(a[1]), "r"(a[2]), "r"(a[3]), "r"(bq[0]), "r"(bq[1]));
}
__device__ __forceinline__ void split2(float a, float b, fp162& h, fp162& l) {
    h = __floats2half2_rn(a, b);
    l = __floats2half2_rn(a - __half2float(__low2half(h)),
                          b - __half2float(__high2half(h)));
}

// ---------------- GEMM: C[M][N] = A[M][K] * B^T ------------------------------
// STAGE 0: [xq|xkb] = xsa @ [Wq;Wk]^T (+bias on xkb half)  NT  3-product
// STAGE 2: eH = exp((2*xq.xkb_h^T - kn)/16 + 14) fp16      NT  2-product
//          (qn row-constant cancels in softmax; exact)
// STAGE 3: Vp = xsa @ Wv3[k] (flat chunk k*262144)         NN  2-product
// STAGE 4: out = (eH @ Vp) * invS + bias2                  NN  1-product
// fp16 hi/lo splits; CTA 128x128, warp 32x64, BK=32, 3-stage cp.async, 2 CTA/SM.

template<int STAGE>
__global__ __launch_bounds__(256, 2)
void hgemm(const fp16* __restrict__ gAh, const fp16* __restrict__ gAl,
           const fp16* __restrict__ gBh, const fp16* __restrict__ gBl,
           float* __restrict__ Cf, fp16* __restrict__ Ch, fp16* __restrict__ Cl,
           const float* __restrict__ aux1, const float* __restrict__ aux2)
{
    constexpr bool NT     = (STAGE == 0 || STAGE == 2);
    constexpr bool USE_BL = (STAGE == 0);                 // only S0 keeps 3-product
    constexpr bool USE_AL = (STAGE != 4);                 // S4: eH single fp16
    constexpr int  Kd  = (STAGE == 0) ? 512  : (STAGE == 2 ? 256  : (STAGE == 3 ? 512 : 2048));
    constexpr int  ldA = (STAGE == 0) ? 512  : (STAGE == 2 ? 2048 : (STAGE == 3 ? 512 : 2048));
    constexpr int  ldB = (STAGE == 0) ? 512  : (STAGE == 2 ? 2048 : 512);
    constexpr int  ldC = (STAGE == 0) ? 2048 : (STAGE == 2 ? 2048 : (STAGE == 3 ? 512 : 2048));
    constexpr int  NC  = Kd / 32;

    extern __shared__ char smem[];
    const uint32_t sb = smem_u32(smem);
    const int tid = threadIdx.x;
    const int z = blockIdx.z, b = z >> 2, k = z & 3;

    const fp16 *Ah = gAh, *Al = gAl, *Bh = gBh, *Bl = gBl;
    size_t coff = 0;
    if (STAGE == 2) {
        size_t o = (size_t)(b * 2048) * 2048 + (size_t)k * 256;
        Ah += o; Al += o; Bh += o + 1024; Bl += o + 1024;
        coff = (size_t)z * 2048 * 2048;
    } else if (STAGE == 3) {
        size_t oa = (size_t)(b * 2048) * 512;
        Ah += oa; Al += oa;
        size_t ob = (size_t)k * 512 * 512;
        Bh += ob; Bl += ob;
        coff = (size_t)z * 2048 * 512;
    } else if (STAGE == 4) {
        size_t oa = (size_t)z * 2048 * 2048;
        Ah += oa; Al += oa;
        size_t ob = (size_t)z * 2048 * 512;
        Bh += ob; Bl += ob;
        coff = (size_t)(b * 2048) * 2048 + (size_t)k * 512;
    }
    const int yBlk = blockIdx.y * 128, xBlk = blockIdx.x * 128;
    Ah += (size_t)yBlk * ldA; Al += (size_t)yBlk * ldA;
    if (NT) { Bh += (size_t)xBlk * ldB; Bl += (size_t)xBlk * ldB; }
    else    { Bh += xBlk; Bl += xBlk; }
    if (Cf) Cf += coff;
    if (Ch) { Ch += coff; if (Cl) Cl += coff; }

    const int wid = tid >> 5, lane = tid & 31;
    const int m0 = (wid & 3) * 32, n0 = (wid >> 2) * 64;

    float acc[2][8][4];
    #pragma unroll
    for (int am = 0; am < 2; am++)
        #pragma unroll
        for (int j = 0; j < 8; j++)
            #pragma unroll
            for (int q = 0; q < 4; q++) acc[am][j][q] = 0.f;

    auto load_chunk = [&](int c, int buf) {
        uint32_t s0 = sb + buf * 32768;
        #pragma unroll
        for (int h = 0; h < 2; h++) {
            int s = tid + h * 256;
            int r = s >> 2, q = s & 3;
            uint32_t d = s0 + r * 64 + ((q ^ ((r >> 1) & 3)) << 4);
            cpa16(d, Ah + (size_t)r * ldA + c * 32 + q * 8);
            if (USE_AL) cpa16(d + 8192, Al + (size_t)r * ldA + c * 32 + q * 8);
        }
        if (NT) {
            #pragma unroll
            for (int h = 0; h < 2; h++) {
                int s = tid + h * 256;
                int r = s >> 2, q = s & 3;
                uint32_t d = s0 + 16384 + r * 64 + ((q ^ ((r >> 1) & 3)) << 4);
                cpa16(d, Bh + (size_t)r * ldB + c * 32 + q * 8);
                if (USE_BL) cpa16(d + 8192, Bl + (size_t)r * ldB + c * 32 + q * 8);
            }
        } else {
            #pragma unroll
            for (int h = 0; h < 2; h++) {
                int s = tid + h * 256;
                int kk = s >> 4, q = s & 15;
                uint32_t d = s0 + 16384 + kk * 256 + ((q ^ (kk & 7)) << 4);
                cpa16(d, Bh + (size_t)(c * 32 + kk) * ldB + q * 8);
                if (USE_BL) cpa16(d + 8192, Bl + (size_t)(c * 32 + kk) * ldB + q * 8);
            }
        }
    };

    load_chunk(0, 0); CP_COMMIT();
    load_chunk(1, 1); CP_COMMIT();

    #pragma unroll 1
    for (int c = 0; c < NC; c++) {
        CP_WAIT1();
        __syncthreads();
        if (c + 2 < NC) load_chunk(c + 2, (c + 2) % 3);
        CP_COMMIT();

        const uint32_t s0 = sb + (c % 3) * 32768;
        #pragma unroll
        for (int s = 0; s < 2; s++) {
            uint32_t ah[2][4], al[2][4];
            #pragma unroll
            for (int am = 0; am < 2; am++) {
                int row = m0 + am * 16 + (lane & 15);
                int q = s * 2 + (lane >> 4);
                uint32_t addr = s0 + row * 64 + ((q ^ ((row >> 1) & 3)) << 4);
                ldsm_x4(ah[am][0], ah[am][1], ah[am][2], ah[am][3], addr);
                if (USE_AL)
                    ldsm_x4(al[am][0], al[am][1], al[am][2], al[am][3], addr + 8192);
            }
            #pragma unroll
            for (int bp = 0; bp < 2; bp++) {
                uint32_t bh[4][2], bl[4][2];
                if (NT) {
                    #pragma unroll
                    for (int i = 0; i < 2; i++) {
                        int bn = 2 * bp + i;
                        int row = n0 + bn * 16 + (lane & 15);
                        int q = s * 2 + (lane >> 4);
                        uint32_t addr = s0 + 16384 + row * 64 + ((q ^ ((row >> 1) & 3)) << 4);
                        uint32_t r0, r1, r2, r3;
                        ldsm_x4(r0, r1, r2, r3, addr);
                        bh[2*i][0] = r0; bh[2*i][1] = r2;
                        bh[2*i+1][0] = r1; bh[2*i+1][1] = r3;
                        if (USE_BL) {
                            ldsm_x4(r0, r1, r2, r3, addr + 8192);
                            bl[2*i][0] = r0; bl[2*i][1] = r2;
                            bl[2*i+1][0] = r1; bl[2*i+1][1] = r3;
                        }
                    }
                } else {
                    #pragma unroll
                    for (int i = 0; i < 2; i++) {
                        int bn = 2 * bp + i;
                        int g = lane >> 3;
                        int kk = s * 16 + (g & 1) * 8 + (lane & 7);
                        int q = (n0 + bn * 16) / 8 + (g >> 1);
                        uint32_t addr = s0 + 16384 + kk * 256 + ((q ^ (kk & 7)) << 4);
                        uint32_t r0, r1, r2, r3;
                        ldsm_x4t(r0, r1, r2, r3, addr);
                        bh[2*i][0] = r0; bh[2*i][1] = r1;
                        bh[2*i+1][0] = r2; bh[2*i+1][1] = r3;
                        if (USE_BL) {
                            ldsm_x4t(r0, r1, r2, r3, addr + 8192);
                            bl[2*i][0] = r0; bl[2*i][1] = r1;
                            bl[2*i+1][0] = r2; bl[2*i+1][1] = r3;
                        }
                    }
                }
                #pragma unroll
                for (int am = 0; am < 2; am++)
                    #pragma unroll
                    for (int jj = 0; jj < 4; jj++)
                        mma16816(acc[am][4*bp+jj], ah[am], bh[jj]);
                if (USE_BL) {
                    #pragma unroll
                    for (int am = 0; am < 2; am++)
                        #pragma unroll
                        for (int jj = 0; jj < 4; jj++)
                            mma16816(acc[am][4*bp+jj], ah[am], bl[jj]);
                }
                if (USE_AL) {
                    #pragma unroll
                    for (int am = 0; am < 2; am++)
                        #pragma unroll
                        for (int jj = 0; jj < 4; jj++)
                            mma16816(acc[am][4*bp+jj], al[am], bh[jj]);
                }
            }
        }
    }

    // ---- epilogue ----
    #pragma unroll
    for (int am = 0; am < 2; am++) {
        const int gi0 = yBlk + m0 + am * 16 + (lane >> 2);
        #pragma unroll
        for (int j = 0; j < 8; j++) {
            const int gj = xBlk + n0 + j * 8 + (lane & 3) * 2;
            #pragma unroll
            for (int half = 0; half < 2; half++) {
                const int gi = gi0 + half * 8;
                float v0 = acc[am][j][half * 2 + 0];
                float v1 = acc[am][j][half * 2 + 1];
                const size_t idx = (size_t)gi * ldC + gj;
                if (STAGE == 0) {
                    if (gj >= 1024) {           // xkb half: add biasW
                        const int c0 = gj - 1024;
                        v0 += aux1[((c0 + 0) & 255) * 4 + ((c0 + 0) >> 8)];
                        v1 += aux1[((c0 + 1) & 255) * 4 + ((c0 + 1) >> 8)];
                    }
                    *reinterpret_cast<float2*>(Cf + idx) = make_float2(v0, v1);
                    fp162 h, l;
                    split2(v0, v1, h, l);
                    *reinterpret_cast<fp162*>(Ch + idx) = h;
                    *reinterpret_cast<fp162*>(Cl + idx) = l;
                } else if (STAGE == 2) {
                    // eH = exp((2*cross - kn_j)/16 + 14), qn_i cancels in softmax
                    const float kn0 = aux2[(size_t)(b * 2048 + gj + 0) * 4 + k];
                    const float kn1 = aux2[(size_t)(b * 2048 + gj + 1) * 4 + k];
                    float t0 = fminf((2.f * v0 - kn0) * 0.0625f + 14.f, 11.f);
                    float t1 = fminf((2.f * v1 - kn1) * 0.0625f + 14.f, 11.f);
                    *reinterpret_cast<fp162*>(Ch + idx) =
                        __floats2half2_rn(__expf(t0), __expf(t1));
                } else if (STAGE == 3) {
                    *reinterpret_cast<fp162*>(Ch + idx) = __floats2half2_rn(v0, v1);
                } else { // STAGE 4
                    const float is0 = aux2[(size_t)z * 2048 + gi];
                    v0 = v0 * is0 + aux1[(gj + 0) * 4 + k];
                    v1 = v1 * is0 + aux1[(gj + 1) * 4 + k];
                    *reinterpret_cast<float2*>(Cf + idx) = make_float2(v0, v1);
                }
            }
        }
    }
}

// ---------------- fused fp32 -> fp16 hi/lo split (wv: hi only) ---------------
// wq -> wqk[0:1024*512), wk -> wqk[1024*512:)
__global__ void split_all(const float4* __restrict__ xsa, const float4* __restrict__ wq,
                          const float4* __restrict__ wk,  const float4* __restrict__ wv,
                          fp162* __restrict__ xh, fp162* __restrict__ xl,
                          fp162* __restrict__ wqkh, fp162* __restrict__ wqkl,
                          fp162* __restrict__ vh)
{
    int i = blockIdx.x * 256 + threadIdx.x;
    if (i >= 1048576) return;
    if (i >= 786432) {                 // wv: hi only
        int j = i - 786432;
        float4 v = wv[j];
        vh[2 * j]     = __floats2half2_rn(v.x, v.y);
        vh[2 * j + 1] = __floats2half2_rn(v.z, v.w);
        return;
    }
    const float4* src;
    fp162 *hi, *lo;
    int j;
    if (i < 524288)       { src = xsa; hi = xh; lo = xl; j = i; }
    else if (i < 655360)  { src = wq;  hi = wqkh; lo = wqkl; j = i - 524288; }
    else                  { src = wk;  hi = wqkh + 262144; lo = wqkl + 262144; j = i - 655360; }
    float4 v = src[j];
    fp162 h0, l0, h1, l1;
    split2(v.x, v.y, h0, l0);
    split2(v.z, v.w, h1, l1);
    hi[2 * j] = h0; hi[2 * j + 1] = h1;
    lo[2 * j] = l0; lo[2 * j + 1] = l1;
}

// ---------------- kn norms (xkb half of merged xqk f32) -----------------------
__global__ void norms_k(const float* __restrict__ xqk, float* __restrict__ kn)
{
    const int row  = blockIdx.x;
    const int w    = threadIdx.x >> 5;
    const int lane = threadIdx.x & 31;
    const size_t base = (size_t)row * 2048 + 1024 + (size_t)w * 256 + lane * 8;

    float4 b0 = *reinterpret_cast<const float4*>(xqk + base);
    float4 b1 = *reinterpret_cast<const float4*>(xqk + base + 4);
    float sk = b0.x*b0.x + b0.y*b0.y + b0.z*b0.z + b0.w*b0.w
             + b1.x*b1.x + b1.y*b1.y + b1.z*b1.z + b1.w*b1.w;
    #pragma unroll
    for (int o = 16; o; o >>= 1)
        sk += __shfl_xor_sync(0xFFFFFFFFu, sk, o);
    if (lane == 0)
        kn[(size_t)row * 4 + w] = sk;
}

// ---------------- row sums of eH -> invS --------------------------------------
__global__ __launch_bounds__(256)
void rowsum_k(const fp16* __restrict__ eH, float* __restrict__ invS)
{
    const int row = blockIdx.x;                 // 0..16383
    const fp162* p = reinterpret_cast<const fp162*>(eH + (size_t)row * 2048);
    const int tid  = threadIdx.x;
    const int lane = tid & 31, warp = tid >> 5;

    float s = 0.f;
    #pragma unroll
    for (int i = 0; i < 4; i++) {
        fp162 v = p[tid * 4 + i];
        s += __half2float(__low2half(v)) + __half2float(__high2half(v));
    }
    #pragma unroll
    for (int o = 16; o; o >>= 1) s += __shfl_xor_sync(0xFFFFFFFFu, s, o);

    __shared__ float ss[8];
    if (lane == 0) ss[warp] = s;
    __syncthreads();
    if (tid == 0) {
        float S = 0.f;
        #pragma unroll
        for (int i = 0; i < 8; i++) S += ss[i];
        invS[row] = 1.f / S;
    }
}

// ---------------- launch ------------------------------------------------------
extern "C" void kernel_launch(void* const* d_in, const int* in_sizes, int n_in,
                              void* d_out, int out_size)
{
    const float* xsa    = (const float*)d_in[0];
    const float* Wq     = (const float*)d_in[1];
    const float* Wk     = (const float*)d_in[2];
    const float* Wv     = (const float*)d_in[3];
    const float* biasW  = (const float*)d_in[4];
    const float* bias2W = (const float*)d_in[5];
    float* out = (float*)d_out;

    float *p_xqk, *p_kn, *p_invS;
    fp16 *xsa_h, *xsa_l, *wqk_h, *wqk_l, *wv_h;
    fp16 *xqk_h, *xqk_l, *eH, *vp_h;
    cudaGetSymbolAddress((void**)&p_xqk, g_xqk);
    cudaGetSymbolAddress((void**)&p_kn,  g_kn);
    cudaGetSymbolAddress((void**)&p_invS, g_invS);
    cudaGetSymbolAddress((void**)&xsa_h, g_xsa_h);
    cudaGetSymbolAddress((void**)&xsa_l, g_xsa_l);
    cudaGetSymbolAddress((void**)&wqk_h, g_wqk_h);
    cudaGetSymbolAddress((void**)&wqk_l, g_wqk_l);
    cudaGetSymbolAddress((void**)&wv_h,  g_wv_h);
    cudaGetSymbolAddress((void**)&xqk_h, g_xqk_h);
    cudaGetSymbolAddress((void**)&xqk_l, g_xqk_l);
    cudaGetSymbolAddress((void**)&eH,    g_eH);
    cudaGetSymbolAddress((void**)&vp_h,  g_vp_h);

    cudaFuncSetAttribute(hgemm<0>, cudaFuncAttributeMaxDynamicSharedMemorySize, 98304);
    cudaFuncSetAttribute(hgemm<2>, cudaFuncAttributeMaxDynamicSharedMemorySize, 98304);
    cudaFuncSetAttribute(hgemm<3>, cudaFuncAttributeMaxDynamicSharedMemorySize, 98304);
    cudaFuncSetAttribute(hgemm<4>, cudaFuncAttributeMaxDynamicSharedMemorySize, 98304);

    // (1) fused input split (wv hi only)
    split_all<<<4096, 256>>>((const float4*)xsa, (const float4*)Wq,
                             (const float4*)Wk,  (const float4*)Wv,
                             (fp162*)xsa_h, (fp162*)xsa_l,
                             (fp162*)wqk_h, (fp162*)wqk_l,
                             (fp162*)wv_h);
    // (2) S3: Vp = xsa @ Wv3[k]  (2-product, Vp single fp16)
    hgemm<3><<<dim3(4, 16, 8), 256, 98304>>>(xsa_h, xsa_l, wv_h, wv_h,
                                             nullptr, vp_h, nullptr, nullptr, nullptr);
    // (3) S0 merged: [xq|xkb] = xsa @ [Wq;Wk]^T (+bias on xkb)
    hgemm<0><<<dim3(16, 32, 1), 256, 98304>>>(xsa_h, xsa_l, wqk_h, wqk_l,
                                              p_xqk, xqk_h, xqk_l, biasW, nullptr);
    // (4) kn norms
    norms_k<<<4096, 128>>>(p_xqk, p_kn);
    // (5) S2: eH = exp((2*xq.xkb_h^T - kn)/16 + 14)  fp16
    hgemm<2><<<dim3(16, 16, 8), 256, 98304>>>(xqk_h, xqk_l, xqk_h, xqk_h,
                                              nullptr, eH, nullptr, nullptr, p_kn);
    // (6) row sums -> invS
    rowsum_k<<<16384, 256>>>(eH, p_invS);
    // (7) S4: out = (eH @ Vp) * invS + bias2
    hgemm<4><<<dim3(4, 16, 8), 256, 98304>>>(eH, eH, vp_h, vp_h,
                                             out, nullptr, nullptr, bias2W, p_invS);
}

// round 12
// speedup vs baseline: 1.9157x; 1.0707x over previous
#include <cuda_runtime.h>
#include <cuda_fp16.h>
#include <cstdint>

#define BB 2
#define LL 2048
#define EE 512
#define KH 4
#define KE 256
typedef __half fp16;
typedef __half2 fp162;

// ---------------- scratch (device globals) ----------------------------------
__device__ float g_kn4 [4096*4*4];                    // per (row,head,part) |xkb|^2 partials
__device__ float g_kn  [4096*4];
__device__ float g_Spart[(size_t)16384*32];           // per (z,row) x 32 partial exp-sums
__device__ float g_invS[16384];

__device__ fp16 g_xsa_h[(size_t)4096*512],  g_xsa_l[(size_t)4096*512];
__device__ fp16 g_wqk_h[(size_t)2048*512],  g_wqk_l[(size_t)2048*512];   // [Wq;Wk]
__device__ fp16 g_wv_h [(size_t)512*2048];
__device__ fp16 g_xqk_h[(size_t)4096*2048], g_xqk_l[(size_t)4096*2048];
__device__ fp16 g_eH  [(size_t)8*2048*2048];          // exp((2cross-kn)/16+14) fp16
__device__ fp16 g_vp_h [(size_t)8*2048*512];

// ---------------- helpers ----------------------------------------------------
__device__ __forceinline__ uint32_t smem_u32(const void* p) {
    uint32_t a;
    asm("{ .reg .u64 t; cvta.to.shared.u64 t, %1; cvt.u32.u64 %0, t; }" : "=r"(a) : "l"(p));
    return a;
}
__device__ __forceinline__ void cpa16(uint32_t d, const void* s) {
    asm volatile("cp.async.cg.shared.global [%0], [%1], 16;" :: "r"(d), "l"(s));
}
#define CP_COMMIT() asm volatile("cp.async.commit_group;" ::: "memory")
#define CP_WAIT1()  asm volatile("cp.async.wait_group 1;" ::: "memory")

__device__ __forceinline__ void ldsm_x4(uint32_t& r0, uint32_t& r1, uint32_t& r2,
                                        uint32_t& r3, uint32_t a) {
    asm volatile("ldmatrix.sync.aligned.m8n8.x4.shared.b16 {%0,%1,%2,%3}, [%4];"
                 : "=r"(r0), "=r"(r1), "=r"(r2), "=r"(r3) : "r"(a));
}
__device__ __forceinline__ void ldsm_x4t(uint32_t& r0, uint32_t& r1, uint32_t& r2,
                                         uint32_t& r3, uint32_t a) {
    asm volatile("ldmatrix.sync.aligned.m8n8.x4.trans.shared.b16 {%0,%1,%2,%3}, [%4];"
                 : "=r"(r0), "=r"(r1), "=r"(r2), "=r"(r3) : "r"(a));
}
__device__ __forceinline__ void mma16816(float c[4], const uint32_t a[4],
                                         const uint32_t bq[2]) {
    asm volatile("mma.sync.aligned.m16n8k16.row.col.f32.f16.f16.f32 "
                 "{%0,%1,%2,%3}, {%4,%5,%6,%7}, {%8,%9}, {%0,%1,%2,%3};"
                 : "+f"(c[0]), "+f"(c[1]), "+f"(c[2]), "+f"(c[3])
                 : "r"(a[0]), "r"(a[1]), "r"(a[2]), "r"(a[3]), "r"(bq[0]), "r"(bq[1]));
}
__device__ __forceinline__ void split2(float a, float b, fp162& h, fp162& l) {
    h = __floats2half2_rn(a, b);
    l = __floats2half2_rn(a - __half2float(__low2half(h)),
                          b - __half2float(__high2half(h)));
}

// ---------------- GEMM: C[M][N] = A[M][K] * B^T ------------------------------
// STAGE 0: [xq|xkb] hi/lo = xsa @ [Wq;Wk]^T (+bias), kn4 partials  NT 3-product BK32
// STAGE 2: eH = exp((2*xq.xkb_h^T - kn)/16 + 14) fp16 + Spart      NT 2-product BK32
// STAGE 3: Vp = xsa @ Wv3[k] (flat chunk k*262144)                 NN 2-product BK32
// STAGE 4: out = (eH @ Vp) * invS + bias2                          NN 1-product BK64
// fp16 hi/lo splits; CTA 128x128, warp 32x64, 3-stage cp.async, 2 CTA/SM.

template<int STAGE>
__global__ __launch_bounds__(256, 2)
void hgemm(const fp16* __restrict__ gAh, const fp16* __restrict__ gAl,
           const fp16* __restrict__ gBh, const fp16* __restrict__ gBl,
           float* __restrict__ Cf, fp16* __restrict__ Ch, fp16* __restrict__ Cl,
           const float* __restrict__ aux1, const float* __restrict__ aux2)
{
    constexpr bool NT     = (STAGE == 0 || STAGE == 2);
    constexpr bool USE_BL = (STAGE == 0);
    constexpr bool USE_AL = (STAGE != 4);
    constexpr int  BK  = (STAGE == 4) ? 64 : 32;
    constexpr int  SN  = BK / 16;
    constexpr int  Kd  = (STAGE == 0) ? 512  : (STAGE == 2 ? 256  : (STAGE == 3 ? 512 : 2048));
    constexpr int  ldA = (STAGE == 0) ? 512  : (STAGE == 2 ? 2048 : (STAGE == 3 ? 512 : 2048));
    constexpr int  ldB = (STAGE == 0) ? 512  : (STAGE == 2 ? 2048 : 512);
    constexpr int  ldC = 2048;   // used by stage 4 only (out) / stage 3 (512) below
    constexpr int  ldC3 = 512;
    constexpr int  NC  = Kd / BK;

    extern __shared__ char smem[];
    const uint32_t sb = smem_u32(smem);
    const int tid = threadIdx.x;
    const int z = blockIdx.z, b = z >> 2, k = z & 3;

    const fp16 *Ah = gAh, *Al = gAl, *Bh = gBh, *Bl = gBl;
    size_t coff = 0;
    if (STAGE == 2) {
        size_t o = (size_t)(b * 2048) * 2048 + (size_t)k * 256;
        Ah += o; Al += o; Bh += o + 1024; Bl += o + 1024;
        coff = (size_t)z * 2048 * 2048;
    } else if (STAGE == 3) {
        size_t oa = (size_t)(b * 2048) * 512;
        Ah += oa; Al += oa;
        size_t ob = (size_t)k * 512 * 512;
        Bh += ob; Bl += ob;
        coff = (size_t)z * 2048 * 512;
    } else if (STAGE == 4) {
        size_t oa = (size_t)z * 2048 * 2048;
        Ah += oa; Al += oa;
        size_t ob = (size_t)z * 2048 * 512;
        Bh += ob; Bl += ob;
        coff = (size_t)(b * 2048) * 2048 + (size_t)k * 512;
    }
    const int yBlk = blockIdx.y * 128, xBlk = blockIdx.x * 128;
    Ah += (size_t)yBlk * ldA; Al += (size_t)yBlk * ldA;
    if (NT) { Bh += (size_t)xBlk * ldB; Bl += (size_t)xBlk * ldB; }
    else    { Bh += xBlk; Bl += xBlk; }
    if (STAGE == 4 && Cf) Cf += coff;
    if (Ch) { Ch += coff; if (Cl) Cl += coff; }

    const int wid = tid >> 5, lane = tid & 31;
    const int m0 = (wid & 3) * 32, n0 = (wid >> 2) * 64;

    float acc[2][8][4];
    #pragma unroll
    for (int am = 0; am < 2; am++)
        #pragma unroll
        for (int j = 0; j < 8; j++)
            #pragma unroll
            for (int q = 0; q < 4; q++) acc[am][j][q] = 0.f;

    auto load_chunk = [&](int c, int buf) {
        uint32_t s0 = sb + buf * 32768;
        if (STAGE == 4) {
            // A: 128 rows x 64 cols fp16 (16KB), 128B rows
            #pragma unroll
            for (int h = 0; h < 4; h++) {
                int s = tid + h * 256;
                int r = s >> 3, q = s & 7;
                uint32_t d = s0 + r * 128 + ((q ^ (r & 7)) << 4);
                cpa16(d, Ah + (size_t)r * ldA + c * 64 + q * 8);
            }
            // B: 64 rows(k) x 128 cols (16KB), 256B rows
            #pragma unroll
            for (int h = 0; h < 4; h++) {
                int s = tid + h * 256;
                int kk = s >> 4, q = s & 15;
                uint32_t d = s0 + 16384 + kk * 256 + ((q ^ (kk & 7)) << 4);
                cpa16(d, Bh + (size_t)(c * 64 + kk) * ldB + q * 8);
            }
            return;
        }
        #pragma unroll
        for (int h = 0; h < 2; h++) {
            int s = tid + h * 256;
            int r = s >> 2, q = s & 3;
            uint32_t d = s0 + r * 64 + ((q ^ ((r >> 1) & 3)) << 4);
            cpa16(d, Ah + (size_t)r * ldA + c * 32 + q * 8);
            if (USE_AL) cpa16(d + 8192, Al + (size_t)r * ldA + c * 32 + q * 8);
        }
        if (NT) {
            #pragma unroll
            for (int h = 0; h < 2; h++) {
                int s = tid + h * 256;
                int r = s >> 2, q = s & 3;
                uint32_t d = s0 + 16384 + r * 64 + ((q ^ ((r >> 1) & 3)) << 4);
                cpa16(d, Bh + (size_t)r * ldB + c * 32 + q * 8);
                if (USE_BL) cpa16(d + 8192, Bl + (size_t)r * ldB + c * 32 + q * 8);
            }
        } else {
            #pragma unroll
            for (int h = 0; h < 2; h++) {
                int s = tid + h * 256;
                int kk = s >> 4, q = s & 15;
                uint32_t d = s0 + 16384 + kk * 256 + ((q ^ (kk & 7)) << 4);
                cpa16(d, Bh + (size_t)(c * 32 + kk) * ldB + q * 8);
                if (USE_BL) cpa16(d + 8192, Bl + (size_t)(c * 32 + kk) * ldB + q * 8);
            }
        }
    };

    load_chunk(0, 0); CP_COMMIT();
    load_chunk(1, 1); CP_COMMIT();

    #pragma unroll 1
    for (int c = 0; c < NC; c++) {
        CP_WAIT1();
        __syncthreads();
        if (c + 2 < NC) load_chunk(c + 2, (c + 2) % 3);
        CP_COMMIT();

        const uint32_t s0 = sb + (c % 3) * 32768;
        #pragma unroll
        for (int s = 0; s < SN; s++) {
            uint32_t ah[2][4], al[2][4];
            #pragma unroll
            for (int am = 0; am < 2; am++) {
                int row = m0 + am * 16 + (lane & 15);
                int q = s * 2 + (lane >> 4);
                uint32_t addr;
                if (STAGE == 4)
                    addr = s0 + row * 128 + ((q ^ (row & 7)) << 4);
                else
                    addr = s0 + row * 64 + ((q ^ ((row >> 1) & 3)) << 4);
                ldsm_x4(ah[am][0], ah[am][1], ah[am][2], ah[am][3], addr);
                if (USE_AL)
                    ldsm_x4(al[am][0], al[am][1], al[am][2], al[am][3], addr + 8192);
            }
            #pragma unroll
            for (int bp = 0; bp < 2; bp++) {
                uint32_t bh[4][2], bl[4][2];
                if (NT) {
                    #pragma unroll
                    for (int i = 0; i < 2; i++) {
                        int bn = 2 * bp + i;
                        int row = n0 + bn * 16 + (lane & 15);
                        int q = s * 2 + (lane >> 4);
                        uint32_t addr = s0 + 16384 + row * 64 + ((q ^ ((row >> 1) & 3)) << 4);
                        uint32_t r0, r1, r2, r3;
                        ldsm_x4(r0, r1, r2, r3, addr);
                        bh[2*i][0] = r0; bh[2*i][1] = r2;
                        bh[2*i+1][0] = r1; bh[2*i+1][1] = r3;
                        if (USE_BL) {
                            ldsm_x4(r0, r1, r2, r3, addr + 8192);
                            bl[2*i][0] = r0; bl[2*i][1] = r2;
                            bl[2*i+1][0] = r1; bl[2*i+1][1] = r3;
                        }
                    }
                } else {
                    #pragma unroll
                    for (int i = 0; i < 2; i++) {
                        int bn = 2 * bp + i;
                        int g = lane >> 3;
                        int kk = s * 16 + (g & 1) * 8 + (lane & 7);
                        int q = (n0 + bn * 16) / 8 + (g >> 1);
                        uint32_t addr = s0 + 16384 + kk * 256 + ((q ^ (kk & 7)) << 4);
                        uint32_t r0, r1, r2, r3;
                        ldsm_x4t(r0, r1, r2, r3, addr);
                        bh[2*i][0] = r0; bh[2*i][1] = r1;
                        bh[2*i+1][0] = r2; bh[2*i+1][1] = r3;
                        if (USE_BL) {
                            ldsm_x4t(r0, r1, r2, r3, addr + 8192);
                            bl[2*i][0] = r0; bl[2*i][1] = r1;
                            bl[2*i+1][0] = r2; bl[2*i+1][1] = r3;
                        }
                    }
                }
                #pragma unroll
                for (int am = 0; am < 2; am++)
                    #pragma unroll
                    for (int jj = 0; jj < 4; jj++)
                        mma16816(acc[am][4*bp+jj], ah[am], bh[jj]);
                if (USE_BL) {
                    #pragma unroll
                    for (int am = 0; am < 2; am++)
                        #pragma unroll
                        for (int jj = 0; jj < 4; jj++)
                            mma16816(acc[am][4*bp+jj], ah[am], bl[jj]);
                }
                if (USE_AL) {
                    #pragma unroll
                    for (int am = 0; am < 2; am++)
                        #pragma unroll
                        for (int jj = 0; jj < 4; jj++)
                            mma16816(acc[am][4*bp+jj], al[am], bh[jj]);
                }
            }
        }
    }

    // ---- epilogue ----
    float sq[2][2] = {{0.f, 0.f}, {0.f, 0.f}};   // per (am,half) row partial sums
    #pragma unroll
    for (int am = 0; am < 2; am++) {
        const int gi0 = yBlk + m0 + am * 16 + (lane >> 2);
        #pragma unroll
        for (int j = 0; j < 8; j++) {
            const int gj = xBlk + n0 + j * 8 + (lane & 3) * 2;
            #pragma unroll
            for (int half = 0; half < 2; half++) {
                const int gi = gi0 + half * 8;
                float v0 = acc[am][j][half * 2 + 0];
                float v1 = acc[am][j][half * 2 + 1];
                if (STAGE == 0) {
                    const size_t idx = (size_t)gi * 2048 + gj;
                    if (gj >= 1024) {
                        const int c0 = gj - 1024;
                        v0 += aux1[((c0 + 0) & 255) * 4 + ((c0 + 0) >> 8)];
                        v1 += aux1[((c0 + 1) & 255) * 4 + ((c0 + 1) >> 8)];
                        sq[am][half] += v0 * v0 + v1 * v1;
                    }
                    fp162 h, l;
                    split2(v0, v1, h, l);
                    *reinterpret_cast<fp162*>(Ch + idx) = h;
                    *reinterpret_cast<fp162*>(Cl + idx) = l;
                } else if (STAGE == 2) {
                    const size_t idx = (size_t)gi * 2048 + gj;
                    const float kn0 = aux2[(size_t)(b * 2048 + gj + 0) * 4 + k];
                    const float kn1 = aux2[(size_t)(b * 2048 + gj + 1) * 4 + k];
                    float t0 = fminf((2.f * v0 - kn0) * 0.0625f + 14.f, 11.f);
                    float t1 = fminf((2.f * v1 - kn1) * 0.0625f + 14.f, 11.f);
                    float e0 = __expf(t0), e1 = __expf(t1);
                    sq[am][half] += e0 + e1;
                    *reinterpret_cast<fp162*>(Ch + idx) = __floats2half2_rn(e0, e1);
                } else if (STAGE == 3) {
                    const size_t idx = (size_t)gi * ldC3 + gj;
                    *reinterpret_cast<fp162*>(Ch + idx) = __floats2half2_rn(v0, v1);
                } else { // STAGE 4
                    const size_t idx = (size_t)gi * ldC + gj;
                    const float is0 = aux2[(size_t)z * 2048 + gi];
                    v0 = v0 * is0 + aux1[(gj + 0) * 4 + k];
                    v1 = v1 * is0 + aux1[(gj + 1) * 4 + k];
                    *reinterpret_cast<float2*>(Cf + idx) = make_float2(v0, v1);
                }
            }
        }
    }
    // ---- deterministic partial-sum stores ----
    if (STAGE == 0 && (xBlk + n0) >= 1024) {
        const int c0 = xBlk + n0 - 1024;
        const int khead = c0 >> 8;
        const int part  = (c0 >> 6) & 3;
        #pragma unroll
        for (int am = 0; am < 2; am++)
            #pragma unroll
            for (int half = 0; half < 2; half++) {
                float s = sq[am][half];
                s += __shfl_xor_sync(0xFFFFFFFFu, s, 1);
                s += __shfl_xor_sync(0xFFFFFFFFu, s, 2);
                if ((lane & 3) == 0) {
                    const int r_ = yBlk + m0 + am * 16 + (lane >> 2) + half * 8;
                    Cf[((size_t)r_ * 4 + khead) * 4 + part] = s;   // Cf = kn4
                }
            }
    }
    if (STAGE == 2) {
        #pragma unroll
        for (int am = 0; am < 2; am++)
            #pragma unroll
            for (int half = 0; half < 2; half++) {
                float s = sq[am][half];
                s += __shfl_xor_sync(0xFFFFFFFFu, s, 1);
                s += __shfl_xor_sync(0xFFFFFFFFu, s, 2);
                if ((lane & 3) == 0) {
                    const int r_ = yBlk + m0 + am * 16 + (lane >> 2) + half * 8;
                    Cf[((size_t)z * 2048 + r_) * 32 + blockIdx.x * 2 + (wid >> 2)] = s;  // Cf = Spart
                }
            }
    }
}

// ---------------- fused fp32 -> fp16 hi/lo split (wv: hi only) ---------------
__global__ void split_all(const float4* __restrict__ xsa, const float4* __restrict__ wq,
                          const float4* __restrict__ wk,  const float4* __restrict__ wv,
                          fp162* __restrict__ xh, fp162* __restrict__ xl,
                          fp162* __restrict__ wqkh, fp162* __restrict__ wqkl,
                          fp162* __restrict__ vh)
{
    int i = blockIdx.x * 256 + threadIdx.x;
    if (i >= 1048576) return;
    if (i >= 786432) {
        int j = i - 786432;
        float4 v = wv[j];
        vh[2 * j]     = __floats2half2_rn(v.x, v.y);
        vh[2 * j + 1] = __floats2half2_rn(v.z, v.w);
        return;
    }
    const float4* src;
    fp162 *hi, *lo;
    int j;
    if (i < 524288)       { src = xsa; hi = xh; lo = xl; j = i; }
    else if (i < 655360)  { src = wq;  hi = wqkh; lo = wqkl; j = i - 524288; }
    else                  { src = wk;  hi = wqkh + 262144; lo = wqkl + 262144; j = i - 655360; }
    float4 v = src[j];
    fp162 h0, l0, h1, l1;
    split2(v.x, v.y, h0, l0);
    split2(v.z, v.w, h1, l1);
    hi[2 * j] = h0; hi[2 * j + 1] = h1;
    lo[2 * j] = l0; lo[2 * j + 1] = l1;
}

// ---------------- tiny combines -----------------------------------------------
__global__ void knsum_k(const float* __restrict__ kn4, float* __restrict__ kn)
{
    int i = blockIdx.x * 256 + threadIdx.x;
    if (i < 16384) {
        float4 v = reinterpret_cast<const float4*>(kn4)[i];
        kn[i] = (v.x + v.y) + (v.z + v.w);
    }
}
__global__ void invs_k(const float* __restrict__ Sp, float* __restrict__ invS)
{
    const int row = blockIdx.x * 8 + (threadIdx.x >> 5);
    const int lane = threadIdx.x & 31;
    float s = Sp[(size_t)row * 32 + lane];
    #pragma unroll
    for (int o = 16; o; o >>= 1) s += __shfl_xor_sync(0xFFFFFFFFu, s, o);
    if (lane == 0) invS[row] = 1.f / s;
}

// ---------------- launch ------------------------------------------------------
extern "C" void kernel_launch(void* const* d_in, const int* in_sizes, int n_in,
                              void* d_out, int out_size)
{
    const float* xsa    = (const float*)d_in[0];
    const float* Wq     = (const float*)d_in[1];
    const float* Wk     = (const float*)d_in[2];
    const float* Wv     = (const float*)d_in[3];
    const float* biasW  = (const float*)d_in[4];
    const float* bias2W = (const float*)d_in[5];
    float* out = (float*)d_out;

    float *p_kn4, *p_kn, *p_Spart, *p_invS;
    fp16 *xsa_h, *xsa_l, *wqk_h, *wqk_l, *wv_h;
    fp16 *xqk_h, *xqk_l, *eH, *vp_h;
    cudaGetSymbolAddress((void**)&p_kn4,  g_kn4);
    cudaGetSymbolAddress((void**)&p_kn,   g_kn);
    cudaGetSymbolAddress((void**)&p_Spart, g_Spart);
    cudaGetSymbolAddress((void**)&p_invS, g_invS);
    cudaGetSymbolAddress((void**)&xsa_h, g_xsa_h);
    cudaGetSymbolAddress((void**)&xsa_l, g_xsa_l);
    cudaGetSymbolAddress((void**)&wqk_h, g_wqk_h);
    cudaGetSymbolAddress((void**)&wqk_l, g_wqk_l);
    cudaGetSymbolAddress((void**)&wv_h,  g_wv_h);
    cudaGetSymbolAddress((void**)&xqk_h, g_xqk_h);
    cudaGetSymbolAddress((void**)&xqk_l, g_xqk_l);
    cudaGetSymbolAddress((void**)&eH,    g_eH);
    cudaGetSymbolAddress((void**)&vp_h,  g_vp_h);

    cudaFuncSetAttribute(hgemm<0>, cudaFuncAttributeMaxDynamicSharedMemorySize, 98304);
    cudaFuncSetAttribute(hgemm<2>, cudaFuncAttributeMaxDynamicSharedMemorySize, 98304);
    cudaFuncSetAttribute(hgemm<3>, cudaFuncAttributeMaxDynamicSharedMemorySize, 98304);
    cudaFuncSetAttribute(hgemm<4>, cudaFuncAttributeMaxDynamicSharedMemorySize, 98304);

    // (1) fused input split
    split_all<<<4096, 256>>>((const float4*)xsa, (const float4*)Wq,
                             (const float4*)Wk,  (const float4*)Wv,
                             (fp162*)xsa_h, (fp162*)xsa_l,
                             (fp162*)wqk_h, (fp162*)wqk_l,
                             (fp162*)wv_h);
    // (2) S3: Vp = xsa @ Wv3[k]
    hgemm<3><<<dim3(4, 16, 8), 256, 98304>>>(xsa_h, xsa_l, wv_h, wv_h,
                                             nullptr, vp_h, nullptr, nullptr, nullptr);
    // (3) S0: [xq|xkb] hi/lo + kn4 partials
    hgemm<0><<<dim3(16, 32, 1), 256, 98304>>>(xsa_h, xsa_l, wqk_h, wqk_l,
                                              p_kn4, xqk_h, xqk_l, biasW, nullptr);
    // (4) kn = sum of 4 parts
    knsum_k<<<64, 256>>>(p_kn4, p_kn);
    // (5) S2: eH + Spart partials
    hgemm<2><<<dim3(16, 16, 8), 256, 98304>>>(xqk_h, xqk_l, xqk_h, xqk_h,
                                              p_Spart, eH, nullptr, nullptr, p_kn);
    // (6) invS
    invs_k<<<2048, 256>>>(p_Spart, p_invS);
    // (7) S4: out = (eH @ Vp) * invS + bias2  (BK=64)
    hgemm<4><<<dim3(4, 16, 8), 256, 98304>>>(eH, eH, vp_h, vp_h,
                                             out, nullptr, nullptr, bias2W, p_invS);
}

// round 13
// speedup vs baseline: 2.2197x; 1.1587x over previous
#include <cuda_runtime.h>
#include <cuda_fp16.h>
#include <cstdint>

#define BB 2
#define LL 2048
#define EE 512
#define KH 4
#define KE 256
typedef __half fp16;
typedef __half2 fp162;

// ---------------- scratch (device globals) ----------------------------------
__device__ float g_kn4 [4096*4*4];                    // per (row,head,part) |xkb|^2 partials
__device__ float g_kn  [4096*4];
__device__ float g_Spart[(size_t)16384*32];           // per (z,row) x 32 partial exp-sums
__device__ float g_invS[16384];

__device__ fp16 g_xsa_h[(size_t)4096*512],  g_xsa_l[(size_t)4096*512];
__device__ fp16 g_wqk_h[(size_t)2048*512],  g_wqk_l[(size_t)2048*512];   // [Wq;Wk]
__device__ fp16 g_wv_h [(size_t)512*2048];
__device__ fp16 g_xqk_h[(size_t)4096*2048];           // [xq | xkb] hi only
__device__ fp16 g_eH  [(size_t)8*2048*2048];          // exp((2cross-kn)/16+14) fp16
__device__ fp16 g_vp_h [(size_t)8*2048*512];

// ---------------- helpers ----------------------------------------------------
__device__ __forceinline__ uint32_t smem_u32(const void* p) {
    uint32_t a;
    asm("{ .reg .u64 t; cvta.to.shared.u64 t, %1; cvt.u32.u64 %0, t; }" : "=r"(a) : "l"(p));
    return a;
}
__device__ __forceinline__ void cpa16(uint32_t d, const void* s) {
    asm volatile("cp.async.cg.shared.global [%0], [%1], 16;" :: "r"(d), "l"(s));
}
#define CP_COMMIT() asm volatile("cp.async.commit_group;" ::: "memory")
#define CP_WAIT1()  asm volatile("cp.async.wait_group 1;" ::: "memory")

__device__ __forceinline__ void ldsm_x4(uint32_t& r0, uint32_t& r1, uint32_t& r2,
                                        uint32_t& r3, uint32_t a) {
    asm volatile("ldmatrix.sync.aligned.m8n8.x4.shared.b16 {%0,%1,%2,%3}, [%4];"
                 : "=r"(r0), "=r"(r1), "=r"(r2), "=r"(r3) : "r"(a));
}
__device__ __forceinline__ void ldsm_x4t(uint32_t& r0, uint32_t& r1, uint32_t& r2,
                                         uint32_t& r3, uint32_t a) {
    asm volatile("ldmatrix.sync.aligned.m8n8.x4.trans.shared.b16 {%0,%1,%2,%3}, [%4];"
                 : "=r"(r0), "=r"(r1), "=r"(r2), "=r"(r3) : "r"(a));
}
__device__ __forceinline__ void mma16816(float c[4], const uint32_t a[4],
                                         const uint32_t bq[2]) {
    asm volatile("mma.sync.aligned.m16n8k16.row.col.f32.f16.f16.f32 "
                 "{%0,%1,%2,%3}, {%4,%5,%6,%7}, {%8,%9}, {%0,%1,%2,%3};"
                 : "+f"(c[0]), "+f"(c[1]), "+f"(c[2]), "+f"(c[3])
                 : "r"(a[0]), "r"(a[1]), "r"(a[2]), "r"(a[3]), "r"(bq[0]), "r"(bq[1]));
}
__device__ __forceinline__ void split2(float a, float b, fp162& h, fp162& l) {
    h = __floats2half2_rn(a, b);
    l = __floats2half2_rn(a - __half2float(__low2half(h)),
                          b - __half2float(__high2half(h)));
}

// ---------------- GEMM: C[M][N] = A[M][K] * B^T ------------------------------
// STAGE 0: [xq|xkb] hi = xsa @ [Wq;Wk]^T (+bias), kn4 partials  NT 3-product BK32
// STAGE 2: eH = exp((2*xq_h.xkb_h^T - kn)/16 + 14) + Spart      NT 1-product BK64
// STAGE 3: Vp = xsa @ Wv3[k] (flat chunk k*262144)              NN 2-product BK32
// STAGE 4: out = (eH @ Vp) * invS + bias2                       NN 1-product BK64
// CTA 128x128, warp 32x64, 3-stage cp.async, 2 CTA/SM.

template<int STAGE>
__global__ __launch_bounds__(256, 2)
void hgemm(const fp16* __restrict__ gAh, const fp16* __restrict__ gAl,
           const fp16* __restrict__ gBh, const fp16* __restrict__ gBl,
           float* __restrict__ Cf, fp16* __restrict__ Ch, fp16* __restrict__ Cl,
           const float* __restrict__ aux1, const float* __restrict__ aux2)
{
    constexpr bool NT     = (STAGE == 0 || STAGE == 2);
    constexpr bool USE_BL = (STAGE == 0);
    constexpr bool USE_AL = (STAGE == 0 || STAGE == 3);
    constexpr int  BK  = (STAGE == 2 || STAGE == 4) ? 64 : 32;
    constexpr int  SN  = BK / 16;
    constexpr int  Kd  = (STAGE == 0) ? 512  : (STAGE == 2 ? 256  : (STAGE == 3 ? 512 : 2048));
    constexpr int  ldA = (STAGE == 0) ? 512  : (STAGE == 2 ? 2048 : (STAGE == 3 ? 512 : 2048));
    constexpr int  ldB = (STAGE == 0) ? 512  : (STAGE == 2 ? 2048 : 512);
    constexpr int  ldC = 2048;
    constexpr int  ldC3 = 512;
    constexpr int  NC  = Kd / BK;

    extern __shared__ char smem[];
    const uint32_t sb = smem_u32(smem);
    const int tid = threadIdx.x;
    const int z = blockIdx.z, b = z >> 2, k = z & 3;

    const fp16 *Ah = gAh, *Al = gAl, *Bh = gBh, *Bl = gBl;
    size_t coff = 0;
    if (STAGE == 2) {
        size_t o = (size_t)(b * 2048) * 2048 + (size_t)k * 256;
        Ah += o; Al += o; Bh += o + 1024; Bl += o + 1024;
        coff = (size_t)z * 2048 * 2048;
    } else if (STAGE == 3) {
        size_t oa = (size_t)(b * 2048) * 512;
        Ah += oa; Al += oa;
        size_t ob = (size_t)k * 512 * 512;
        Bh += ob; Bl += ob;
        coff = (size_t)z * 2048 * 512;
    } else if (STAGE == 4) {
        size_t oa = (size_t)z * 2048 * 2048;
        Ah += oa; Al += oa;
        size_t ob = (size_t)z * 2048 * 512;
        Bh += ob; Bl += ob;
        coff = (size_t)(b * 2048) * 2048 + (size_t)k * 512;
    }
    const int yBlk = blockIdx.y * 128, xBlk = blockIdx.x * 128;
    Ah += (size_t)yBlk * ldA; Al += (size_t)yBlk * ldA;
    if (NT) { Bh += (size_t)xBlk * ldB; Bl += (size_t)xBlk * ldB; }
    else    { Bh += xBlk; Bl += xBlk; }
    if (STAGE == 4 && Cf) Cf += coff;
    if (Ch) { Ch += coff; if (Cl) Cl += coff; }

    const int wid = tid >> 5, lane = tid & 31;
    const int m0 = (wid & 3) * 32, n0 = (wid >> 2) * 64;

    float acc[2][8][4];
    #pragma unroll
    for (int am = 0; am < 2; am++)
        #pragma unroll
        for (int j = 0; j < 8; j++)
            #pragma unroll
            for (int q = 0; q < 4; q++) acc[am][j][q] = 0.f;

    auto load_chunk = [&](int c, int buf) {
        uint32_t s0 = sb + buf * 32768;
        if (BK == 64) {
            // A: 128 rows x 64 cols fp16 (16KB), 128B rows
            #pragma unroll
            for (int h = 0; h < 4; h++) {
                int s = tid + h * 256;
                int r = s >> 3, q = s & 7;
                uint32_t d = s0 + r * 128 + ((q ^ (r & 7)) << 4);
                cpa16(d, Ah + (size_t)r * ldA + c * 64 + q * 8);
            }
            if (NT) {
                // B (stage 2): 128 n-rows x 64 k-cols (16KB), 128B rows
                #pragma unroll
                for (int h = 0; h < 4; h++) {
                    int s = tid + h * 256;
                    int r = s >> 3, q = s & 7;
                    uint32_t d = s0 + 16384 + r * 128 + ((q ^ (r & 7)) << 4);
                    cpa16(d, Bh + (size_t)r * ldB + c * 64 + q * 8);
                }
            } else {
                // B (stage 4): 64 k-rows x 128 cols (16KB), 256B rows
                #pragma unroll
                for (int h = 0; h < 4; h++) {
                    int s = tid + h * 256;
                    int kk = s >> 4, q = s & 15;
                    uint32_t d = s0 + 16384 + kk * 256 + ((q ^ (kk & 7)) << 4);
                    cpa16(d, Bh + (size_t)(c * 64 + kk) * ldB + q * 8);
                }
            }
            return;
        }
        #pragma unroll
        for (int h = 0; h < 2; h++) {
            int s = tid + h * 256;
            int r = s >> 2, q = s & 3;
            uint32_t d = s0 + r * 64 + ((q ^ ((r >> 1) & 3)) << 4);
            cpa16(d, Ah + (size_t)r * ldA + c * 32 + q * 8);
            if (USE_AL) cpa16(d + 8192, Al + (size_t)r * ldA + c * 32 + q * 8);
        }
        if (NT) {
            #pragma unroll
            for (int h = 0; h < 2; h++) {
                int s = tid + h * 256;
                int r = s >> 2, q = s & 3;
                uint32_t d = s0 + 16384 + r * 64 + ((q ^ ((r >> 1) & 3)) << 4);
                cpa16(d, Bh + (size_t)r * ldB + c * 32 + q * 8);
                if (USE_BL) cpa16(d + 8192, Bl + (size_t)r * ldB + c * 32 + q * 8);
            }
        } else {
            #pragma unroll
            for (int h = 0; h < 2; h++) {
                int s = tid + h * 256;
                int kk = s >> 4, q = s & 15;
                uint32_t d = s0 + 16384 + kk * 256 + ((q ^ (kk & 7)) << 4);
                cpa16(d, Bh + (size_t)(c * 32 + kk) * ldB + q * 8);
                if (USE_BL) cpa16(d + 8192, Bl + (size_t)(c * 32 + kk) * ldB + q * 8);
            }
        }
    };

    load_chunk(0, 0); CP_COMMIT();
    load_chunk(1, 1); CP_COMMIT();

    #pragma unroll 1
    for (int c = 0; c < NC; c++) {
        CP_WAIT1();
        __syncthreads();
        if (c + 2 < NC) load_chunk(c + 2, (c + 2) % 3);
        CP_COMMIT();

        const uint32_t s0 = sb + (c % 3) * 32768;
        #pragma unroll
        for (int s = 0; s < SN; s++) {
            uint32_t ah[2][4], al[2][4];
            #pragma unroll
            for (int am = 0; am < 2; am++) {
                int row = m0 + am * 16 + (lane & 15);
                int q = s * 2 + (lane >> 4);
                uint32_t addr;
                if (BK == 64)
                    addr = s0 + row * 128 + ((q ^ (row & 7)) << 4);
                else
                    addr = s0 + row * 64 + ((q ^ ((row >> 1) & 3)) << 4);
                ldsm_x4(ah[am][0], ah[am][1], ah[am][2], ah[am][3], addr);
                if (USE_AL)
                    ldsm_x4(al[am][0], al[am][1], al[am][2], al[am][3], addr + 8192);
            }
            #pragma unroll
            for (int bp = 0; bp < 2; bp++) {
                uint32_t bh[4][2], bl[4][2];
                if (NT) {
                    #pragma unroll
                    for (int i = 0; i < 2; i++) {
                        int bn = 2 * bp + i;
                        int row = n0 + bn * 16 + (lane & 15);
                        int q = s * 2 + (lane >> 4);
                        uint32_t addr;
                        if (BK == 64)
                            addr = s0 + 16384 + row * 128 + ((q ^ (row & 7)) << 4);
                        else
                            addr = s0 + 16384 + row * 64 + ((q ^ ((row >> 1) & 3)) << 4);
                        uint32_t r0, r1, r2, r3;
                        ldsm_x4(r0, r1, r2, r3, addr);
                        bh[2*i][0] = r0; bh[2*i][1] = r2;
                        bh[2*i+1][0] = r1; bh[2*i+1][1] = r3;
                        if (USE_BL) {
                            ldsm_x4(r0, r1, r2, r3, addr + 8192);
                            bl[2*i][0] = r0; bl[2*i][1] = r2;
                            bl[2*i+1][0] = r1; bl[2*i+1][1] = r3;
                        }
                    }
                } else {
                    #pragma unroll
                    for (int i = 0; i < 2; i++) {
                        int bn = 2 * bp + i;
                        int g = lane >> 3;
                        int kk = s * 16 + (g & 1) * 8 + (lane & 7);
                        int q = (n0 + bn * 16) / 8 + (g >> 1);
                        uint32_t addr = s0 + 16384 + kk * 256 + ((q ^ (kk & 7)) << 4);
                        uint32_t r0, r1, r2, r3;
                        ldsm_x4t(r0, r1, r2, r3, addr);
                        bh[2*i][0] = r0; bh[2*i][1] = r1;
                        bh[2*i+1][0] = r2; bh[2*i+1][1] = r3;
                        if (USE_BL) {
                            ldsm_x4t(r0, r1, r2, r3, addr + 8192);
                            bl[2*i][0] = r0; bl[2*i][1] = r1;
                            bl[2*i+1][0] = r2; bl[2*i+1][1] = r3;
                        }
                    }
                }
                #pragma unroll
                for (int am = 0; am < 2; am++)
                    #pragma unroll
                    for (int jj = 0; jj < 4; jj++)
                        mma16816(acc[am][4*bp+jj], ah[am], bh[jj]);
                if (USE_BL) {
                    #pragma unroll
                    for (int am = 0; am < 2; am++)
                        #pragma unroll
                        for (int jj = 0; jj < 4; jj++)
                            mma16816(acc[am][4*bp+jj], ah[am], bl[jj]);
                }
                if (USE_AL) {
                    #pragma unroll
                    for (int am = 0; am < 2; am++)
                        #pragma unroll
                        for (int jj = 0; jj < 4; jj++)
                            mma16816(acc[am][4*bp+jj], al[am], bh[jj]);
                }
            }
        }
    }

    // ---- epilogue ----
    float sq[2][2] = {{0.f, 0.f}, {0.f, 0.f}};
    #pragma unroll
    for (int am = 0; am < 2; am++) {
        const int gi0 = yBlk + m0 + am * 16 + (lane >> 2);
        #pragma unroll
        for (int j = 0; j < 8; j++) {
            const int gj = xBlk + n0 + j * 8 + (lane & 3) * 2;
            #pragma unroll
            for (int half = 0; half < 2; half++) {
                const int gi = gi0 + half * 8;
                float v0 = acc[am][j][half * 2 + 0];
                float v1 = acc[am][j][half * 2 + 1];
                if (STAGE == 0) {
                    const size_t idx = (size_t)gi * 2048 + gj;
                    if (gj >= 1024) {
                        const int c0 = gj - 1024;
                        v0 += aux1[((c0 + 0) & 255) * 4 + ((c0 + 0) >> 8)];
                        v1 += aux1[((c0 + 1) & 255) * 4 + ((c0 + 1) >> 8)];
                        sq[am][half] += v0 * v0 + v1 * v1;
                    }
                    *reinterpret_cast<fp162*>(Ch + idx) = __floats2half2_rn(v0, v1);
                } else if (STAGE == 2) {
                    const size_t idx = (size_t)gi * 2048 + gj;
                    const float kn0 = aux2[(size_t)(b * 2048 + gj + 0) * 4 + k];
                    const float kn1 = aux2[(size_t)(b * 2048 + gj + 1) * 4 + k];
                    float t0 = fminf((2.f * v0 - kn0) * 0.0625f + 14.f, 11.f);
                    float t1 = fminf((2.f * v1 - kn1) * 0.0625f + 14.f, 11.f);
                    float e0 = __expf(t0), e1 = __expf(t1);
                    sq[am][half] += e0 + e1;
                    *reinterpret_cast<fp162*>(Ch + idx) = __floats2half2_rn(e0, e1);
                } else if (STAGE == 3) {
                    const size_t idx = (size_t)gi * ldC3 + gj;
                    *reinterpret_cast<fp162*>(Ch + idx) = __floats2half2_rn(v0, v1);
                } else { // STAGE 4
                    const size_t idx = (size_t)gi * ldC + gj;
                    const float is0 = aux2[(size_t)z * 2048 + gi];
                    v0 = v0 * is0 + aux1[(gj + 0) * 4 + k];
                    v1 = v1 * is0 + aux1[(gj + 1) * 4 + k];
                    *reinterpret_cast<float2*>(Cf + idx) = make_float2(v0, v1);
                }
            }
        }
    }
    // ---- deterministic partial-sum stores ----
    if (STAGE == 0 && (xBlk + n0) >= 1024) {
        const int c0 = xBlk + n0 - 1024;
        const int khead = c0 >> 8;
        const int part  = (c0 >> 6) & 3;
        #pragma unroll
        for (int am = 0; am < 2; am++)
            #pragma unroll
            for (int half = 0; half < 2; half++) {
                float s = sq[am][half];
                s += __shfl_xor_sync(0xFFFFFFFFu, s, 1);
                s += __shfl_xor_sync(0xFFFFFFFFu, s, 2);
                if ((lane & 3) == 0) {
                    const int r_ = yBlk + m0 + am * 16 + (lane >> 2) + half * 8;
                    Cf[((size_t)r_ * 4 + khead) * 4 + part] = s;   // Cf = kn4
                }
            }
    }
    if (STAGE == 2) {
        #pragma unroll
        for (int am = 0; am < 2; am++)
            #pragma unroll
            for (int half = 0; half < 2; half++) {
                float s = sq[am][half];
                s += __shfl_xor_sync(0xFFFFFFFFu, s, 1);
                s += __shfl_xor_sync(0xFFFFFFFFu, s, 2);
                if ((lane & 3) == 0) {
                    const int r_ = yBlk + m0 + am * 16 + (lane >> 2) + half * 8;
                    Cf[((size_t)z * 2048 + r_) * 32 + blockIdx.x * 2 + (wid >> 2)] = s;  // Cf = Spart
                }
            }
    }
}

// ---------------- fused fp32 -> fp16 hi/lo split (wv: hi only) ---------------
__global__ void split_all(const float4* __restrict__ xsa, const float4* __restrict__ wq,
                          const float4* __restrict__ wk,  const float4* __restrict__ wv,
                          fp162* __restrict__ xh, fp162* __restrict__ xl,
                          fp162* __restrict__ wqkh, fp162* __restrict__ wqkl,
                          fp162* __restrict__ vh)
{
    int i = blockIdx.x * 256 + threadIdx.x;
    if (i >= 1048576) return;
    if (i >= 786432) {
        int j = i - 786432;
        float4 v = wv[j];
        vh[2 * j]     = __floats2half2_rn(v.x, v.y);
        vh[2 * j + 1] = __floats2half2_rn(v.z, v.w);
        return;
    }
    const float4* src;
    fp162 *hi, *lo;
    int j;
    if (i < 524288)       { src = xsa; hi = xh; lo = xl; j = i; }
    else if (i < 655360)  { src = wq;  hi = wqkh; lo = wqkl; j = i - 524288; }
    else                  { src = wk;  hi = wqkh + 262144; lo = wqkl + 262144; j = i - 655360; }
    float4 v = src[j];
    fp162 h0, l0, h1, l1;
    split2(v.x, v.y, h0, l0);
    split2(v.z, v.w, h1, l1);
    hi[2 * j] = h0; hi[2 * j + 1] = h1;
    lo[2 * j] = l0; lo[2 * j + 1] = l1;
}

// ---------------- tiny combines -----------------------------------------------
__global__ void knsum_k(const float* __restrict__ kn4, float* __restrict__ kn)
{
    int i = blockIdx.x * 256 + threadIdx.x;
    if (i < 16384) {
        float4 v = reinterpret_cast<const float4*>(kn4)[i];
        kn[i] = (v.x + v.y) + (v.z + v.w);
    }
}
__global__ void invs_k(const float* __restrict__ Sp, float* __restrict__ invS)
{
    const int row = blockIdx.x * 8 + (threadIdx.x >> 5);
    const int lane = threadIdx.x & 31;
    float s = Sp[(size_t)row * 32 + lane];
    #pragma unroll
    for (int o = 16; o; o >>= 1) s += __shfl_xor_sync(0xFFFFFFFFu, s, o);
    if (lane == 0) invS[row] = 1.f / s;
}

// ---------------- launch ------------------------------------------------------
extern "C" void kernel_launch(void* const* d_in, const int* in_sizes, int n_in,
                              void* d_out, int out_size)
{
    const float* xsa    = (const float*)d_in[0];
    const float* Wq     = (const float*)d_in[1];
    const float* Wk     = (const float*)d_in[2];
    const float* Wv     = (const float*)d_in[3];
    const float* biasW  = (const float*)d_in[4];
    const float* bias2W = (const float*)d_in[5];
    float* out = (float*)d_out;

    float *p_kn4, *p_kn, *p_Spart, *p_invS;
    fp16 *xsa_h, *xsa_l, *wqk_h, *wqk_l, *wv_h;
    fp16 *xqk_h, *eH, *vp_h;
    cudaGetSymbolAddress((void**)&p_kn4,  g_kn4);
    cudaGetSymbolAddress((void**)&p_kn,   g_kn);
    cudaGetSymbolAddress((void**)&p_Spart, g_Spart);
    cudaGetSymbolAddress((void**)&p_invS, g_invS);
    cudaGetSymbolAddress((void**)&xsa_h, g_xsa_h);
    cudaGetSymbolAddress((void**)&xsa_l, g_xsa_l);
    cudaGetSymbolAddress((void**)&wqk_h, g_wqk_h);
    cudaGetSymbolAddress((void**)&wqk_l, g_wqk_l);
    cudaGetSymbolAddress((void**)&wv_h,  g_wv_h);
    cudaGetSymbolAddress((void**)&xqk_h, g_xqk_h);
    cudaGetSymbolAddress((void**)&eH,    g_eH);
    cudaGetSymbolAddress((void**)&vp_h,  g_vp_h);

    cudaFuncSetAttribute(hgemm<0>, cudaFuncAttributeMaxDynamicSharedMemorySize, 98304);
    cudaFuncSetAttribute(hgemm<2>, cudaFuncAttributeMaxDynamicSharedMemorySize, 98304);
    cudaFuncSetAttribute(hgemm<3>, cudaFuncAttributeMaxDynamicSharedMemorySize, 98304);
    cudaFuncSetAttribute(hgemm<4>, cudaFuncAttributeMaxDynamicSharedMemorySize, 98304);

    // (1) fused input split
    split_all<<<4096, 256>>>((const float4*)xsa, (const float4*)Wq,
                             (const float4*)Wk,  (const float4*)Wv,
                             (fp162*)xsa_h, (fp162*)xsa_l,
                             (fp162*)wqk_h, (fp162*)wqk_l,
                             (fp162*)wv_h);
    // (2) S3: Vp = xsa @ Wv3[k]
    hgemm<3><<<dim3(4, 16, 8), 256, 98304>>>(xsa_h, xsa_l, wv_h, wv_h,
                                             nullptr, vp_h, nullptr, nullptr, nullptr);
    // (3) S0: [xq|xkb] hi + kn4 partials (3-product internally)
    hgemm<0><<<dim3(16, 32, 1), 256, 98304>>>(xsa_h, xsa_l, wqk_h, wqk_l,
                                              p_kn4, xqk_h, nullptr, biasW, nullptr);
    // (4) kn = sum of 4 parts
    knsum_k<<<64, 256>>>(p_kn4, p_kn);
    // (5) S2: eH + Spart partials  (1-product, BK=64)
    hgemm<2><<<dim3(16, 16, 8), 256, 98304>>>(xqk_h, xqk_h, xqk_h, xqk_h,
                                              p_Spart, eH, nullptr, nullptr, p_kn);
    // (6) invS
    invs_k<<<2048, 256>>>(p_Spart, p_invS);
    // (7) S4: out = (eH @ Vp) * invS + bias2  (BK=64)
    hgemm<4><<<dim3(4, 16, 8), 256, 98304>>>(eH, eH, vp_h, vp_h,
                                             out, nullptr, nullptr, bias2W, p_invS);
}

// round 14
// speedup vs baseline: 2.6013x; 1.1719x over previous
#include <cuda_runtime.h>
#include <cuda_fp16.h>
#include <cstdint>

#define BB 2
#define LL 2048
#define EE 512
#define KH 4
#define KE 256
typedef __half fp16;
typedef __half2 fp162;

// ---------------- scratch (device globals) ----------------------------------
__device__ float g_kn4 [4096*4*4];                    // per (row,head,part) |xkb|^2 partials
__device__ float g_kn  [4096*4];
__device__ float g_Spart[(size_t)16384*32];           // per (z,row) x 32 partial exp-sums
__device__ float g_invS[16384];

__device__ fp16 g_xsa_h[(size_t)4096*512],  g_xsa_l[(size_t)4096*512];
__device__ fp16 g_wqk_h[(size_t)2048*512];            // [Wq;Wk] hi only
__device__ fp16 g_wv_h [(size_t)512*2048];
__device__ fp16 g_xqk_h[(size_t)4096*2048];           // [xq | xkb] hi only
__device__ fp16 g_eH  [(size_t)8*2048*2048];          // exp((2cross-kn)/16+14) fp16
__device__ fp16 g_vp_h [(size_t)8*2048*512];

// ---------------- helpers ----------------------------------------------------
__device__ __forceinline__ uint32_t smem_u32(const void* p) {
    uint32_t a;
    asm("{ .reg .u64 t; cvta.to.shared.u64 t, %1; cvt.u32.u64 %0, t; }" : "=r"(a) : "l"(p));
    return a;
}
__device__ __forceinline__ void cpa16(uint32_t d, const void* s) {
    asm volatile("cp.async.cg.shared.global [%0], [%1], 16;" :: "r"(d), "l"(s));
}
#define CP_COMMIT() asm volatile("cp.async.commit_group;" ::: "memory")
#define CP_WAIT1()  asm volatile("cp.async.wait_group 1;" ::: "memory")

__device__ __forceinline__ void ldsm_x4(uint32_t& r0, uint32_t& r1, uint32_t& r2,
                                        uint32_t& r3, uint32_t a) {
    asm volatile("ldmatrix.sync.aligned.m8n8.x4.shared.b16 {%0,%1,%2,%3}, [%4];"
                 : "=r"(r0), "=r"(r1), "=r"(r2), "=r"(r3) : "r"(a));
}
__device__ __forceinline__ void ldsm_x4t(uint32_t& r0, uint32_t& r1, uint32_t& r2,
                                         uint32_t& r3, uint32_t a) {
    asm volatile("ldmatrix.sync.aligned.m8n8.x4.trans.shared.b16 {%0,%1,%2,%3}, [%4];"
                 : "=r"(r0), "=r"(r1), "=r"(r2), "=r"(r3) : "r"(a));
}
__device__ __forceinline__ void mma16816(float c[4], const uint32_t a[4],
                                         const uint32_t bq[2]) {
    asm volatile("mma.sync.aligned.m16n8k16.row.col.f32.f16.f16.f32 "
                 "{%0,%1,%2,%3}, {%4,%5,%6,%7}, {%8,%9}, {%0,%1,%2,%3};"
                 : "+f"(c[0]), "+f"(c[1]), "+f"(c[2]), "+f"(c[3])
                 : "r"(a[0]), "r"(a[1]), "r"(a[2]), "r"(a[3]), "r"(bq[0]), "r"(bq[1]));
}
__device__ __forceinline__ void split2(float a, float b, fp162& h, fp162& l) {
    h = __floats2half2_rn(a, b);
    l = __floats2half2_rn(a - __half2float(__low2half(h)),
                          b - __half2float(__high2half(h)));
}

// ---------------- GEMM: C[M][N] = A[M][K] * B^T ------------------------------
// STAGE 0: [xq|xkb] hi = xsa @ [Wq;Wk]^T (+bias), kn4 partials  NT 2-product BK32
// STAGE 2: eH = exp((2*xq_h.xkb_h^T - kn)/16 + 14) + Spart      NT 1-product BK64
// STAGE 3: Vp = xsa_h @ Wv3[k] (flat chunk k*262144)            NN 1-product BK64
// STAGE 4: out = (eH @ Vp) * invS + bias2                       NN 1-product BK64
// CTA 128x128, warp 32x64, 3-stage cp.async, 2 CTA/SM.

template<int STAGE>
__global__ __launch_bounds__(256, 2)
void hgemm(const fp16* __restrict__ gAh, const fp16* __restrict__ gAl,
           const fp16* __restrict__ gBh,
           float* __restrict__ Cf, fp16* __restrict__ Ch,
           const float* __restrict__ aux1, const float* __restrict__ aux2)
{
    constexpr bool NT     = (STAGE == 0 || STAGE == 2);
    constexpr bool USE_AL = (STAGE == 0);                // only S0 uses A-lo
    constexpr int  BK  = (STAGE == 0) ? 32 : 64;
    constexpr int  SN  = BK / 16;
    constexpr int  Kd  = (STAGE == 0) ? 512  : (STAGE == 2 ? 256  : (STAGE == 3 ? 512 : 2048));
    constexpr int  ldA = (STAGE == 0) ? 512  : (STAGE == 2 ? 2048 : (STAGE == 3 ? 512 : 2048));
    constexpr int  ldB = (STAGE == 0) ? 512  : (STAGE == 2 ? 2048 : 512);
    constexpr int  ldC = 2048;
    constexpr int  ldC3 = 512;
    constexpr int  NC  = Kd / BK;

    extern __shared__ char smem[];
    const uint32_t sb = smem_u32(smem);
    const int tid = threadIdx.x;
    const int z = blockIdx.z, b = z >> 2, k = z & 3;

    const fp16 *Ah = gAh, *Al = gAl, *Bh = gBh;
    size_t coff = 0;
    if (STAGE == 2) {
        size_t o = (size_t)(b * 2048) * 2048 + (size_t)k * 256;
        Ah += o; Bh += o + 1024;
        coff = (size_t)z * 2048 * 2048;
    } else if (STAGE == 3) {
        size_t oa = (size_t)(b * 2048) * 512;
        Ah += oa;
        Bh += (size_t)k * 512 * 512;
        coff = (size_t)z * 2048 * 512;
    } else if (STAGE == 4) {
        Ah += (size_t)z * 2048 * 2048;
        Bh += (size_t)z * 2048 * 512;
        coff = (size_t)(b * 2048) * 2048 + (size_t)k * 512;
    }
    const int yBlk = blockIdx.y * 128, xBlk = blockIdx.x * 128;
    Ah += (size_t)yBlk * ldA;
    if (USE_AL) Al += (size_t)yBlk * ldA;
    if (NT) Bh += (size_t)xBlk * ldB;
    else    Bh += xBlk;
    if (STAGE == 4 && Cf) Cf += coff;
    if (Ch) Ch += coff;

    const int wid = tid >> 5, lane = tid & 31;
    const int m0 = (wid & 3) * 32, n0 = (wid >> 2) * 64;

    float acc[2][8][4];
    #pragma unroll
    for (int am = 0; am < 2; am++)
        #pragma unroll
        for (int j = 0; j < 8; j++)
            #pragma unroll
            for (int q = 0; q < 4; q++) acc[am][j][q] = 0.f;

    auto load_chunk = [&](int c, int buf) {
        uint32_t s0 = sb + buf * 32768;
        if (BK == 64) {
            // A: 128 rows x 64 cols fp16 (16KB), 128B rows
            #pragma unroll
            for (int h = 0; h < 4; h++) {
                int s = tid + h * 256;
                int r = s >> 3, q = s & 7;
                uint32_t d = s0 + r * 128 + ((q ^ (r & 7)) << 4);
                cpa16(d, Ah + (size_t)r * ldA + c * 64 + q * 8);
            }
            if (NT) {
                // B (stage 2): 128 n-rows x 64 k-cols (16KB), 128B rows
                #pragma unroll
                for (int h = 0; h < 4; h++) {
                    int s = tid + h * 256;
                    int r = s >> 3, q = s & 7;
                    uint32_t d = s0 + 16384 + r * 128 + ((q ^ (r & 7)) << 4);
                    cpa16(d, Bh + (size_t)r * ldB + c * 64 + q * 8);
                }
            } else {
                // B (stages 3,4): 64 k-rows x 128 cols (16KB), 256B rows
                #pragma unroll
                for (int h = 0; h < 4; h++) {
                    int s = tid + h * 256;
                    int kk = s >> 4, q = s & 15;
                    uint32_t d = s0 + 16384 + kk * 256 + ((q ^ (kk & 7)) << 4);
                    cpa16(d, Bh + (size_t)(c * 64 + kk) * ldB + q * 8);
                }
            }
            return;
        }
        // STAGE 0: BK32, A hi+lo, B hi
        #pragma unroll
        for (int h = 0; h < 2; h++) {
            int s = tid + h * 256;
            int r = s >> 2, q = s & 3;
            uint32_t d = s0 + r * 64 + ((q ^ ((r >> 1) & 3)) << 4);
            cpa16(d,        Ah + (size_t)r * ldA + c * 32 + q * 8);
            cpa16(d + 8192, Al + (size_t)r * ldA + c * 32 + q * 8);
        }
        #pragma unroll
        for (int h = 0; h < 2; h++) {
            int s = tid + h * 256;
            int r = s >> 2, q = s & 3;
            uint32_t d = s0 + 16384 + r * 64 + ((q ^ ((r >> 1) & 3)) << 4);
            cpa16(d, Bh + (size_t)r * ldB + c * 32 + q * 8);
        }
    };

    load_chunk(0, 0); CP_COMMIT();
    load_chunk(1, 1); CP_COMMIT();

    #pragma unroll 1
    for (int c = 0; c < NC; c++) {
        CP_WAIT1();
        __syncthreads();
        if (c + 2 < NC) load_chunk(c + 2, (c + 2) % 3);
        CP_COMMIT();

        const uint32_t s0 = sb + (c % 3) * 32768;
        #pragma unroll
        for (int s = 0; s < SN; s++) {
            uint32_t ah[2][4], al[2][4];
            #pragma unroll
            for (int am = 0; am < 2; am++) {
                int row = m0 + am * 16 + (lane & 15);
                int q = s * 2 + (lane >> 4);
                uint32_t addr;
                if (BK == 64)
                    addr = s0 + row * 128 + ((q ^ (row & 7)) << 4);
                else
                    addr = s0 + row * 64 + ((q ^ ((row >> 1) & 3)) << 4);
                ldsm_x4(ah[am][0], ah[am][1], ah[am][2], ah[am][3], addr);
                if (USE_AL)
                    ldsm_x4(al[am][0], al[am][1], al[am][2], al[am][3], addr + 8192);
            }
            #pragma unroll
            for (int bp = 0; bp < 2; bp++) {
                uint32_t bh[4][2];
                if (NT) {
                    #pragma unroll
                    for (int i = 0; i < 2; i++) {
                        int bn = 2 * bp + i;
                        int row = n0 + bn * 16 + (lane & 15);
                        int q = s * 2 + (lane >> 4);
                        uint32_t addr;
                        if (BK == 64)
                            addr = s0 + 16384 + row * 128 + ((q ^ (row & 7)) << 4);
                        else
                            addr = s0 + 16384 + row * 64 + ((q ^ ((row >> 1) & 3)) << 4);
                        uint32_t r0, r1, r2, r3;
                        ldsm_x4(r0, r1, r2, r3, addr);
                        bh[2*i][0] = r0; bh[2*i][1] = r2;
                        bh[2*i+1][0] = r1; bh[2*i+1][1] = r3;
                    }
                } else {
                    #pragma unroll
                    for (int i = 0; i < 2; i++) {
                        int bn = 2 * bp + i;
                        int g = lane >> 3;
                        int kk = s * 16 + (g & 1) * 8 + (lane & 7);
                        int q = (n0 + bn * 16) / 8 + (g >> 1);
                        uint32_t addr = s0 + 16384 + kk * 256 + ((q ^ (kk & 7)) << 4);
                        uint32_t r0, r1, r2, r3;
                        ldsm_x4t(r0, r1, r2, r3, addr);
                        bh[2*i][0] = r0; bh[2*i][1] = r1;
                        bh[2*i+1][0] = r2; bh[2*i+1][1] = r3;
                    }
                }
                #pragma unroll
                for (int am = 0; am < 2; am++)
                    #pragma unroll
                    for (int jj = 0; jj < 4; jj++)
                        mma16816(acc[am][4*bp+jj], ah[am], bh[jj]);
                if (USE_AL) {
                    #pragma unroll
                    for (int am = 0; am < 2; am++)
                        #pragma unroll
                        for (int jj = 0; jj < 4; jj++)
                            mma16816(acc[am][4*bp+jj], al[am], bh[jj]);
                }
            }
        }
    }

    // ---- epilogue ----
    float sq[2][2] = {{0.f, 0.f}, {0.f, 0.f}};
    #pragma unroll
    for (int am = 0; am < 2; am++) {
        const int gi0 = yBlk + m0 + am * 16 + (lane >> 2);
        #pragma unroll
        for (int j = 0; j < 8; j++) {
            const int gj = xBlk + n0 + j * 8 + (lane & 3) * 2;
            #pragma unroll
            for (int half = 0; half < 2; half++) {
                const int gi = gi0 + half * 8;
                float v0 = acc[am][j][half * 2 + 0];
                float v1 = acc[am][j][half * 2 + 1];
                if (STAGE == 0) {
                    const size_t idx = (size_t)gi * 2048 + gj;
                    if (gj >= 1024) {
                        const int c0 = gj - 1024;
                        v0 += aux1[((c0 + 0) & 255) * 4 + ((c0 + 0) >> 8)];
                        v1 += aux1[((c0 + 1) & 255) * 4 + ((c0 + 1) >> 8)];
                        sq[am][half] += v0 * v0 + v1 * v1;
                    }
                    *reinterpret_cast<fp162*>(Ch + idx) = __floats2half2_rn(v0, v1);
                } else if (STAGE == 2) {
                    const size_t idx = (size_t)gi * 2048 + gj;
                    const float kn0 = aux2[(size_t)(b * 2048 + gj + 0) * 4 + k];
                    const float kn1 = aux2[(size_t)(b * 2048 + gj + 1) * 4 + k];
                    float t0 = fminf((2.f * v0 - kn0) * 0.0625f + 14.f, 11.f);
                    float t1 = fminf((2.f * v1 - kn1) * 0.0625f + 14.f, 11.f);
                    float e0 = __expf(t0), e1 = __expf(t1);
                    sq[am][half] += e0 + e1;
                    *reinterpret_cast<fp162*>(Ch + idx) = __floats2half2_rn(e0, e1);
                } else if (STAGE == 3) {
                    const size_t idx = (size_t)gi * ldC3 + gj;
                    *reinterpret_cast<fp162*>(Ch + idx) = __floats2half2_rn(v0, v1);
                } else { // STAGE 4
                    const size_t idx = (size_t)gi * ldC + gj;
                    const float is0 = aux2[(size_t)z * 2048 + gi];
                    v0 = v0 * is0 + aux1[(gj + 0) * 4 + k];
                    v1 = v1 * is0 + aux1[(gj + 1) * 4 + k];
                    *reinterpret_cast<float2*>(Cf + idx) = make_float2(v0, v1);
                }
            }
        }
    }
    // ---- deterministic partial-sum stores ----
    if (STAGE == 0 && (xBlk + n0) >= 1024) {
        const int c0 = xBlk + n0 - 1024;
        const int khead = c0 >> 8;
        const int part  = (c0 >> 6) & 3;
        #pragma unroll
        for (int am = 0; am < 2; am++)
            #pragma unroll
            for (int half = 0; half < 2; half++) {
                float s = sq[am][half];
                s += __shfl_xor_sync(0xFFFFFFFFu, s, 1);
                s += __shfl_xor_sync(0xFFFFFFFFu, s, 2);
                if ((lane & 3) == 0) {
                    const int r_ = yBlk + m0 + am * 16 + (lane >> 2) + half * 8;
                    Cf[((size_t)r_ * 4 + khead) * 4 + part] = s;   // Cf = kn4
                }
            }
    }
    if (STAGE == 2) {
        #pragma unroll
        for (int am = 0; am < 2; am++)
            #pragma unroll
            for (int half = 0; half < 2; half++) {
                float s = sq[am][half];
                s += __shfl_xor_sync(0xFFFFFFFFu, s, 1);
                s += __shfl_xor_sync(0xFFFFFFFFu, s, 2);
                if ((lane & 3) == 0) {
                    const int r_ = yBlk + m0 + am * 16 + (lane >> 2) + half * 8;
                    Cf[((size_t)z * 2048 + r_) * 32 + blockIdx.x * 2 + (wid >> 2)] = s;  // Cf = Spart
                }
            }
    }
}

// ---------------- fused fp32 -> fp16 split (xsa hi+lo; weights hi only) -------
__global__ void split_all(const float4* __restrict__ xsa, const float4* __restrict__ wq,
                          const float4* __restrict__ wk,  const float4* __restrict__ wv,
                          fp162* __restrict__ xh, fp162* __restrict__ xl,
                          fp162* __restrict__ wqkh, fp162* __restrict__ vh)
{
    int i = blockIdx.x * 256 + threadIdx.x;
    if (i >= 1048576) return;
    if (i < 524288) {                  // xsa: hi + lo
        float4 v = xsa[i];
        fp162 h0, l0, h1, l1;
        split2(v.x, v.y, h0, l0);
        split2(v.z, v.w, h1, l1);
        xh[2 * i] = h0; xh[2 * i + 1] = h1;
        xl[2 * i] = l0; xl[2 * i + 1] = l1;
        return;
    }
    const float4* src;
    fp162* hi;
    int j;
    if (i < 655360)       { src = wq; hi = wqkh;          j = i - 524288; }
    else if (i < 786432)  { src = wk; hi = wqkh + 262144; j = i - 655360; }
    else                  { src = wv; hi = vh;            j = i - 786432; }
    float4 v = src[j];
    hi[2 * j]     = __floats2half2_rn(v.x, v.y);
    hi[2 * j + 1] = __floats2half2_rn(v.z, v.w);
}

// ---------------- tiny combines -----------------------------------------------
__global__ void knsum_k(const float* __restrict__ kn4, float* __restrict__ kn)
{
    int i = blockIdx.x * 256 + threadIdx.x;
    if (i < 16384) {
        float4 v = reinterpret_cast<const float4*>(kn4)[i];
        kn[i] = (v.x + v.y) + (v.z + v.w);
    }
}
__global__ void invs_k(const float* __restrict__ Sp, float* __restrict__ invS)
{
    const int row = blockIdx.x * 8 + (threadIdx.x >> 5);
    const int lane = threadIdx.x & 31;
    float s = Sp[(size_t)row * 32 + lane];
    #pragma unroll
    for (int o = 16; o; o >>= 1) s += __shfl_xor_sync(0xFFFFFFFFu, s, o);
    if (lane == 0) invS[row] = 1.f / s;
}

// ---------------- launch ------------------------------------------------------
extern "C" void kernel_launch(void* const* d_in, const int* in_sizes, int n_in,
                              void* d_out, int out_size)
{
    const float* xsa    = (const float*)d_in[0];
    const float* Wq     = (const float*)d_in[1];
    const float* Wk     = (const float*)d_in[2];
    const float* Wv     = (const float*)d_in[3];
    const float* biasW  = (const float*)d_in[4];
    const float* bias2W = (const float*)d_in[5];
    float* out = (float*)d_out;

    float *p_kn4, *p_kn, *p_Spart, *p_invS;
    fp16 *xsa_h, *xsa_l, *wqk_h, *wv_h;
    fp16 *xqk_h, *eH, *vp_h;
    cudaGetSymbolAddress((void**)&p_kn4,  g_kn4);
    cudaGetSymbolAddress((void**)&p_kn,   g_kn);
    cudaGetSymbolAddress((void**)&p_Spart, g_Spart);
    cudaGetSymbolAddress((void**)&p_invS, g_invS);
    cudaGetSymbolAddress((void**)&xsa_h, g_xsa_h);
    cudaGetSymbolAddress((void**)&xsa_l, g_xsa_l);
    cudaGetSymbolAddress((void**)&wqk_h, g_wqk_h);
    cudaGetSymbolAddress((void**)&wv_h,  g_wv_h);
    cudaGetSymbolAddress((void**)&xqk_h, g_xqk_h);
    cudaGetSymbolAddress((void**)&eH,    g_eH);
    cudaGetSymbolAddress((void**)&vp_h,  g_vp_h);

    cudaFuncSetAttribute(hgemm<0>, cudaFuncAttributeMaxDynamicSharedMemorySize, 98304);
    cudaFuncSetAttribute(hgemm<2>, cudaFuncAttributeMaxDynamicSharedMemorySize, 98304);
    cudaFuncSetAttribute(hgemm<3>, cudaFuncAttributeMaxDynamicSharedMemorySize, 98304);
    cudaFuncSetAttribute(hgemm<4>, cudaFuncAttributeMaxDynamicSharedMemorySize, 98304);

    // (1) fused input split
    split_all<<<4096, 256>>>((const float4*)xsa, (const float4*)Wq,
                             (const float4*)Wk,  (const float4*)Wv,
                             (fp162*)xsa_h, (fp162*)xsa_l,
                             (fp162*)wqk_h, (fp162*)wv_h);
    // (2) S3: Vp = xsa_h @ Wv3[k]  (1-product, BK=64)
    hgemm<3><<<dim3(4, 16, 8), 256, 98304>>>(xsa_h, nullptr, wv_h,
                                             nullptr, vp_h, nullptr, nullptr);
    // (3) S0: [xq|xkb] hi + kn4 partials  (2-product, BK=32)
    hgemm<0><<<dim3(16, 32, 1), 256, 98304>>>(xsa_h, xsa_l, wqk_h,
                                              p_kn4, xqk_h, biasW, nullptr);
    // (4) kn = sum of 4 parts
    knsum_k<<<64, 256>>>(p_kn4, p_kn);
    // (5) S2: eH + Spart partials  (1-product, BK=64)
    hgemm<2><<<dim3(16, 16, 8), 256, 98304>>>(xqk_h, nullptr, xqk_h,
                                              p_Spart, eH, nullptr, p_kn);
    // (6) invS
    invs_k<<<2048, 256>>>(p_Spart, p_invS);
    // (7) S4: out = (eH @ Vp) * invS + bias2  (1-product, BK=64)
    hgemm<4><<<dim3(4, 16, 8), 256, 98304>>>(eH, nullptr, vp_h,
                                             out, nullptr, bias2W, p_invS);
}

// round 15
// speedup vs baseline: 2.7761x; 1.0672x over previous
#include <cuda_runtime.h>
#include <cuda_fp16.h>
#include <cstdint>

typedef __half fp16;
typedef __half2 fp162;

// ---------------- scratch (device globals) ----------------------------------
__device__ float g_kn4 [4096*4*4];                    // per (row,head,part) |xkb|^2 partials
__device__ float g_Spart[(size_t)16384*32];           // per (z,row) x 32 partial exp-sums

__device__ fp16 g_xsa_h[(size_t)4096*512],  g_xsa_l[(size_t)4096*512];
__device__ fp16 g_wqk_h[(size_t)2048*512];            // [Wq;Wk] hi
__device__ fp16 g_wv_h [(size_t)512*2048];
__device__ fp16 g_xqk_h[(size_t)4096*2048];           // [xq | xkb] hi
__device__ fp16 g_eH  [(size_t)8*2048*2048];
__device__ fp16 g_vp_h [(size_t)8*2048*512];

// ---------------- helpers ----------------------------------------------------
__device__ __forceinline__ uint32_t smem_u32(const void* p) {
    uint32_t a;
    asm("{ .reg .u64 t; cvta.to.shared.u64 t, %1; cvt.u32.u64 %0, t; }" : "=r"(a) : "l"(p));
    return a;
}
__device__ __forceinline__ void cpa16(uint32_t d, const void* s) {
    asm volatile("cp.async.cg.shared.global [%0], [%1], 16;" :: "r"(d), "l"(s));
}
#define CP_COMMIT() asm volatile("cp.async.commit_group;" ::: "memory")
#define CP_WAIT1()  asm volatile("cp.async.wait_group 1;" ::: "memory")

__device__ __forceinline__ void ldsm_x4(uint32_t& r0, uint32_t& r1, uint32_t& r2,
                                        uint32_t& r3, uint32_t a) {
    asm volatile("ldmatrix.sync.aligned.m8n8.x4.shared.b16 {%0,%1,%2,%3}, [%4];"
                 : "=r"(r0), "=r"(r1), "=r"(r2), "=r"(r3) : "r"(a));
}
__device__ __forceinline__ void ldsm_x4t(uint32_t& r0, uint32_t& r1, uint32_t& r2,
                                         uint32_t& r3, uint32_t a) {
    asm volatile("ldmatrix.sync.aligned.m8n8.x4.trans.shared.b16 {%0,%1,%2,%3}, [%4];"
                 : "=r"(r0), "=r"(r1), "=r"(r2), "=r"(r3) : "r"(a));
}
__device__ __forceinline__ void mma16816(float c[4], const uint32_t a[4],
                                         const uint32_t bq[2]) {
    asm volatile("mma.sync.aligned.m16n8k16.row.col.f32.f16.f16.f32 "
                 "{%0,%1,%2,%3}, {%4,%5,%6,%7}, {%8,%9}, {%0,%1,%2,%3};"
                 : "+f"(c[0]), "+f"(c[1]), "+f"(c[2]), "+f"(c[3])
                 : "r"(a[0]), "r"(a[1]), "r"(a[2]), "r"(a[3]), "r"(bq[0]), "r"(bq[1]));
}
__device__ __forceinline__ void split2(float a, float b, fp162& h, fp162& l) {
    h = __floats2half2_rn(a, b);
    l = __floats2half2_rn(a - __half2float(__low2half(h)),
                          b - __half2float(__high2half(h)));
}

// ---------------- GEMM body ----------------------------------------------------
// STAGE 0: [xq|xkb] hi = xsa @ [Wq;Wk]^T (+bias), kn4 partials  NT 2-product BK32
// STAGE 2: eH = exp((2*xq.xkb^T - kn)/16 + 14) + Spart          NT 1-product BK64
//          kn summed from kn4 in prologue (smem)
// STAGE 3: Vp = xsa_h @ Wv3[k]                                  NN 1-product BK64
// STAGE 4: out = (eH @ Vp) * invS + bias2                       NN 1-product BK64
//          invS reduced from Spart in prologue (smem)
// CTA 128x128, warp 32x64, 3-stage cp.async.

template<int STAGE>
__device__ __forceinline__ void gemm_body(
    int bx, int by, int bz, char* smem,
    const fp16* __restrict__ gAh, const fp16* __restrict__ gAl,
    const fp16* __restrict__ gBh,
    float* __restrict__ Cf, fp16* __restrict__ Ch,
    const float* __restrict__ aux1, const float* __restrict__ aux2)
{
    constexpr bool NT     = (STAGE == 0 || STAGE == 2);
    constexpr bool USE_AL = (STAGE == 0);
    constexpr int  BK  = (STAGE == 0) ? 32 : 64;
    constexpr int  SN  = BK / 16;
    constexpr int  Kd  = (STAGE == 0) ? 512  : (STAGE == 2 ? 256  : (STAGE == 3 ? 512 : 2048));
    constexpr int  ldA = (STAGE == 0) ? 512  : (STAGE == 2 ? 2048 : (STAGE == 3 ? 512 : 2048));
    constexpr int  ldB = (STAGE == 0) ? 512  : (STAGE == 2 ? 2048 : 512);
    constexpr int  NC  = Kd / BK;

    const uint32_t sb = smem_u32(smem);
    const int tid = threadIdx.x;
    const int b = bz >> 2, k = bz & 3;

    const fp16 *Ah = gAh, *Al = gAl, *Bh = gBh;
    size_t coff = 0;
    if (STAGE == 2) {
        size_t o = (size_t)(b * 2048) * 2048 + (size_t)k * 256;
        Ah += o; Bh += o + 1024;
        coff = (size_t)bz * 2048 * 2048;
    } else if (STAGE == 3) {
        Ah += (size_t)(b * 2048) * 512;
        Bh += (size_t)k * 512 * 512;
        coff = (size_t)bz * 2048 * 512;
    } else if (STAGE == 4) {
        Ah += (size_t)bz * 2048 * 2048;
        Bh += (size_t)bz * 2048 * 512;
        coff = (size_t)(b * 2048) * 2048 + (size_t)k * 512;
    }
    const int yBlk = by * 128, xBlk = bx * 128;
    Ah += (size_t)yBlk * ldA;
    if (USE_AL) Al += (size_t)yBlk * ldA;
    if (NT) Bh += (size_t)xBlk * ldB;
    else    Bh += xBlk;
    if (STAGE == 4 && Cf) Cf += coff;
    if (Ch) Ch += coff;

    float* exsm = reinterpret_cast<float*>(smem + 98304);   // 128 floats
    if (STAGE == 2 && tid < 128) {
        // kn for column gj = xBlk + tid: sum 4 parts of kn4
        float4 v = *reinterpret_cast<const float4*>(
            aux2 + ((size_t)(b * 2048 + xBlk + tid) * 4 + k) * 4);
        exsm[tid] = (v.x + v.y) + (v.z + v.w);
    }
    if (STAGE == 4 && tid < 128) {
        const float* sp = aux2 + ((size_t)bz * 2048 + yBlk + tid) * 32;
        float s = 0.f;
        #pragma unroll
        for (int i = 0; i < 32; i += 4) {
            float4 v = *reinterpret_cast<const float4*>(sp + i);
            s += (v.x + v.y) + (v.z + v.w);
        }
        exsm[tid] = 1.f / s;
    }

    const int wid = tid >> 5, lane = tid & 31;
    const int m0 = (wid & 3) * 32, n0 = (wid >> 2) * 64;

    float acc[2][8][4];
    #pragma unroll
    for (int am = 0; am < 2; am++)
        #pragma unroll
        for (int j = 0; j < 8; j++)
            #pragma unroll
            for (int q = 0; q < 4; q++) acc[am][j][q] = 0.f;

    auto load_chunk = [&](int c, int buf) {
        uint32_t s0 = sb + buf * 32768;
        if (BK == 64) {
            #pragma unroll
            for (int h = 0; h < 4; h++) {
                int s = tid + h * 256;
                int r = s >> 3, q = s & 7;
                uint32_t d = s0 + r * 128 + ((q ^ (r & 7)) << 4);
                cpa16(d, Ah + (size_t)r * ldA + c * 64 + q * 8);
            }
            if (NT) {
                #pragma unroll
                for (int h = 0; h < 4; h++) {
                    int s = tid + h * 256;
                    int r = s >> 3, q = s & 7;
                    uint32_t d = s0 + 16384 + r * 128 + ((q ^ (r & 7)) << 4);
                    cpa16(d, Bh + (size_t)r * ldB + c * 64 + q * 8);
                }
            } else {
                #pragma unroll
                for (int h = 0; h < 4; h++) {
                    int s = tid + h * 256;
                    int kk = s >> 4, q = s & 15;
                    uint32_t d = s0 + 16384 + kk * 256 + ((q ^ (kk & 7)) << 4);
                    cpa16(d, Bh + (size_t)(c * 64 + kk) * ldB + q * 8);
                }
            }
            return;
        }
        // STAGE 0: BK32, A hi+lo, B hi
        #pragma unroll
        for (int h = 0; h < 2; h++) {
            int s = tid + h * 256;
            int r = s >> 2, q = s & 3;
            uint32_t d = s0 + r * 64 + ((q ^ ((r >> 1) & 3)) << 4);
            cpa16(d,        Ah + (size_t)r * ldA + c * 32 + q * 8);
            cpa16(d + 8192, Al + (size_t)r * ldA + c * 32 + q * 8);
        }
        #pragma unroll
        for (int h = 0; h < 2; h++) {
            int s = tid + h * 256;
            int r = s >> 2, q = s & 3;
            uint32_t d = s0 + 16384 + r * 64 + ((q ^ ((r >> 1) & 3)) << 4);
            cpa16(d, Bh + (size_t)r * ldB + c * 32 + q * 8);
        }
    };

    load_chunk(0, 0); CP_COMMIT();
    load_chunk(1, 1); CP_COMMIT();

    #pragma unroll 1
    for (int c = 0; c < NC; c++) {
        CP_WAIT1();
        __syncthreads();
        if (c + 2 < NC) load_chunk(c + 2, (c + 2) % 3);
        CP_COMMIT();

        const uint32_t s0 = sb + (c % 3) * 32768;
        #pragma unroll
        for (int s = 0; s < SN; s++) {
            uint32_t ah[2][4], al[2][4];
            #pragma unroll
            for (int am = 0; am < 2; am++) {
                int row = m0 + am * 16 + (lane & 15);
                int q = s * 2 + (lane >> 4);
                uint32_t addr;
                if (BK == 64)
                    addr = s0 + row * 128 + ((q ^ (row & 7)) << 4);
                else
                    addr = s0 + row * 64 + ((q ^ ((row >> 1) & 3)) << 4);
                ldsm_x4(ah[am][0], ah[am][1], ah[am][2], ah[am][3], addr);
                if (USE_AL)
                    ldsm_x4(al[am][0], al[am][1], al[am][2], al[am][3], addr + 8192);
            }
            #pragma unroll
            for (int bp = 0; bp < 2; bp++) {
                uint32_t bh[4][2];
                if (NT) {
                    #pragma unroll
                    for (int i = 0; i < 2; i++) {
                        int bn = 2 * bp + i;
                        int row = n0 + bn * 16 + (lane & 15);
                        int q = s * 2 + (lane >> 4);
                        uint32_t addr;
                        if (BK == 64)
                            addr = s0 + 16384 + row * 128 + ((q ^ (row & 7)) << 4);
                        else
                            addr = s0 + 16384 + row * 64 + ((q ^ ((row >> 1) & 3)) << 4);
                        uint32_t r0, r1, r2, r3;
                        ldsm_x4(r0, r1, r2, r3, addr);
                        bh[2*i][0] = r0; bh[2*i][1] = r2;
                        bh[2*i+1][0] = r1; bh[2*i+1][1] = r3;
                    }
                } else {
                    #pragma unroll
                    for (int i = 0; i < 2; i++) {
                        int bn = 2 * bp + i;
                        int g = lane >> 3;
                        int kk = s * 16 + (g & 1) * 8 + (lane & 7);
                        int q = (n0 + bn * 16) / 8 + (g >> 1);
                        uint32_t addr = s0 + 16384 + kk * 256 + ((q ^ (kk & 7)) << 4);
                        uint32_t r0, r1, r2, r3;
                        ldsm_x4t(r0, r1, r2, r3, addr);
                        bh[2*i][0] = r0; bh[2*i][1] = r1;
                        bh[2*i+1][0] = r2; bh[2*i+1][1] = r3;
                    }
                }
                #pragma unroll
                for (int am = 0; am < 2; am++)
                    #pragma unroll
                    for (int jj = 0; jj < 4; jj++)
                        mma16816(acc[am][4*bp+jj], ah[am], bh[jj]);
                if (USE_AL) {
                    #pragma unroll
                    for (int am = 0; am < 2; am++)
                        #pragma unroll
                        for (int jj = 0; jj < 4; jj++)
                            mma16816(acc[am][4*bp+jj], al[am], bh[jj]);
                }
            }
        }
    }

    // ---- epilogue ----
    float sq[2][2] = {{0.f, 0.f}, {0.f, 0.f}};
    #pragma unroll
    for (int am = 0; am < 2; am++) {
        const int gi0 = yBlk + m0 + am * 16 + (lane >> 2);
        #pragma unroll
        for (int j = 0; j < 8; j++) {
            const int gj = xBlk + n0 + j * 8 + (lane & 3) * 2;
            #pragma unroll
            for (int half = 0; half < 2; half++) {
                const int gi = gi0 + half * 8;
                float v0 = acc[am][j][half * 2 + 0];
                float v1 = acc[am][j][half * 2 + 1];
                if (STAGE == 0) {
                    const size_t idx = (size_t)gi * 2048 + gj;
                    if (gj >= 1024) {
                        const int c0 = gj - 1024;
                        v0 += aux1[((c0 + 0) & 255) * 4 + ((c0 + 0) >> 8)];
                        v1 += aux1[((c0 + 1) & 255) * 4 + ((c0 + 1) >> 8)];
                        sq[am][half] += v0 * v0 + v1 * v1;
                    }
                    *reinterpret_cast<fp162*>(Ch + idx) = __floats2half2_rn(v0, v1);
                } else if (STAGE == 2) {
                    const size_t idx = (size_t)gi * 2048 + gj;
                    const float kn0 = exsm[gj - xBlk];
                    const float kn1 = exsm[gj - xBlk + 1];
                    float t0 = fminf((2.f * v0 - kn0) * 0.0625f + 14.f, 11.f);
                    float t1 = fminf((2.f * v1 - kn1) * 0.0625f + 14.f, 11.f);
                    float e0 = __expf(t0), e1 = __expf(t1);
                    sq[am][half] += e0 + e1;
                    *reinterpret_cast<fp162*>(Ch + idx) = __floats2half2_rn(e0, e1);
                } else if (STAGE == 3) {
                    const size_t idx = (size_t)gi * 512 + gj;
                    *reinterpret_cast<fp162*>(Ch + idx) = __floats2half2_rn(v0, v1);
                } else { // STAGE 4
                    const size_t idx = (size_t)gi * 2048 + gj;
                    const float is0 = exsm[gi - yBlk];
                    v0 = v0 * is0 + aux1[(gj + 0) * 4 + k];
                    v1 = v1 * is0 + aux1[(gj + 1) * 4 + k];
                    *reinterpret_cast<float2*>(Cf + idx) = make_float2(v0, v1);
                }
            }
        }
    }
    // ---- deterministic partial-sum stores ----
    if (STAGE == 0 && (xBlk + n0) >= 1024) {
        const int c0 = xBlk + n0 - 1024;
        const int khead = c0 >> 8;
        const int part  = (c0 >> 6) & 3;
        #pragma unroll
        for (int am = 0; am < 2; am++)
            #pragma unroll
            for (int half = 0; half < 2; half++) {
                float s = sq[am][half];
                s += __shfl_xor_sync(0xFFFFFFFFu, s, 1);
                s += __shfl_xor_sync(0xFFFFFFFFu, s, 2);
                if ((lane & 3) == 0) {
                    const int r_ = yBlk + m0 + am * 16 + (lane >> 2) + half * 8;
                    Cf[((size_t)r_ * 4 + khead) * 4 + part] = s;   // Cf = kn4
                }
            }
    }
    if (STAGE == 2) {
        #pragma unroll
        for (int am = 0; am < 2; am++)
            #pragma unroll
            for (int half = 0; half < 2; half++) {
                float s = sq[am][half];
                s += __shfl_xor_sync(0xFFFFFFFFu, s, 1);
                s += __shfl_xor_sync(0xFFFFFFFFu, s, 2);
                if ((lane & 3) == 0) {
                    const int r_ = yBlk + m0 + am * 16 + (lane >> 2) + half * 8;
                    Cf[((size_t)bz * 2048 + r_) * 32 + bx * 2 + (wid >> 2)] = s;  // Cf = Spart
                }
            }
    }
}

// ---------------- kernels -------------------------------------------------------
// Merged S0 + S3 (independent stages, one launch fills waves together)
__global__ __launch_bounds__(256, 2)
void hgemm03(const fp16* __restrict__ xsa_h, const fp16* __restrict__ xsa_l,
             const fp16* __restrict__ wqk_h, const fp16* __restrict__ wv_h,
             float* __restrict__ kn4, fp16* __restrict__ xqk_h,
             fp16* __restrict__ vp_h, const float* __restrict__ biasW)
{
    extern __shared__ char smem[];
    const int bid = blockIdx.x;
    if (bid < 512) {       // S0: grid 16 x 32
        gemm_body<0>(bid & 15, bid >> 4, 0, smem,
                     xsa_h, xsa_l, wqk_h, kn4, xqk_h, biasW, nullptr);
    } else {               // S3: grid 4 x 16 x 8
        const int b2 = bid - 512;
        gemm_body<3>(b2 & 3, (b2 >> 2) & 15, b2 >> 6, smem,
                     xsa_h, nullptr, wv_h, nullptr, vp_h, nullptr, nullptr);
    }
}

__global__ __launch_bounds__(256, 2)
void hgemm2(const fp16* __restrict__ xqk_h, float* __restrict__ Spart,
            fp16* __restrict__ eH, const float* __restrict__ kn4)
{
    extern __shared__ char smem[];
    gemm_body<2>(blockIdx.x, blockIdx.y, blockIdx.z, smem,
                 xqk_h, nullptr, xqk_h, Spart, eH, nullptr, kn4);
}

__global__ __launch_bounds__(256, 2)
void hgemm4(const fp16* __restrict__ eH, const fp16* __restrict__ vp_h,
            float* __restrict__ out, const float* __restrict__ bias2W,
            const float* __restrict__ Spart)
{
    extern __shared__ char smem[];
    gemm_body<4>(blockIdx.x, blockIdx.y, blockIdx.z, smem,
                 eH, nullptr, vp_h, out, nullptr, bias2W, Spart);
}

// ---------------- fused fp32 -> fp16 split (xsa hi+lo; weights hi only) -------
__global__ void split_all(const float4* __restrict__ xsa, const float4* __restrict__ wq,
                          const float4* __restrict__ wk,  const float4* __restrict__ wv,
                          fp162* __restrict__ xh, fp162* __restrict__ xl,
                          fp162* __restrict__ wqkh, fp162* __restrict__ vh)
{
    int i = blockIdx.x * 256 + threadIdx.x;
    if (i >= 1048576) return;
    if (i < 524288) {
        float4 v = xsa[i];
        fp162 h0, l0, h1, l1;
        split2(v.x, v.y, h0, l0);
        split2(v.z, v.w, h1, l1);
        xh[2 * i] = h0; xh[2 * i + 1] = h1;
        xl[2 * i] = l0; xl[2 * i + 1] = l1;
        return;
    }
    const float4* src;
    fp162* hi;
    int j;
    if (i < 655360)       { src = wq; hi = wqkh;          j = i - 524288; }
    else if (i < 786432)  { src = wk; hi = wqkh + 262144; j = i - 655360; }
    else                  { src = wv; hi = vh;            j = i - 786432; }
    float4 v = src[j];
    hi[2 * j]     = __floats2half2_rn(v.x, v.y);
    hi[2 * j + 1] = __floats2half2_rn(v.z, v.w);
}

// ---------------- launch ------------------------------------------------------
extern "C" void kernel_launch(void* const* d_in, const int* in_sizes, int n_in,
                              void* d_out, int out_size)
{
    const float* xsa    = (const float*)d_in[0];
    const float* Wq     = (const float*)d_in[1];
    const float* Wk     = (const float*)d_in[2];
    const float* Wv     = (const float*)d_in[3];
    const float* biasW  = (const float*)d_in[4];
    const float* bias2W = (const float*)d_in[5];
    float* out = (float*)d_out;

    float *p_kn4, *p_Spart;
    fp16 *xsa_h, *xsa_l, *wqk_h, *wv_h, *xqk_h, *eH, *vp_h;
    cudaGetSymbolAddress((void**)&p_kn4,   g_kn4);
    cudaGetSymbolAddress((void**)&p_Spart, g_Spart);
    cudaGetSymbolAddress((void**)&xsa_h, g_xsa_h);
    cudaGetSymbolAddress((void**)&xsa_l, g_xsa_l);
    cudaGetSymbolAddress((void**)&wqk_h, g_wqk_h);
    cudaGetSymbolAddress((void**)&wv_h,  g_wv_h);
    cudaGetSymbolAddress((void**)&xqk_h, g_xqk_h);
    cudaGetSymbolAddress((void**)&eH,    g_eH);
    cudaGetSymbolAddress((void**)&vp_h,  g_vp_h);

    cudaFuncSetAttribute(hgemm03, cudaFuncAttributeMaxDynamicSharedMemorySize, 98816);
    cudaFuncSetAttribute(hgemm2,  cudaFuncAttributeMaxDynamicSharedMemorySize, 98816);
    cudaFuncSetAttribute(hgemm4,  cudaFuncAttributeMaxDynamicSharedMemorySize, 98816);

    // (1) fused input split
    split_all<<<4096, 256>>>((const float4*)xsa, (const float4*)Wq,
                             (const float4*)Wk,  (const float4*)Wv,
                             (fp162*)xsa_h, (fp162*)xsa_l,
                             (fp162*)wqk_h, (fp162*)wv_h);
    // (2) merged S0 + S3
    hgemm03<<<1024, 256, 98816>>>(xsa_h, xsa_l, wqk_h, wv_h,
                                  p_kn4, xqk_h, vp_h, biasW);
    // (3) S2: eH + Spart (kn folded into prologue)
    hgemm2<<<dim3(16, 16, 8), 256, 98816>>>(xqk_h, p_Spart, eH, p_kn4);
    // (4) S4: out (invS folded into prologue)
    hgemm4<<<dim3(4, 16, 8), 256, 98816>>>(eH, vp_h, out, bias2W, p_Spart);
}

// round 16
// speedup vs baseline: 2.8604x; 1.0304x over previous
#include <cuda_runtime.h>
#include <cuda_fp16.h>
#include <cstdint>

typedef __half fp16;
typedef __half2 fp162;

// ---------------- scratch (device globals) ----------------------------------
__device__ float g_kn4 [4096*4*4];
__device__ float g_Spart[(size_t)16384*32];
__device__ int   g_sync[168];     // [0..31] c0(S0 rowblocks), [32..39] c3(S3 z), [40..167] c2(z*16+y)

__device__ fp16 g_xsa_h[(size_t)4096*512],  g_xsa_l[(size_t)4096*512];
__device__ fp16 g_wqk_h[(size_t)2048*512];
__device__ fp16 g_wv_h [(size_t)512*2048];
__device__ fp16 g_xqk_h[(size_t)4096*2048];
__device__ fp16 g_eH  [(size_t)8*2048*2048];
__device__ fp16 g_vp_h [(size_t)8*2048*512];

// ---------------- helpers ----------------------------------------------------
__device__ __forceinline__ uint32_t smem_u32(const void* p) {
    uint32_t a;
    asm("{ .reg .u64 t; cvta.to.shared.u64 t, %1; cvt.u32.u64 %0, t; }" : "=r"(a) : "l"(p));
    return a;
}
__device__ __forceinline__ void cpa16(uint32_t d, const void* s) {
    asm volatile("cp.async.cg.shared.global [%0], [%1], 16;" :: "r"(d), "l"(s));
}
#define CP_COMMIT() asm volatile("cp.async.commit_group;" ::: "memory")
#define CP_WAIT1()  asm volatile("cp.async.wait_group 1;" ::: "memory")

__device__ __forceinline__ int ldacq(const int* p) {
    int v;
    asm volatile("ld.acquire.gpu.global.s32 %0, [%1];" : "=r"(v) : "l"(p) : "memory");
    return v;
}

__device__ __forceinline__ void ldsm_x4(uint32_t& r0, uint32_t& r1, uint32_t& r2,
                                        uint32_t& r3, uint32_t a) {
    asm volatile("ldmatrix.sync.aligned.m8n8.x4.shared.b16 {%0,%1,%2,%3}, [%4];"
                 : "=r"(r0), "=r"(r1), "=r"(r2), "=r"(r3) : "r"(a));
}
__device__ __forceinline__ void ldsm_x4t(uint32_t& r0, uint32_t& r1, uint32_t& r2,
                                         uint32_t& r3, uint32_t a) {
    asm volatile("ldmatrix.sync.aligned.m8n8.x4.trans.shared.b16 {%0,%1,%2,%3}, [%4];"
                 : "=r"(r0), "=r"(r1), "=r"(r2), "=r"(r3) : "r"(a));
}
__device__ __forceinline__ void mma16816(float c[4], const uint32_t a[4],
                                         const uint32_t bq[2]) {
    asm volatile("mma.sync.aligned.m16n8k16.row.col.f32.f16.f16.f32 "
                 "{%0,%1,%2,%3}, {%4,%5,%6,%7}, {%8,%9}, {%0,%1,%2,%3};"
                 : "+f"(c[0]), "+f"(c[1]), "+f"(c[2]), "+f"(c[3])
                 : "r"(a[0]), "r"(a[1]), "r"(a[2]), "r"(a[3]), "r"(bq[0]), "r"(bq[1]));
}
__device__ __forceinline__ void split2(float a, float b, fp162& h, fp162& l) {
    h = __floats2half2_rn(a, b);
    l = __floats2half2_rn(a - __half2float(__low2half(h)),
                          b - __half2float(__high2half(h)));
}

// ---------------- GEMM body ----------------------------------------------------
// STAGE 0: [xq|xkb] hi = xsa @ [Wq;Wk]^T (+bias), kn4 partials  NT 2-product BK32
// STAGE 2: eH = exp((2*xq.xkb^T - kn)/16 + 14) + Spart          NT 1-product BK64
// STAGE 3: Vp = xsa_h @ Wv3[k]                                  NN 1-product BK64
// STAGE 4: out = (eH @ Vp) * invS + bias2                       NN 1-product BK64
// CTA 128x128, warp 32x64, 3-stage cp.async.

template<int STAGE>
__device__ __forceinline__ void gemm_body(
    int bx, int by, int bz, char* smem,
    const fp16* __restrict__ gAh, const fp16* __restrict__ gAl,
    const fp16* __restrict__ gBh,
    float* __restrict__ Cf, fp16* __restrict__ Ch,
    const float* __restrict__ aux1, const float* __restrict__ aux2)
{
    constexpr bool NT     = (STAGE == 0 || STAGE == 2);
    constexpr bool USE_AL = (STAGE == 0);
    constexpr int  BK  = (STAGE == 0) ? 32 : 64;
    constexpr int  SN  = BK / 16;
    constexpr int  Kd  = (STAGE == 0) ? 512  : (STAGE == 2 ? 256  : (STAGE == 3 ? 512 : 2048));
    constexpr int  ldA = (STAGE == 0) ? 512  : (STAGE == 2 ? 2048 : (STAGE == 3 ? 512 : 2048));
    constexpr int  ldB = (STAGE == 0) ? 512  : (STAGE == 2 ? 2048 : 512);
    constexpr int  NC  = Kd / BK;

    const uint32_t sb = smem_u32(smem);
    const int tid = threadIdx.x;
    const int b = bz >> 2, k = bz & 3;

    const fp16 *Ah = gAh, *Al = gAl, *Bh = gBh;
    size_t coff = 0;
    if (STAGE == 2) {
        size_t o = (size_t)(b * 2048) * 2048 + (size_t)k * 256;
        Ah += o; Bh += o + 1024;
        coff = (size_t)bz * 2048 * 2048;
    } else if (STAGE == 3) {
        Ah += (size_t)(b * 2048) * 512;
        Bh += (size_t)k * 512 * 512;
        coff = (size_t)bz * 2048 * 512;
    } else if (STAGE == 4) {
        Ah += (size_t)bz * 2048 * 2048;
        Bh += (size_t)bz * 2048 * 512;
        coff = (size_t)(b * 2048) * 2048 + (size_t)k * 512;
    }
    const int yBlk = by * 128, xBlk = bx * 128;
    Ah += (size_t)yBlk * ldA;
    if (USE_AL) Al += (size_t)yBlk * ldA;
    if (NT) Bh += (size_t)xBlk * ldB;
    else    Bh += xBlk;
    if (STAGE == 4 && Cf) Cf += coff;
    if (Ch) Ch += coff;

    float* exsm = reinterpret_cast<float*>(smem + 98304);   // 128 floats
    if (STAGE == 2 && tid < 128) {
        float4 v = *reinterpret_cast<const float4*>(
            aux2 + ((size_t)(b * 2048 + xBlk + tid) * 4 + k) * 4);
        exsm[tid] = (v.x + v.y) + (v.z + v.w);
    }
    if (STAGE == 4 && tid < 128) {
        const float* sp = aux2 + ((size_t)bz * 2048 + yBlk + tid) * 32;
        float s = 0.f;
        #pragma unroll
        for (int i = 0; i < 32; i += 4) {
            float4 v = *reinterpret_cast<const float4*>(sp + i);
            s += (v.x + v.y) + (v.z + v.w);
        }
        exsm[tid] = 1.f / s;
    }

    const int wid = tid >> 5, lane = tid & 31;
    const int m0 = (wid & 3) * 32, n0 = (wid >> 2) * 64;

    float acc[2][8][4];
    #pragma unroll
    for (int am = 0; am < 2; am++)
        #pragma unroll
        for (int j = 0; j < 8; j++)
            #pragma unroll
            for (int q = 0; q < 4; q++) acc[am][j][q] = 0.f;

    auto load_chunk = [&](int c, int buf) {
        uint32_t s0 = sb + buf * 32768;
        if (BK == 64) {
            #pragma unroll
            for (int h = 0; h < 4; h++) {
                int s = tid + h * 256;
                int r = s >> 3, q = s & 7;
                uint32_t d = s0 + r * 128 + ((q ^ (r & 7)) << 4);
                cpa16(d, Ah + (size_t)r * ldA + c * 64 + q * 8);
            }
            if (NT) {
                #pragma unroll
                for (int h = 0; h < 4; h++) {
                    int s = tid + h * 256;
                    int r = s >> 3, q = s & 7;
                    uint32_t d = s0 + 16384 + r * 128 + ((q ^ (r & 7)) << 4);
                    cpa16(d, Bh + (size_t)r * ldB + c * 64 + q * 8);
                }
            } else {
                #pragma unroll
                for (int h = 0; h < 4; h++) {
                    int s = tid + h * 256;
                    int kk = s >> 4, q = s & 15;
                    uint32_t d = s0 + 16384 + kk * 256 + ((q ^ (kk & 7)) << 4);
                    cpa16(d, Bh + (size_t)(c * 64 + kk) * ldB + q * 8);
                }
            }
            return;
        }
        // STAGE 0: BK32, A hi+lo, B hi
        #pragma unroll
        for (int h = 0; h < 2; h++) {
            int s = tid + h * 256;
            int r = s >> 2, q = s & 3;
            uint32_t d = s0 + r * 64 + ((q ^ ((r >> 1) & 3)) << 4);
            cpa16(d,        Ah + (size_t)r * ldA + c * 32 + q * 8);
            cpa16(d + 8192, Al + (size_t)r * ldA + c * 32 + q * 8);
        }
        #pragma unroll
        for (int h = 0; h < 2; h++) {
            int s = tid + h * 256;
            int r = s >> 2, q = s & 3;
            uint32_t d = s0 + 16384 + r * 64 + ((q ^ ((r >> 1) & 3)) << 4);
            cpa16(d, Bh + (size_t)r * ldB + c * 32 + q * 8);
        }
    };

    load_chunk(0, 0); CP_COMMIT();
    load_chunk(1, 1); CP_COMMIT();

    #pragma unroll 1
    for (int c = 0; c < NC; c++) {
        CP_WAIT1();
        __syncthreads();
        if (c + 2 < NC) load_chunk(c + 2, (c + 2) % 3);
        CP_COMMIT();

        const uint32_t s0 = sb + (c % 3) * 32768;
        #pragma unroll
        for (int s = 0; s < SN; s++) {
            uint32_t ah[2][4], al[2][4];
            #pragma unroll
            for (int am = 0; am < 2; am++) {
                int row = m0 + am * 16 + (lane & 15);
                int q = s * 2 + (lane >> 4);
                uint32_t addr;
                if (BK == 64)
                    addr = s0 + row * 128 + ((q ^ (row & 7)) << 4);
                else
                    addr = s0 + row * 64 + ((q ^ ((row >> 1) & 3)) << 4);
                ldsm_x4(ah[am][0], ah[am][1], ah[am][2], ah[am][3], addr);
                if (USE_AL)
                    ldsm_x4(al[am][0], al[am][1], al[am][2], al[am][3], addr + 8192);
            }
            #pragma unroll
            for (int bp = 0; bp < 2; bp++) {
                uint32_t bh[4][2];
                if (NT) {
                    #pragma unroll
                    for (int i = 0; i < 2; i++) {
                        int bn = 2 * bp + i;
                        int row = n0 + bn * 16 + (lane & 15);
                        int q = s * 2 + (lane >> 4);
                        uint32_t addr;
                        if (BK == 64)
                            addr = s0 + 16384 + row * 128 + ((q ^ (row & 7)) << 4);
                        else
                            addr = s0 + 16384 + row * 64 + ((q ^ ((row >> 1) & 3)) << 4);
                        uint32_t r0, r1, r2, r3;
                        ldsm_x4(r0, r1, r2, r3, addr);
                        bh[2*i][0] = r0; bh[2*i][1] = r2;
                        bh[2*i+1][0] = r1; bh[2*i+1][1] = r3;
                    }
                } else {
                    #pragma unroll
                    for (int i = 0; i < 2; i++) {
                        int bn = 2 * bp + i;
                        int g = lane >> 3;
                        int kk = s * 16 + (g & 1) * 8 + (lane & 7);
                        int q = (n0 + bn * 16) / 8 + (g >> 1);
                        uint32_t addr = s0 + 16384 + kk * 256 + ((q ^ (kk & 7)) << 4);
                        uint32_t r0, r1, r2, r3;
                        ldsm_x4t(r0, r1, r2, r3, addr);
                        bh[2*i][0] = r0; bh[2*i][1] = r1;
                        bh[2*i+1][0] = r2; bh[2*i+1][1] = r3;
                    }
                }
                #pragma unroll
                for (int am = 0; am < 2; am++)
                    #pragma unroll
                    for (int jj = 0; jj < 4; jj++)
                        mma16816(acc[am][4*bp+jj], ah[am], bh[jj]);
                if (USE_AL) {
                    #pragma unroll
                    for (int am = 0; am < 2; am++)
                        #pragma unroll
                        for (int jj = 0; jj < 4; jj++)
                            mma16816(acc[am][4*bp+jj], al[am], bh[jj]);
                }
            }
        }
    }

    // ---- epilogue ----
    float sq[2][2] = {{0.f, 0.f}, {0.f, 0.f}};
    #pragma unroll
    for (int am = 0; am < 2; am++) {
        const int gi0 = yBlk + m0 + am * 16 + (lane >> 2);
        #pragma unroll
        for (int j = 0; j < 8; j++) {
            const int gj = xBlk + n0 + j * 8 + (lane & 3) * 2;
            #pragma unroll
            for (int half = 0; half < 2; half++) {
                const int gi = gi0 + half * 8;
                float v0 = acc[am][j][half * 2 + 0];
                float v1 = acc[am][j][half * 2 + 1];
                if (STAGE == 0) {
                    const size_t idx = (size_t)gi * 2048 + gj;
                    if (gj >= 1024) {
                        const int c0 = gj - 1024;
                        v0 += aux1[((c0 + 0) & 255) * 4 + ((c0 + 0) >> 8)];
                        v1 += aux1[((c0 + 1) & 255) * 4 + ((c0 + 1) >> 8)];
                        sq[am][half] += v0 * v0 + v1 * v1;
                    }
                    *reinterpret_cast<fp162*>(Ch + idx) = __floats2half2_rn(v0, v1);
                } else if (STAGE == 2) {
                    const size_t idx = (size_t)gi * 2048 + gj;
                    const float kn0 = exsm[gj - xBlk];
                    const float kn1 = exsm[gj - xBlk + 1];
                    float t0 = fminf((2.f * v0 - kn0) * 0.0625f + 14.f, 11.f);
                    float t1 = fminf((2.f * v1 - kn1) * 0.0625f + 14.f, 11.f);
                    float e0 = __expf(t0), e1 = __expf(t1);
                    sq[am][half] += e0 + e1;
                    *reinterpret_cast<fp162*>(Ch + idx) = __floats2half2_rn(e0, e1);
                } else if (STAGE == 3) {
                    const size_t idx = (size_t)gi * 512 + gj;
                    *reinterpret_cast<fp162*>(Ch + idx) = __floats2half2_rn(v0, v1);
                } else { // STAGE 4
                    const size_t idx = (size_t)gi * 2048 + gj;
                    const float is0 = exsm[gi - yBlk];
                    v0 = v0 * is0 + aux1[(gj + 0) * 4 + k];
                    v1 = v1 * is0 + aux1[(gj + 1) * 4 + k];
                    *reinterpret_cast<float2*>(Cf + idx) = make_float2(v0, v1);
                }
            }
        }
    }
    // ---- deterministic partial-sum stores ----
    if (STAGE == 0 && (xBlk + n0) >= 1024) {
        const int c0 = xBlk + n0 - 1024;
        const int khead = c0 >> 8;
        const int part  = (c0 >> 6) & 3;
        #pragma unroll
        for (int am = 0; am < 2; am++)
            #pragma unroll
            for (int half = 0; half < 2; half++) {
                float s = sq[am][half];
                s += __shfl_xor_sync(0xFFFFFFFFu, s, 1);
                s += __shfl_xor_sync(0xFFFFFFFFu, s, 2);
                if ((lane & 3) == 0) {
                    const int r_ = yBlk + m0 + am * 16 + (lane >> 2) + half * 8;
                    Cf[((size_t)r_ * 4 + khead) * 4 + part] = s;   // Cf = kn4
                }
            }
    }
    if (STAGE == 2) {
        #pragma unroll
        for (int am = 0; am < 2; am++)
            #pragma unroll
            for (int half = 0; half < 2; half++) {
                float s = sq[am][half];
                s += __shfl_xor_sync(0xFFFFFFFFu, s, 1);
                s += __shfl_xor_sync(0xFFFFFFFFu, s, 2);
                if ((lane & 3) == 0) {
                    const int r_ = yBlk + m0 + am * 16 + (lane >> 2) + half * 8;
                    Cf[((size_t)bz * 2048 + r_) * 32 + bx * 2 + (wid >> 2)] = s;  // Cf = Spart
                }
            }
    }
}

// ---------------- fully merged pipeline kernel ---------------------------------
// bids: [0,512) S0 | [512,1024) S3 | [1024,3072) S2 | [3072,3584) S4
// deps enforced via arrival counters; deadlock-free by bid-ordered dispatch
// (every waiter's producers have smaller bids).
__global__ __launch_bounds__(256, 2)
void hgemm_all(const fp16* __restrict__ xsa_h, const fp16* __restrict__ xsa_l,
               const fp16* __restrict__ wqk_h, const fp16* __restrict__ wv_h,
               float* __restrict__ kn4, fp16* __restrict__ xqk_h,
               fp16* __restrict__ vp_h, const float* __restrict__ biasW,
               float* __restrict__ Spart, fp16* __restrict__ eH,
               float* __restrict__ out, const float* __restrict__ bias2W)
{
    extern __shared__ char smem[];
    const int bid = blockIdx.x;
    const int tid = threadIdx.x;
    if (bid < 512) {
        int x = bid & 15, y = bid >> 4;
        gemm_body<0>(x, y, 0, smem, xsa_h, xsa_l, wqk_h, kn4, xqk_h, biasW, nullptr);
        __threadfence();
        __syncthreads();
        if (tid == 0) atomicAdd(&g_sync[y], 1);
    } else if (bid < 1024) {
        int t = bid - 512, x = t & 3, y = (t >> 2) & 15, z = t >> 6;
        gemm_body<3>(x, y, z, smem, xsa_h, nullptr, wv_h, nullptr, vp_h, nullptr, nullptr);
        __threadfence();
        __syncthreads();
        if (tid == 0) atomicAdd(&g_sync[32 + z], 1);
    } else if (bid < 3072) {
        int t = bid - 1024, x = t & 15, y = (t >> 4) & 15, z = t >> 8;
        int b = z >> 2;
        if (tid == 0) {
            while (ldacq(&g_sync[b * 16 + y]) < 16) __nanosleep(100);
            while (ldacq(&g_sync[b * 16 + x]) < 16) __nanosleep(100);
        }
        __syncthreads();
        gemm_body<2>(x, y, z, smem, xqk_h, nullptr, xqk_h, Spart, eH, nullptr, kn4);
        __threadfence();
        __syncthreads();
        if (tid == 0) atomicAdd(&g_sync[40 + z * 16 + y], 1);
    } else {
        int t = bid - 3072, x = t & 3, y = (t >> 2) & 15, z = t >> 6;
        if (tid == 0) {
            while (ldacq(&g_sync[40 + z * 16 + y]) < 16) __nanosleep(100);
            while (ldacq(&g_sync[32 + z]) < 64) __nanosleep(100);
        }
        __syncthreads();
        gemm_body<4>(x, y, z, smem, eH, nullptr, vp_h, out, nullptr, bias2W, Spart);
    }
}

// ---------------- fused fp32 -> fp16 split + sync-counter reset ---------------
__global__ void split_all(const float4* __restrict__ xsa, const float4* __restrict__ wq,
                          const float4* __restrict__ wk,  const float4* __restrict__ wv,
                          fp162* __restrict__ xh, fp162* __restrict__ xl,
                          fp162* __restrict__ wqkh, fp162* __restrict__ vh)
{
    if (blockIdx.x == 0 && threadIdx.x < 168) g_sync[threadIdx.x] = 0;
    int i = blockIdx.x * 256 + threadIdx.x;
    if (i >= 1048576) return;
    if (i < 524288) {
        float4 v = xsa[i];
        fp162 h0, l0, h1, l1;
        split2(v.x, v.y, h0, l0);
        split2(v.z, v.w, h1, l1);
        xh[2 * i] = h0; xh[2 * i + 1] = h1;
        xl[2 * i] = l0; xl[2 * i + 1] = l1;
        return;
    }
    const float4* src;
    fp162* hi;
    int j;
    if (i < 655360)       { src = wq; hi = wqkh;          j = i - 524288; }
    else if (i < 786432)  { src = wk; hi = wqkh + 262144; j = i - 655360; }
    else                  { src = wv; hi = vh;            j = i - 786432; }
    float4 v = src[j];
    hi[2 * j]     = __floats2half2_rn(v.x, v.y);
    hi[2 * j + 1] = __floats2half2_rn(v.z, v.w);
}

// ---------------- launch ------------------------------------------------------
extern "C" void kernel_launch(void* const* d_in, const int* in_sizes, int n_in,
                              void* d_out, int out_size)
{
    const float* xsa    = (const float*)d_in[0];
    const float* Wq     = (const float*)d_in[1];
    const float* Wk     = (const float*)d_in[2];
    const float* Wv     = (const float*)d_in[3];
    const float* biasW  = (const float*)d_in[4];
    const float* bias2W = (const float*)d_in[5];
    float* out = (float*)d_out;

    float *p_kn4, *p_Spart;
    fp16 *xsa_h, *xsa_l, *wqk_h, *wv_h, *xqk_h, *eH, *vp_h;
    cudaGetSymbolAddress((void**)&p_kn4,   g_kn4);
    cudaGetSymbolAddress((void**)&p_Spart, g_Spart);
    cudaGetSymbolAddress((void**)&xsa_h, g_xsa_h);
    cudaGetSymbolAddress((void**)&xsa_l, g_xsa_l);
    cudaGetSymbolAddress((void**)&wqk_h, g_wqk_h);
    cudaGetSymbolAddress((void**)&wv_h,  g_wv_h);
    cudaGetSymbolAddress((void**)&xqk_h, g_xqk_h);
    cudaGetSymbolAddress((void**)&eH,    g_eH);
    cudaGetSymbolAddress((void**)&vp_h,  g_vp_h);

    cudaFuncSetAttribute(hgemm_all, cudaFuncAttributeMaxDynamicSharedMemorySize, 98816);

    // (1) fused input split + counter reset
    split_all<<<4096, 256>>>((const float4*)xsa, (const float4*)Wq,
                             (const float4*)Wk,  (const float4*)Wv,
                             (fp162*)xsa_h, (fp162*)xsa_l,
                             (fp162*)wqk_h, (fp162*)wv_h);
    // (2) entire GEMM pipeline in one launch (S0+S3 -> S2 -> S4 via spin-waits)
    hgemm_all<<<3584, 256, 98816>>>(xsa_h, xsa_l, wqk_h, wv_h,
                                    p_kn4, xqk_h, vp_h, biasW,
                                    p_Spart, eH, out, bias2W);
}

// round 17
// speedup vs baseline: 2.9033x; 1.0150x over previous
#include <cuda_runtime.h>
#include <cuda_fp16.h>
#include <cstdint>

typedef __half fp16;
typedef __half2 fp162;

// ---------------- scratch (device globals) ----------------------------------
__device__ float g_kn4 [4096*4*4];
__device__ float g_Spart[(size_t)16384*32];
__device__ int   g_sync[168];     // [0..31] c0(S0 rowblocks), [32..39] c3(S3 z), [40..167] c2(z*16+y)

__device__ fp16 g_xsa_h[(size_t)4096*512],  g_xsa_l[(size_t)4096*512];
__device__ fp16 g_wqk_h[(size_t)2048*512];
__device__ fp16 g_wv_h [(size_t)512*2048];
__device__ fp16 g_xqk_h[(size_t)4096*2048];
__device__ fp16 g_eH  [(size_t)8*2048*2048];
__device__ fp16 g_vp_h [(size_t)8*2048*512];

// ---------------- helpers ----------------------------------------------------
__device__ __forceinline__ uint32_t smem_u32(const void* p) {
    uint32_t a;
    asm("{ .reg .u64 t; cvta.to.shared.u64 t, %1; cvt.u32.u64 %0, t; }" : "=r"(a) : "l"(p));
    return a;
}
__device__ __forceinline__ void cpa16(uint32_t d, const void* s) {
    asm volatile("cp.async.cg.shared.global [%0], [%1], 16;" :: "r"(d), "l"(s));
}
#define CP_COMMIT() asm volatile("cp.async.commit_group;" ::: "memory")

__device__ __forceinline__ int ldacq(const int* p) {
    int v;
    asm volatile("ld.acquire.gpu.global.s32 %0, [%1];" : "=r"(v) : "l"(p) : "memory");
    return v;
}

__device__ __forceinline__ void ldsm_x4(uint32_t& r0, uint32_t& r1, uint32_t& r2,
                                        uint32_t& r3, uint32_t a) {
    asm volatile("ldmatrix.sync.aligned.m8n8.x4.shared.b16 {%0,%1,%2,%3}, [%4];"
                 : "=r"(r0), "=r"(r1), "=r"(r2), "=r"(r3) : "r"(a));
}
__device__ __forceinline__ void ldsm_x4t(uint32_t& r0, uint32_t& r1, uint32_t& r2,
                                         uint32_t& r3, uint32_t a) {
    asm volatile("ldmatrix.sync.aligned.m8n8.x4.trans.shared.b16 {%0,%1,%2,%3}, [%4];"
                 : "=r"(r0), "=r"(r1), "=r"(r2), "=r"(r3) : "r"(a));
}
__device__ __forceinline__ void mma16816(float c[4], const uint32_t a[4],
                                         const uint32_t bq[2]) {
    asm volatile("mma.sync.aligned.m16n8k16.row.col.f32.f16.f16.f32 "
                 "{%0,%1,%2,%3}, {%4,%5,%6,%7}, {%8,%9}, {%0,%1,%2,%3};"
                 : "+f"(c[0]), "+f"(c[1]), "+f"(c[2]), "+f"(c[3])
                 : "r"(a[0]), "r"(a[1]), "r"(a[2]), "r"(a[3]), "r"(bq[0]), "r"(bq[1]));
}
__device__ __forceinline__ void split2(float a, float b, fp162& h, fp162& l) {
    h = __floats2half2_rn(a, b);
    l = __floats2half2_rn(a - __half2float(__low2half(h)),
                          b - __half2float(__high2half(h)));
}

// ---------------- GEMM body ----------------------------------------------------
// STAGE 0: [xq|xkb] hi = xsa @ [Wq;Wk]^T (+bias), kn4 partials  NT 2-product BK32 depth4
// STAGE 2: eH = exp((2*xq.xkb^T - kn)/16 + 14) + Spart          NT 1-product BK64 depth3
// STAGE 3: Vp = xsa_h @ Wv3[k]                                  NN 1-product BK64 depth3
// STAGE 4: out = (eH @ Vp) * invS + bias2                       NN 1-product BK64 depth3
// CTA 128x128, warp 32x64.

template<int STAGE>
__device__ __forceinline__ void gemm_body(
    int bx, int by, int bz, char* smem,
    const fp16* __restrict__ gAh, const fp16* __restrict__ gAl,
    const fp16* __restrict__ gBh,
    float* __restrict__ Cf, fp16* __restrict__ Ch,
    const float* __restrict__ aux1, const float* __restrict__ aux2)
{
    constexpr bool NT     = (STAGE == 0 || STAGE == 2);
    constexpr bool USE_AL = (STAGE == 0);
    constexpr int  BK    = (STAGE == 0) ? 32 : 64;
    constexpr int  SN    = BK / 16;
    constexpr int  DEPTH = (STAGE == 0) ? 4 : 3;
    constexpr int  BUFB  = (STAGE == 0) ? 24576 : 32768;
    constexpr int  Kd  = (STAGE == 0) ? 512  : (STAGE == 2 ? 256  : (STAGE == 3 ? 512 : 2048));
    constexpr int  ldA = (STAGE == 0) ? 512  : (STAGE == 2 ? 2048 : (STAGE == 3 ? 512 : 2048));
    constexpr int  ldB = (STAGE == 0) ? 512  : (STAGE == 2 ? 2048 : 512);
    constexpr int  NC  = Kd / BK;

    const uint32_t sb = smem_u32(smem);
    const int tid = threadIdx.x;
    const int b = bz >> 2, k = bz & 3;

    const fp16 *Ah = gAh, *Al = gAl, *Bh = gBh;
    size_t coff = 0;
    if (STAGE == 2) {
        size_t o = (size_t)(b * 2048) * 2048 + (size_t)k * 256;
        Ah += o; Bh += o + 1024;
        coff = (size_t)bz * 2048 * 2048;
    } else if (STAGE == 3) {
        Ah += (size_t)(b * 2048) * 512;
        Bh += (size_t)k * 512 * 512;
        coff = (size_t)bz * 2048 * 512;
    } else if (STAGE == 4) {
        Ah += (size_t)bz * 2048 * 2048;
        Bh += (size_t)bz * 2048 * 512;
        coff = (size_t)(b * 2048) * 2048 + (size_t)k * 512;
    }
    const int yBlk = by * 128, xBlk = bx * 128;
    Ah += (size_t)yBlk * ldA;
    if (USE_AL) Al += (size_t)yBlk * ldA;
    if (NT) Bh += (size_t)xBlk * ldB;
    else    Bh += xBlk;
    if (STAGE == 4 && Cf) Cf += coff;
    if (Ch) Ch += coff;

    const int wid = tid >> 5, lane = tid & 31;
    const int m0 = (wid & 3) * 32, n0 = (wid >> 2) * 64;

    float acc[2][8][4];
    #pragma unroll
    for (int am = 0; am < 2; am++)
        #pragma unroll
        for (int j = 0; j < 8; j++)
            #pragma unroll
            for (int q = 0; q < 4; q++) acc[am][j][q] = 0.f;

    auto load_chunk = [&](int c, int buf) {
        uint32_t s0 = sb + buf * BUFB;
        if (BK == 64) {
            #pragma unroll
            for (int h = 0; h < 4; h++) {
                int s = tid + h * 256;
                int r = s >> 3, q = s & 7;
                uint32_t d = s0 + r * 128 + ((q ^ (r & 7)) << 4);
                cpa16(d, Ah + (size_t)r * ldA + c * 64 + q * 8);
            }
            if (NT) {
                #pragma unroll
                for (int h = 0; h < 4; h++) {
                    int s = tid + h * 256;
                    int r = s >> 3, q = s & 7;
                    uint32_t d = s0 + 16384 + r * 128 + ((q ^ (r & 7)) << 4);
                    cpa16(d, Bh + (size_t)r * ldB + c * 64 + q * 8);
                }
            } else {
                #pragma unroll
                for (int h = 0; h < 4; h++) {
                    int s = tid + h * 256;
                    int kk = s >> 4, q = s & 15;
                    uint32_t d = s0 + 16384 + kk * 256 + ((q ^ (kk & 7)) << 4);
                    cpa16(d, Bh + (size_t)(c * 64 + kk) * ldB + q * 8);
                }
            }
            return;
        }
        // STAGE 0: BK32, A hi+lo, B hi
        #pragma unroll
        for (int h = 0; h < 2; h++) {
            int s = tid + h * 256;
            int r = s >> 2, q = s & 3;
            uint32_t d = s0 + r * 64 + ((q ^ ((r >> 1) & 3)) << 4);
            cpa16(d,        Ah + (size_t)r * ldA + c * 32 + q * 8);
            cpa16(d + 8192, Al + (size_t)r * ldA + c * 32 + q * 8);
        }
        #pragma unroll
        for (int h = 0; h < 2; h++) {
            int s = tid + h * 256;
            int r = s >> 2, q = s & 3;
            uint32_t d = s0 + 16384 + r * 64 + ((q ^ ((r >> 1) & 3)) << 4);
            cpa16(d, Bh + (size_t)r * ldB + c * 32 + q * 8);
        }
    };

    // prologue: fill DEPTH-1 buffers first so exsm latency hides behind them
    #pragma unroll
    for (int i = 0; i < DEPTH - 1; i++) { load_chunk(i, i); CP_COMMIT(); }

    float* exsm = reinterpret_cast<float*>(smem + 98304);   // 128 floats
    if (STAGE == 2 && tid < 128) {
        float4 v = *reinterpret_cast<const float4*>(
            aux2 + ((size_t)(b * 2048 + xBlk + tid) * 4 + k) * 4);
        exsm[tid] = (v.x + v.y) + (v.z + v.w);
    }
    if (STAGE == 4 && tid < 128) {
        const float* sp = aux2 + ((size_t)bz * 2048 + yBlk + tid) * 32;
        float s = 0.f;
        #pragma unroll
        for (int i = 0; i < 32; i += 4) {
            float4 v = *reinterpret_cast<const float4*>(sp + i);
            s += (v.x + v.y) + (v.z + v.w);
        }
        exsm[tid] = 1.f / s;
    }

    #pragma unroll 1
    for (int c = 0; c < NC; c++) {
        if (DEPTH == 4) asm volatile("cp.async.wait_group 2;" ::: "memory");
        else            asm volatile("cp.async.wait_group 1;" ::: "memory");
        __syncthreads();
        if (c + DEPTH - 1 < NC) load_chunk(c + DEPTH - 1, (c + DEPTH - 1) % DEPTH);
        CP_COMMIT();

        const uint32_t s0 = sb + (c % DEPTH) * BUFB;
        #pragma unroll
        for (int s = 0; s < SN; s++) {
            uint32_t ah[2][4], al[2][4];
            #pragma unroll
            for (int am = 0; am < 2; am++) {
                int row = m0 + am * 16 + (lane & 15);
                int q = s * 2 + (lane >> 4);
                uint32_t addr;
                if (BK == 64)
                    addr = s0 + row * 128 + ((q ^ (row & 7)) << 4);
                else
                    addr = s0 + row * 64 + ((q ^ ((row >> 1) & 3)) << 4);
                ldsm_x4(ah[am][0], ah[am][1], ah[am][2], ah[am][3], addr);
                if (USE_AL)
                    ldsm_x4(al[am][0], al[am][1], al[am][2], al[am][3], addr + 8192);
            }
            #pragma unroll
            for (int bp = 0; bp < 2; bp++) {
                uint32_t bh[4][2];
                if (NT) {
                    #pragma unroll
                    for (int i = 0; i < 2; i++) {
                        int bn = 2 * bp + i;
                        int row = n0 + bn * 16 + (lane & 15);
                        int q = s * 2 + (lane >> 4);
                        uint32_t addr;
                        if (BK == 64)
                            addr = s0 + 16384 + row * 128 + ((q ^ (row & 7)) << 4);
                        else
                            addr = s0 + 16384 + row * 64 + ((q ^ ((row >> 1) & 3)) << 4);
                        uint32_t r0, r1, r2, r3;
                        ldsm_x4(r0, r1, r2, r3, addr);
                        bh[2*i][0] = r0; bh[2*i][1] = r2;
                        bh[2*i+1][0] = r1; bh[2*i+1][1] = r3;
                    }
                } else {
                    #pragma unroll
                    for (int i = 0; i < 2; i++) {
                        int bn = 2 * bp + i;
                        int g = lane >> 3;
                        int kk = s * 16 + (g & 1) * 8 + (lane & 7);
                        int q = (n0 + bn * 16) / 8 + (g >> 1);
                        uint32_t addr = s0 + 16384 + kk * 256 + ((q ^ (kk & 7)) << 4);
                        uint32_t r0, r1, r2, r3;
                        ldsm_x4t(r0, r1, r2, r3, addr);
                        bh[2*i][0] = r0; bh[2*i][1] = r1;
                        bh[2*i+1][0] = r2; bh[2*i+1][1] = r3;
                    }
                }
                #pragma unroll
                for (int am = 0; am < 2; am++)
                    #pragma unroll
                    for (int jj = 0; jj < 4; jj++)
                        mma16816(acc[am][4*bp+jj], ah[am], bh[jj]);
                if (USE_AL) {
                    #pragma unroll
                    for (int am = 0; am < 2; am++)
                        #pragma unroll
                        for (int jj = 0; jj < 4; jj++)
                            mma16816(acc[am][4*bp+jj], al[am], bh[jj]);
                }
            }
        }
    }

    // ---- epilogue ----
    float sq[2][2] = {{0.f, 0.f}, {0.f, 0.f}};
    #pragma unroll
    for (int am = 0; am < 2; am++) {
        const int gi0 = yBlk + m0 + am * 16 + (lane >> 2);
        #pragma unroll
        for (int j = 0; j < 8; j++) {
            const int gj = xBlk + n0 + j * 8 + (lane & 3) * 2;
            #pragma unroll
            for (int half = 0; half < 2; half++) {
                const int gi = gi0 + half * 8;
                float v0 = acc[am][j][half * 2 + 0];
                float v1 = acc[am][j][half * 2 + 1];
                if (STAGE == 0) {
                    const size_t idx = (size_t)gi * 2048 + gj;
                    if (gj >= 1024) {
                        const int c0 = gj - 1024;
                        v0 += aux1[((c0 + 0) & 255) * 4 + ((c0 + 0) >> 8)];
                        v1 += aux1[((c0 + 1) & 255) * 4 + ((c0 + 1) >> 8)];
                        sq[am][half] += v0 * v0 + v1 * v1;
                    }
                    *reinterpret_cast<fp162*>(Ch + idx) = __floats2half2_rn(v0, v1);
                } else if (STAGE == 2) {
                    const size_t idx = (size_t)gi * 2048 + gj;
                    const float kn0 = exsm[gj - xBlk];
                    const float kn1 = exsm[gj - xBlk + 1];
                    float t0 = fminf((2.f * v0 - kn0) * 0.0625f + 14.f, 11.f);
                    float t1 = fminf((2.f * v1 - kn1) * 0.0625f + 14.f, 11.f);
                    float e0 = __expf(t0), e1 = __expf(t1);
                    sq[am][half] += e0 + e1;
                    *reinterpret_cast<fp162*>(Ch + idx) = __floats2half2_rn(e0, e1);
                } else if (STAGE == 3) {
                    const size_t idx = (size_t)gi * 512 + gj;
                    *reinterpret_cast<fp162*>(Ch + idx) = __floats2half2_rn(v0, v1);
                } else { // STAGE 4
                    const size_t idx = (size_t)gi * 2048 + gj;
                    const float is0 = exsm[gi - yBlk];
                    v0 = v0 * is0 + aux1[(gj + 0) * 4 + k];
                    v1 = v1 * is0 + aux1[(gj + 1) * 4 + k];
                    *reinterpret_cast<float2*>(Cf + idx) = make_float2(v0, v1);
                }
            }
        }
    }
    // ---- deterministic partial-sum stores ----
    if (STAGE == 0 && (xBlk + n0) >= 1024) {
        const int c0 = xBlk + n0 - 1024;
        const int khead = c0 >> 8;
        const int part  = (c0 >> 6) & 3;
        #pragma unroll
        for (int am = 0; am < 2; am++)
            #pragma unroll
            for (int half = 0; half < 2; half++) {
                float s = sq[am][half];
                s += __shfl_xor_sync(0xFFFFFFFFu, s, 1);
                s += __shfl_xor_sync(0xFFFFFFFFu, s, 2);
                if ((lane & 3) == 0) {
                    const int r_ = yBlk + m0 + am * 16 + (lane >> 2) + half * 8;
                    Cf[((size_t)r_ * 4 + khead) * 4 + part] = s;   // Cf = kn4
                }
            }
    }
    if (STAGE == 2) {
        #pragma unroll
        for (int am = 0; am < 2; am++)
            #pragma unroll
            for (int half = 0; half < 2; half++) {
                float s = sq[am][half];
                s += __shfl_xor_sync(0xFFFFFFFFu, s, 1);
                s += __shfl_xor_sync(0xFFFFFFFFu, s, 2);
                if ((lane & 3) == 0) {
                    const int r_ = yBlk + m0 + am * 16 + (lane >> 2) + half * 8;
                    Cf[((size_t)bz * 2048 + r_) * 32 + bx * 2 + (wid >> 2)] = s;  // Cf = Spart
                }
            }
    }
}

// ---------------- fully merged pipeline kernel ---------------------------------
// bids: [0,512) S0 | [512,1024) S3 | [1024,3072) S2 | [3072,3584) S4
__global__ __launch_bounds__(256, 2)
void hgemm_all(const fp16* __restrict__ xsa_h, const fp16* __restrict__ xsa_l,
               const fp16* __restrict__ wqk_h, const fp16* __restrict__ wv_h,
               float* __restrict__ kn4, fp16* __restrict__ xqk_h,
               fp16* __restrict__ vp_h, const float* __restrict__ biasW,
               float* __restrict__ Spart, fp16* __restrict__ eH,
               float* __restrict__ out, const float* __restrict__ bias2W)
{
    extern __shared__ char smem[];
    const int bid = blockIdx.x;
    const int tid = threadIdx.x;
    if (bid < 512) {
        int x = bid & 15, y = bid >> 4;
        gemm_body<0>(x, y, 0, smem, xsa_h, xsa_l, wqk_h, kn4, xqk_h, biasW, nullptr);
        __threadfence();
        __syncthreads();
        if (tid == 0) atomicAdd(&g_sync[y], 1);
    } else if (bid < 1024) {
        int t = bid - 512, x = t & 3, y = (t >> 2) & 15, z = t >> 6;
        gemm_body<3>(x, y, z, smem, xsa_h, nullptr, wv_h, nullptr, vp_h, nullptr, nullptr);
        __threadfence();
        __syncthreads();
        if (tid == 0) atomicAdd(&g_sync[32 + z], 1);
    } else if (bid < 3072) {
        int t = bid - 1024, x = t & 15, y = (t >> 4) & 15, z = t >> 8;
        int b = z >> 2;
        if (tid == 0)  while (ldacq(&g_sync[b * 16 + y]) < 16) __nanosleep(64);
        if (tid == 32) while (ldacq(&g_sync[b * 16 + x]) < 16) __nanosleep(64);
        __syncthreads();
        gemm_body<2>(x, y, z, smem, xqk_h, nullptr, xqk_h, Spart, eH, nullptr, kn4);
        __threadfence();
        __syncthreads();
        if (tid == 0) atomicAdd(&g_sync[40 + z * 16 + y], 1);
    } else {
        int t = bid - 3072, x = t & 3, y = (t >> 2) & 15, z = t >> 6;
        if (tid == 0)  while (ldacq(&g_sync[40 + z * 16 + y]) < 16) __nanosleep(64);
        if (tid == 32) while (ldacq(&g_sync[32 + z]) < 64) __nanosleep(64);
        __syncthreads();
        gemm_body<4>(x, y, z, smem, eH, nullptr, vp_h, out, nullptr, bias2W, Spart);
    }
}

// ---------------- fused fp32 -> fp16 split + sync-counter reset ---------------
__global__ void split_all(const float4* __restrict__ xsa, const float4* __restrict__ wq,
                          const float4* __restrict__ wk,  const float4* __restrict__ wv,
                          fp162* __restrict__ xh, fp162* __restrict__ xl,
                          fp162* __restrict__ wqkh, fp162* __restrict__ vh)
{
    if (blockIdx.x == 0 && threadIdx.x < 168) g_sync[threadIdx.x] = 0;
    int i = blockIdx.x * 256 + threadIdx.x;
    if (i >= 1048576) return;
    if (i < 524288) {
        float4 v = xsa[i];
        fp162 h0, l0, h1, l1;
        split2(v.x, v.y, h0, l0);
        split2(v.z, v.w, h1, l1);
        xh[2 * i] = h0; xh[2 * i + 1] = h1;
        xl[2 * i] = l0; xl[2 * i + 1] = l1;
        return;
    }
    const float4* src;
    fp162* hi;
    int j;
    if (i < 655360)       { src = wq; hi = wqkh;          j = i - 524288; }
    else if (i < 786432)  { src = wk; hi = wqkh + 262144; j = i - 655360; }
    else                  { src = wv; hi = vh;            j = i - 786432; }
    float4 v = src[j];
    hi[2 * j]     = __floats2half2_rn(v.x, v.y);
    hi[2 * j + 1] = __floats2half2_rn(v.z, v.w);
}

// ---------------- launch ------------------------------------------------------
extern "C" void kernel_launch(void* const* d_in, const int* in_sizes, int n_in,
                              void* d_out, int out_size)
{
    const float* xsa    = (const float*)d_in[0];
    const float* Wq     = (const float*)d_in[1];
    const float* Wk     = (const float*)d_in[2];
    const float* Wv     = (const float*)d_in[3];
    const float* biasW  = (const float*)d_in[4];
    const float* bias2W = (const float*)d_in[5];
    float* out = (float*)d_out;

    float *p_kn4, *p_Spart;
    fp16 *xsa_h, *xsa_l, *wqk_h, *wv_h, *xqk_h, *eH, *vp_h;
    cudaGetSymbolAddress((void**)&p_kn4,   g_kn4);
    cudaGetSymbolAddress((void**)&p_Spart, g_Spart);
    cudaGetSymbolAddress((void**)&xsa_h, g_xsa_h);
    cudaGetSymbolAddress((void**)&xsa_l, g_xsa_l);
    cudaGetSymbolAddress((void**)&wqk_h, g_wqk_h);
    cudaGetSymbolAddress((void**)&wv_h,  g_wv_h);
    cudaGetSymbolAddress((void**)&xqk_h, g_xqk_h);
    cudaGetSymbolAddress((void**)&eH,    g_eH);
    cudaGetSymbolAddress((void**)&vp_h,  g_vp_h);

    cudaFuncSetAttribute(hgemm_all, cudaFuncAttributeMaxDynamicSharedMemorySize, 98816);

    // (1) fused input split + counter reset
    split_all<<<4096, 256>>>((const float4*)xsa, (const float4*)Wq,
                             (const float4*)Wk,  (const float4*)Wv,
                             (fp162*)xsa_h, (fp162*)xsa_l,
                             (fp162*)wqk_h, (fp162*)wv_h);
    // (2) entire GEMM pipeline in one launch (S0+S3 -> S2 -> S4 via spin-waits)
    hgemm_all<<<3584, 256, 98816>>>(xsa_h, xsa_l, wqk_h, wv_h,
                                    p_kn4, xqk_h, vp_h, biasW,
                                    p_Spart, eH, out, bias2W);
}